// round 10
// baseline (speedup 1.0000x reference)
#include <cuda_runtime.h>
#include <cuda_bf16.h>
#include <math.h>
#include <stdint.h>

#define B_   32
#define S_   512
#define H_   512
#define NH_  8
#define HD_  64
#define F_   2048
#define L_   6
#define OUT_ 80
#define FD_  256
#define M_   (B_*S_)   // 16384 tokens

typedef __nv_bfloat16  bf16;
typedef __nv_bfloat162 bf162;

// ---------------- scratch (static device globals) ----------------
__device__ float g_h   [M_*H_];
__device__ float g_x1  [M_*H_];
__device__ float g_op  [M_*H_];
__device__ float g_cv2 [M_*H_];
__device__ float g_qkv [M_*3*H_];
__device__ bf16  g_hh  [M_*H_],  g_hl  [M_*H_];
__device__ bf16  g_x1h [M_*H_],  g_x1l [M_*H_];
__device__ bf16  g_ah  [M_*H_],  g_al  [M_*H_];
__device__ bf16  g_midh[M_*F_],  g_midl[M_*F_];
__device__ bf16  g_mkh [M_*H_],  g_mkl [M_*H_];
__device__ bf16  g_dpxh[M_*FD_], g_dpxl[M_*FD_];
__device__ bf16  g_qsh[M_*H_], g_qsl[M_*H_];
__device__ bf16  g_ksh[M_*H_], g_ksl[M_*H_];
__device__ bf16  g_vsh[M_*H_], g_vsl[M_*H_];
__device__ bf16  g_wqkvh[L_*3*H_*H_], g_wqkvl[L_*3*H_*H_];
__device__ bf16  g_woh [L_*H_*H_],    g_wol [L_*H_*H_];
__device__ bf16  g_w1h [L_*F_*3*H_],  g_w1l [L_*F_*3*H_];
__device__ bf16  g_w2h [L_*H_*3*F_],  g_w2l [L_*H_*3*F_];
__device__ bf16  g_pjh [OUT_*H_],     g_pjl [OUT_*H_];
__device__ bf16  g_d1h [FD_*3*H_],    g_d1l [FD_*3*H_];
__device__ bf16  g_d2h [FD_*3*FD_],   g_d2l [FD_*3*FD_];
__device__ float g_bqkv[L_*3*H_];
__device__ float2 g_rope[S_*32];

#define FLAG_RELU  1
#define FLAG_MASK  2
#define FLAG_TRANS 4

#define SWZ128(r,c) ((uint32_t)((r)*128 + ((((c) ^ ((r)&7))) << 4)))

// ---------------- helpers ----------------
__device__ __forceinline__ void split_hl(float x, bf16& h, bf16& l) {
    h = __float2bfloat16_rn(x);
    l = __float2bfloat16_rn(x - __bfloat162float(h));
}

__device__ __forceinline__ uint32_t packb(bf16 x, bf16 y) {
    return (uint32_t)__bfloat16_as_ushort(x) | ((uint32_t)__bfloat16_as_ushort(y) << 16);
}

__device__ __forceinline__ uint32_t smem_u32(const void* p) {
    uint32_t a;
    asm("{ .reg .u64 t; cvta.to.shared.u64 t, %1; cvt.u32.u64 %0, t; }" : "=r"(a) : "l"(p));
    return a;
}

__device__ __forceinline__ void cpa16(uint32_t dst, const void* src, int sz) {
    asm volatile("cp.async.cg.shared.global [%0], [%1], 16, %2;"
                 :: "r"(dst), "l"(src), "r"(sz));
}

__device__ __forceinline__ void ldsm4(uint32_t* r, uint32_t addr) {
    asm volatile("ldmatrix.sync.aligned.m8n8.x4.shared.b16 {%0,%1,%2,%3}, [%4];"
                 : "=r"(r[0]), "=r"(r[1]), "=r"(r[2]), "=r"(r[3]) : "r"(addr));
}

__device__ __forceinline__ void ldsm4t(uint32_t* r, uint32_t addr) {
    asm volatile("ldmatrix.sync.aligned.m8n8.x4.trans.shared.b16 {%0,%1,%2,%3}, [%4];"
                 : "=r"(r[0]), "=r"(r[1]), "=r"(r[2]), "=r"(r[3]) : "r"(addr));
}

__device__ __forceinline__ void mma16816(float* c, const uint32_t* a,
                                         uint32_t b0, uint32_t b1) {
    asm volatile(
        "mma.sync.aligned.m16n8k16.row.col.f32.bf16.bf16.f32 "
        "{%0,%1,%2,%3}, {%4,%5,%6,%7}, {%8,%9}, {%0,%1,%2,%3};"
        : "+f"(c[0]), "+f"(c[1]), "+f"(c[2]), "+f"(c[3])
        : "r"(a[0]), "r"(a[1]), "r"(a[2]), "r"(a[3]), "r"(b0), "r"(b1));
}

// ---------------- split-bf16 HMMA GEMM: 256 thr, 8 warps, 3 CTAs/SM ----------------
// CTA tile 64(M) x 128(N), warp tile 32x32 (2x4 warp grid), K-chunk 32.
// smem 48KB: A planes 8K+8K, B planes 16K+16K; 128B rows hold two chunk-halves.
__global__ __launch_bounds__(256, 3) void hgemm_kernel(
    const bf16* __restrict__ Ahi, const bf16* __restrict__ Alo,
    const bf16* __restrict__ Whi, const bf16* __restrict__ Wlo,
    const float* __restrict__ bias,
    float* __restrict__ Cf, bf16* __restrict__ Chi, bf16* __restrict__ Clo,
    int N, int cinLog2, int nseg, int pad, int flags,
    const int* __restrict__ lengths)
{
    extern __shared__ __align__(16) char smem[];
    const uint32_t sb = smem_u32(smem);
    const uint32_t sAHI = sb, sALO = sb + 8192, sBHI = sb + 16384, sBLO = sb + 32768;

    int t = threadIdx.x, wid = t >> 5, lane = t & 31;
    int m0 = blockIdx.y * 64, n0 = blockIdx.x * 128;
    int cin  = 1 << cinLog2;
    int Kdim = nseg << cinLog2;
    int nch  = Kdim >> 5;
    int wm = (wid >> 2) * 32, wn = (wid & 3) * 32;

    float acc[2][4][4];
#pragma unroll
    for (int i = 0; i < 2; i++)
#pragma unroll
        for (int j = 0; j < 4; j++)
#pragma unroll
            for (int e = 0; e < 4; e++) acc[i][j][e] = 0.f;

    auto load_chunk = [&](int kc) {
        int kh4 = (kc & 1) * 4;
        int kk0 = kc << 5;
        int seg = kk0 >> cinLog2;
        int ci0 = kk0 & (cin - 1);
        // A: 64 rows x 4 chunks = 256 sites, one per thread
        {
            int r = t >> 2, c = t & 3;
            int m = m0 + r;
            const bf16 *sh = Ahi, *sl = Alo;
            int sz = 16;
            if (nseg == 1) {
                size_t off = (size_t)m * cin + kk0 + c * 8;
                sh += off; sl += off;
            } else {
                int s = m & (S_ - 1);
                int srow = s + seg - pad;
                if (srow >= 0 && srow < S_) {
                    size_t off = (size_t)(m + srow - s) * cin + ci0 + c * 8;
                    sh += off; sl += off;
                } else sz = 0;
            }
            uint32_t d = SWZ128(r, kh4 + c);
            cpa16(sAHI + d, sh, sz);
            cpa16(sALO + d, sl, sz);
        }
        // B: 128 rows x 4 chunks = 512 sites, 2 per thread
#pragma unroll
        for (int it = 0; it < 2; it++) {
            int idx = t + it * 256;
            int r = idx >> 2, c = idx & 3;
            int n = n0 + r;
            int sz = (n < N) ? 16 : 0;
            size_t off = (n < N) ? ((size_t)n * Kdim + kk0 + c * 8) : 0;
            uint32_t d = SWZ128(r, kh4 + c);
            cpa16(sBHI + d, Whi + off, sz);
            cpa16(sBLO + d, Wlo + off, sz);
        }
        asm volatile("cp.async.commit_group;");
    };

    int rsel = lane & 15, chalf = lane >> 4;
    auto compute_chunk = [&](int kc) {
        int kh4 = (kc & 1) * 4;
#pragma unroll
        for (int ks = 0; ks < 2; ks++) {
            int cc = kh4 + ks * 2 + chalf;
            uint32_t ah[2][4], al[2][4];
#pragma unroll
            for (int i = 0; i < 2; i++) {
                int rr = wm + i * 16 + rsel;
                uint32_t off = SWZ128(rr, cc);
                ldsm4(ah[i], sAHI + off);
                ldsm4(al[i], sALO + off);
            }
#pragma unroll
            for (int jj = 0; jj < 2; jj++) {
                uint32_t bh[4], bl[4];
                int rr = wn + jj * 16 + rsel;
                uint32_t off = SWZ128(rr, cc);
                ldsm4(bh, sBHI + off);
                ldsm4(bl, sBLO + off);
                mma16816(acc[0][jj * 2 + 0], ah[0], bh[0], bh[2]);
                mma16816(acc[0][jj * 2 + 1], ah[0], bh[1], bh[3]);
                mma16816(acc[1][jj * 2 + 0], ah[1], bh[0], bh[2]);
                mma16816(acc[1][jj * 2 + 1], ah[1], bh[1], bh[3]);
                mma16816(acc[0][jj * 2 + 0], ah[0], bl[0], bl[2]);
                mma16816(acc[0][jj * 2 + 1], ah[0], bl[1], bl[3]);
                mma16816(acc[1][jj * 2 + 0], ah[1], bl[0], bl[2]);
                mma16816(acc[1][jj * 2 + 1], ah[1], bl[1], bl[3]);
                mma16816(acc[0][jj * 2 + 0], al[0], bh[0], bh[2]);
                mma16816(acc[0][jj * 2 + 1], al[0], bh[1], bh[3]);
                mma16816(acc[1][jj * 2 + 0], al[1], bh[0], bh[2]);
                mma16816(acc[1][jj * 2 + 1], al[1], bh[1], bh[3]);
            }
        }
    };

    load_chunk(0);
    for (int kc = 0; kc < nch; kc++) {
        asm volatile("cp.async.wait_group 0;");
        __syncthreads();
        if (kc + 1 < nch) load_chunk(kc + 1);
        compute_chunk(kc);
    }

    // ---- epilogue: warp owns rows wm..wm+31, cols wn..wn+31 ----
    int r0 = lane >> 2, c0 = (lane & 3) * 2;
#pragma unroll
    for (int i = 0; i < 2; i++) {
        int mA = m0 + wm + i * 16 + r0;
        int mB = mA + 8;
        int sA = mA & (S_ - 1), bA = mA >> 9;
        int sB = mB & (S_ - 1), bB = mB >> 9;
        float mvA = 1.f, mvB = 1.f;
        if (flags & FLAG_MASK) {
            mvA = (sA >= lengths[bA]) ? 1.f : 0.f;   // reference's inverted mask
            mvB = (sB >= lengths[bB]) ? 1.f : 0.f;
        }
#pragma unroll
        for (int j = 0; j < 4; j++) {
            int nb = n0 + wn + j * 8 + c0;
            if (nb >= N) continue;
            float b0 = __ldg(bias + nb);
            float b1 = (nb + 1 < N) ? __ldg(bias + nb + 1) : 0.f;
            float v00 = acc[i][j][0] + b0, v01 = acc[i][j][1] + b1;
            float v10 = acc[i][j][2] + b0, v11 = acc[i][j][3] + b1;
            if (flags & FLAG_RELU) {
                v00 = fmaxf(v00, 0.f); v01 = fmaxf(v01, 0.f);
                v10 = fmaxf(v10, 0.f); v11 = fmaxf(v11, 0.f);
            }
            v00 *= mvA; v01 *= mvA; v10 *= mvB; v11 *= mvB;
            if (flags & FLAG_TRANS) {
                Cf[((size_t)bA * N + nb) * S_ + sA] = v00;
                Cf[((size_t)bB * N + nb) * S_ + sB] = v10;
                if (nb + 1 < N) {
                    Cf[((size_t)bA * N + nb + 1) * S_ + sA] = v01;
                    Cf[((size_t)bB * N + nb + 1) * S_ + sB] = v11;
                }
            } else {
                if (Cf) {
                    *(float2*)(Cf + (size_t)mA * N + nb) = make_float2(v00, v01);
                    *(float2*)(Cf + (size_t)mB * N + nb) = make_float2(v10, v11);
                }
                if (Chi) {
                    bf16 h0, l0, h1, l1;
                    split_hl(v00, h0, l0); split_hl(v01, h1, l1);
                    *(bf162*)(Chi + (size_t)mA * N + nb) = bf162(h0, h1);
                    *(bf162*)(Clo + (size_t)mA * N + nb) = bf162(l0, l1);
                    split_hl(v10, h0, l0); split_hl(v11, h1, l1);
                    *(bf162*)(Chi + (size_t)mB * N + nb) = bf162(h0, h1);
                    *(bf162*)(Clo + (size_t)mB * N + nb) = bf162(l0, l1);
                }
            }
        }
    }
}

// ---------------- rope + split: qkv fp32 -> 6 bf16 planes ----------------
__global__ __launch_bounds__(256) void rope_split_kernel(
    const float* __restrict__ qkv, const float2* __restrict__ rt)
{
    int idx = blockIdx.x * blockDim.x + threadIdx.x;
    if (idx >= M_ * 64) return;
    int m  = idx >> 6;
    int d0 = (idx & 63) * 8;
    int s  = m & (S_ - 1);
    const float* base = qkv + (size_t)m * (3 * H_);
    float sgn = ((d0 & 63) < 32) ? -1.f : 1.f;
    const float2* rte = rt + s * 32 + (d0 & 31);
    size_t ob = (size_t)m * H_ + d0;

#pragma unroll
    for (int which = 0; which < 2; which++) {
        const float* p = base + which * H_;
        float4 xa = *(const float4*)(p + d0);
        float4 xb = *(const float4*)(p + d0 + 4);
        float4 pa = *(const float4*)(p + (d0 ^ 32));
        float4 pb = *(const float4*)(p + (d0 ^ 32) + 4);
        float xs[8] = {xa.x, xa.y, xa.z, xa.w, xb.x, xb.y, xb.z, xb.w};
        float ps[8] = {pa.x, pa.y, pa.z, pa.w, pb.x, pb.y, pb.z, pb.w};
        uint32_t wh[4], wl[4];
#pragma unroll
        for (int e = 0; e < 8; e += 2) {
            float2 c0 = rte[e], c1 = rte[e + 1];
            float v0 = xs[e] * c0.x + sgn * ps[e] * c0.y;
            float v1 = xs[e + 1] * c1.x + sgn * ps[e + 1] * c1.y;
            bf16 h0, l0, h1, l1;
            split_hl(v0, h0, l0); split_hl(v1, h1, l1);
            wh[e >> 1] = packb(h0, h1); wl[e >> 1] = packb(l0, l1);
        }
        bf16* dh = which ? g_ksh : g_qsh;
        bf16* dl = which ? g_ksl : g_qsl;
        *(uint4*)(dh + ob) = make_uint4(wh[0], wh[1], wh[2], wh[3]);
        *(uint4*)(dl + ob) = make_uint4(wl[0], wl[1], wl[2], wl[3]);
    }
    {
        const float* p = base + 2 * H_;
        float4 xa = *(const float4*)(p + d0);
        float4 xb = *(const float4*)(p + d0 + 4);
        float vs[8] = {xa.x, xa.y, xa.z, xa.w, xb.x, xb.y, xb.z, xb.w};
        uint32_t wh[4], wl[4];
#pragma unroll
        for (int e = 0; e < 8; e += 2) {
            bf16 h0, l0, h1, l1;
            split_hl(vs[e], h0, l0); split_hl(vs[e + 1], h1, l1);
            wh[e >> 1] = packb(h0, h1); wl[e >> 1] = packb(l0, l1);
        }
        *(uint4*)(g_vsh + ob) = make_uint4(wh[0], wh[1], wh[2], wh[3]);
        *(uint4*)(g_vsl + ob) = make_uint4(wl[0], wl[1], wl[2], wl[3]);
    }
}

// ---------------- HMMA flash attention on pre-split planes ----------------
__global__ __launch_bounds__(128) void attn_kernel(
    const bf16* __restrict__ qsh, const bf16* __restrict__ qsl,
    const bf16* __restrict__ ksh, const bf16* __restrict__ ksl,
    const bf16* __restrict__ vsh, const bf16* __restrict__ vsl,
    bf16* __restrict__ ohi, bf16* __restrict__ olo,
    const int* __restrict__ lengths)
{
    extern __shared__ __align__(16) char sm[];
    const uint32_t sb = smem_u32(sm);
    const uint32_t QH = 0, QL = 8192, KH = 16384, KL = 24576, VH = 32768, VL = 40960;

    int t = threadIdx.x, wid = t >> 5, lane = t & 31;
    int qt = blockIdx.x, hh = blockIdx.y, b = blockIdx.z;
    int len = lengths[b];

#pragma unroll
    for (int it = 0; it < 4; it++) {
        int idx = t + it * 128;
        int r = idx >> 3, c = idx & 7;
        size_t src = ((size_t)b * S_ + qt * 64 + r) * H_ + hh * HD_ + c * 8;
        uint32_t d = SWZ128(r, c);
        cpa16(sb + QH + d, qsh + src, 16);
        cpa16(sb + QL + d, qsl + src, 16);
    }
    asm volatile("cp.async.commit_group;");
    asm volatile("cp.async.wait_group 0;");
    __syncthreads();

    int rsel = lane & 15, chalf = lane >> 4;
    uint32_t qh[4][4], ql[4][4];
#pragma unroll
    for (int ks = 0; ks < 4; ks++) {
        int rr = wid * 16 + rsel;
        uint32_t off = SWZ128(rr, ks * 2 + chalf);
        ldsm4(qh[ks], sb + QH + off);
        ldsm4(ql[ks], sb + QL + off);
    }

    float oc[8][4];
#pragma unroll
    for (int dt = 0; dt < 8; dt++)
#pragma unroll
        for (int e = 0; e < 4; e++) oc[dt][e] = 0.f;
    float m0 = -INFINITY, m1 = -INFINITY, ls0 = 0.f, ls1 = 0.f;

    int kt0 = len >> 6;
    if (kt0 > 7) kt0 = 7;

    for (int kt = kt0; kt < 8; kt++) {
        __syncthreads();
#pragma unroll
        for (int it = 0; it < 4; it++) {
            int idx = t + it * 128;
            int r = idx >> 3, c = idx & 7;
            size_t src = ((size_t)b * S_ + kt * 64 + r) * H_ + hh * HD_ + c * 8;
            uint32_t d = SWZ128(r, c);
            cpa16(sb + KH + d, ksh + src, 16);
            cpa16(sb + KL + d, ksl + src, 16);
            cpa16(sb + VH + d, vsh + src, 16);
            cpa16(sb + VL + d, vsl + src, 16);
        }
        asm volatile("cp.async.commit_group;");
        asm volatile("cp.async.wait_group 0;");
        __syncthreads();

        float sv[8][4];
#pragma unroll
        for (int jt = 0; jt < 8; jt++)
#pragma unroll
            for (int e = 0; e < 4; e++) sv[jt][e] = 0.f;
#pragma unroll
        for (int ks = 0; ks < 4; ks++) {
#pragma unroll
            for (int jj = 0; jj < 4; jj++) {
                uint32_t bh[4], bl[4];
                int rr = jj * 16 + rsel;
                uint32_t off = SWZ128(rr, ks * 2 + chalf);
                ldsm4(bh, sb + KH + off);
                ldsm4(bl, sb + KL + off);
                mma16816(sv[jj * 2 + 0], qh[ks], bh[0], bh[2]);
                mma16816(sv[jj * 2 + 1], qh[ks], bh[1], bh[3]);
                mma16816(sv[jj * 2 + 0], qh[ks], bl[0], bl[2]);
                mma16816(sv[jj * 2 + 1], qh[ks], bl[1], bl[3]);
                mma16816(sv[jj * 2 + 0], ql[ks], bh[0], bh[2]);
                mma16816(sv[jj * 2 + 1], ql[ks], bh[1], bh[3]);
            }
        }

        int colb = kt * 64 + (lane & 3) * 2;
        float rm0 = -INFINITY, rm1 = -INFINITY;
#pragma unroll
        for (int jt = 0; jt < 8; jt++) {
#pragma unroll
            for (int e = 0; e < 2; e++) {
                int kp = colb + jt * 8 + e;
                bool keep = (kp >= len);
                float v0 = sv[jt][e] * 0.125f;
                float v1 = sv[jt][2 + e] * 0.125f;
                sv[jt][e]     = keep ? v0 : -1e9f;
                sv[jt][2 + e] = keep ? v1 : -1e9f;
                rm0 = fmaxf(rm0, sv[jt][e]);
                rm1 = fmaxf(rm1, sv[jt][2 + e]);
            }
        }
        rm0 = fmaxf(rm0, __shfl_xor_sync(0xffffffffu, rm0, 1));
        rm0 = fmaxf(rm0, __shfl_xor_sync(0xffffffffu, rm0, 2));
        rm1 = fmaxf(rm1, __shfl_xor_sync(0xffffffffu, rm1, 1));
        rm1 = fmaxf(rm1, __shfl_xor_sync(0xffffffffu, rm1, 2));
        float mn0 = fmaxf(m0, rm0), mn1 = fmaxf(m1, rm1);
        float a0 = __expf(m0 - mn0), a1 = __expf(m1 - mn1);
        m0 = mn0; m1 = mn1;
        float s0 = 0.f, s1 = 0.f;
#pragma unroll
        for (int jt = 0; jt < 8; jt++) {
            sv[jt][0] = __expf(sv[jt][0] - mn0);
            sv[jt][1] = __expf(sv[jt][1] - mn0);
            sv[jt][2] = __expf(sv[jt][2] - mn1);
            sv[jt][3] = __expf(sv[jt][3] - mn1);
            s0 += sv[jt][0] + sv[jt][1];
            s1 += sv[jt][2] + sv[jt][3];
        }
        s0 += __shfl_xor_sync(0xffffffffu, s0, 1);
        s0 += __shfl_xor_sync(0xffffffffu, s0, 2);
        s1 += __shfl_xor_sync(0xffffffffu, s1, 1);
        s1 += __shfl_xor_sync(0xffffffffu, s1, 2);
        ls0 = ls0 * a0 + s0;
        ls1 = ls1 * a1 + s1;
#pragma unroll
        for (int dt = 0; dt < 8; dt++) {
            oc[dt][0] *= a0; oc[dt][1] *= a0;
            oc[dt][2] *= a1; oc[dt][3] *= a1;
        }

#pragma unroll
        for (int jp = 0; jp < 4; jp++) {
            uint32_t pah[4], pal[4];
#pragma unroll
            for (int half = 0; half < 2; half++) {
                bf16 h0, lo0, h1, lo1, h2, lo2, h3, lo3;
                split_hl(sv[2 * jp + half][0], h0, lo0);
                split_hl(sv[2 * jp + half][1], h1, lo1);
                split_hl(sv[2 * jp + half][2], h2, lo2);
                split_hl(sv[2 * jp + half][3], h3, lo3);
                pah[2 * half + 0] = packb(h0, h1);  pal[2 * half + 0] = packb(lo0, lo1);
                pah[2 * half + 1] = packb(h2, h3);  pal[2 * half + 1] = packb(lo2, lo3);
            }
            int vrow = jp * 16 + ((lane >> 3) & 1) * 8 + (lane & 7);
#pragma unroll
            for (int g = 0; g < 4; g++) {
                int cch = 2 * g + (lane >> 4);
                uint32_t off = SWZ128(vrow, cch);
                uint32_t vh[4], vl[4];
                ldsm4t(vh, sb + VH + off);
                ldsm4t(vl, sb + VL + off);
                mma16816(oc[2 * g],     pah, vh[0], vh[1]);
                mma16816(oc[2 * g + 1], pah, vh[2], vh[3]);
                mma16816(oc[2 * g],     pah, vl[0], vl[1]);
                mma16816(oc[2 * g + 1], pah, vl[2], vl[3]);
                mma16816(oc[2 * g],     pal, vh[0], vh[1]);
                mma16816(oc[2 * g + 1], pal, vh[2], vh[3]);
            }
        }
    }

    float i0 = 1.f / ls0, i1 = 1.f / ls1;
    int r0 = qt * 64 + wid * 16 + (lane >> 2);
#pragma unroll
    for (int dt = 0; dt < 8; dt++) {
        int d = hh * HD_ + dt * 8 + (lane & 3) * 2;
        size_t o0 = ((size_t)b * S_ + r0) * H_ + d;
        size_t o1 = o0 + (size_t)8 * H_;
        bf16 h0, lo0, h1, lo1;
        split_hl(oc[dt][0] * i0, h0, lo0);
        split_hl(oc[dt][1] * i0, h1, lo1);
        *(bf162*)(ohi + o0) = bf162(h0, h1);
        *(bf162*)(olo + o0) = bf162(lo0, lo1);
        split_hl(oc[dt][2] * i1, h0, lo0);
        split_hl(oc[dt][3] * i1, h1, lo1);
        *(bf162*)(ohi + o1) = bf162(h0, h1);
        *(bf162*)(olo + o1) = bf162(lo0, lo1);
    }
}

// ---------------- LayerNorm (residual add + optional split outputs) ----------------
__global__ __launch_bounds__(128) void ln_kernel(
    const float* __restrict__ x, const float* __restrict__ res,
    const float* __restrict__ g, const float* __restrict__ be,
    float* __restrict__ out, bf16* __restrict__ ohi, bf16* __restrict__ olo, int C)
{
    int m = blockIdx.x, t = threadIdx.x;
    int nv = C >> 2;
    float4 v = make_float4(0.f, 0.f, 0.f, 0.f);
    if (t < nv) {
        v = ((const float4*)(x + (size_t)m * C))[t];
        if (res) {
            float4 w = ((const float4*)(res + (size_t)m * C))[t];
            v.x += w.x; v.y += w.y; v.z += w.z; v.w += w.w;
        }
    }
    float sum = v.x + v.y + v.z + v.w;
    float sq  = v.x * v.x + v.y * v.y + v.z * v.z + v.w * v.w;
#pragma unroll
    for (int off = 16; off; off >>= 1) {
        sum += __shfl_xor_sync(0xffffffffu, sum, off);
        sq  += __shfl_xor_sync(0xffffffffu, sq,  off);
    }
    __shared__ float s1[4], s2[4];
    if ((t & 31) == 0) { s1[t >> 5] = sum; s2[t >> 5] = sq; }
    __syncthreads();
    sum = s1[0] + s1[1] + s1[2] + s1[3];
    sq  = s2[0] + s2[1] + s2[2] + s2[3];
    float mean = sum / C;
    float var  = sq / C - mean * mean;
    float inv  = rsqrtf(var + 1e-5f);
    if (t < nv) {
        float4 gv = ((const float4*)g)[t];
        float4 bv = ((const float4*)be)[t];
        float4 o4;
        o4.x = (v.x - mean) * inv * gv.x + bv.x;
        o4.y = (v.y - mean) * inv * gv.y + bv.y;
        o4.z = (v.z - mean) * inv * gv.z + bv.z;
        o4.w = (v.w - mean) * inv * gv.w + bv.w;
        if (out) ((float4*)(out + (size_t)m * C))[t] = o4;
        if (ohi) {
            bf16 h0, l0, h1, l1, h2, l2, h3, l3;
            split_hl(o4.x, h0, l0); split_hl(o4.y, h1, l1);
            split_hl(o4.z, h2, l2); split_hl(o4.w, h3, l3);
            *(bf162*)(ohi + (size_t)m * C + t * 4)     = bf162(h0, h1);
            *(bf162*)(ohi + (size_t)m * C + t * 4 + 2) = bf162(h2, h3);
            *(bf162*)(olo + (size_t)m * C + t * 4)     = bf162(l0, l1);
            *(bf162*)(olo + (size_t)m * C + t * 4 + 2) = bf162(l2, l3);
        }
    }
}

// ---------------- small kernels ----------------
__global__ __launch_bounds__(256) void embed_kernel(
    const int* __restrict__ x, const float* __restrict__ emb,
    float* __restrict__ h, bf16* __restrict__ hh, bf16* __restrict__ hl)
{
    int idx = blockIdx.x * blockDim.x + threadIdx.x;
    if (idx >= M_ * (H_ / 4)) return;
    int m = idx >> 7, c4 = idx & 127;
    int tok = x[m];
    float4 e = ((const float4*)(emb + (size_t)tok * H_))[c4];
    const float sc = 22.62741699796952f;  // sqrt(512)
    e.x *= sc; e.y *= sc; e.z *= sc; e.w *= sc;
    ((float4*)(h + (size_t)m * H_))[c4] = e;
    bf16 h0, l0, h1, l1, h2, l2, h3, l3;
    split_hl(e.x, h0, l0); split_hl(e.y, h1, l1);
    split_hl(e.z, h2, l2); split_hl(e.w, h3, l3);
    *(bf162*)(hh + (size_t)m * H_ + c4 * 4)     = bf162(h0, h1);
    *(bf162*)(hh + (size_t)m * H_ + c4 * 4 + 2) = bf162(h2, h3);
    *(bf162*)(hl + (size_t)m * H_ + c4 * 4)     = bf162(l0, l1);
    *(bf162*)(hl + (size_t)m * H_ + c4 * 4 + 2) = bf162(l2, l3);
}

__global__ __launch_bounds__(256) void maskmul_kernel(
    const float* __restrict__ in, bf16* __restrict__ ohi, bf16* __restrict__ olo,
    const int* __restrict__ lengths)
{
    int idx = blockIdx.x * blockDim.x + threadIdx.x;
    if (idx >= M_ * H_) return;
    int m = idx >> 9;
    int s = m & (S_ - 1), b = m >> 9;
    float v = in[idx] * ((s >= lengths[b]) ? 1.f : 0.f);  // inverted mask
    bf16 h, l;
    split_hl(v, h, l);
    ohi[idx] = h; olo[idx] = l;
}

#define NW1 (L_*F_*H_*3)
#define NW2 (L_*H_*F_*3)
#define ND1 (FD_*H_*3)
#define ND2 (FD_*FD_*3)
__global__ __launch_bounds__(256) void prep_conv_kernel(
    const float* __restrict__ c1w, const float* __restrict__ c2w,
    const float* __restrict__ d1w, const float* __restrict__ d2w)
{
    int idx = blockIdx.x * blockDim.x + threadIdx.x;
    const float* src; bf16 *dh, *dl; int CI; int base;
    if (idx < NW1)                        { src = c1w; dh = g_w1h; dl = g_w1l; CI = H_;  base = idx; }
    else if (idx < NW1 + NW2)             { src = c2w; dh = g_w2h; dl = g_w2l; CI = F_;  base = idx - NW1; }
    else if (idx < NW1 + NW2 + ND1)       { src = d1w; dh = g_d1h; dl = g_d1l; CI = H_;  base = idx - NW1 - NW2; }
    else if (idx < NW1 + NW2 + ND1 + ND2) { src = d2w; dh = g_d2h; dl = g_d2l; CI = FD_; base = idx - NW1 - NW2 - ND1; }
    else return;
    int kk = base % 3;
    int rest = base / 3;
    int ci = rest % CI;
    int co = rest / CI;
    float v = src[base];
    bf16 h, l; split_hl(v, h, l);
    size_t o = (size_t)co * (3 * CI) + kk * CI + ci;
    dh[o] = h; dl[o] = l;
}

#define NQKV (L_*3*H_*H_)
#define NWO  (L_*H_*H_)
#define NPJ  (OUT_*H_)
#define NBQ  (L_*3*H_)
#define NRT  (S_*32)
__global__ __launch_bounds__(256) void prep_lin_kernel(
    const float* __restrict__ Wq, const float* __restrict__ Wk,
    const float* __restrict__ Wv, const float* __restrict__ Wo,
    const float* __restrict__ pj,
    const float* __restrict__ bq, const float* __restrict__ bk,
    const float* __restrict__ bv)
{
    int idx = blockIdx.x * blockDim.x + threadIdx.x;
    if (idx < NQKV) {
        int e = idx % H_;
        int n = (idx / H_) % (3 * H_);
        int l = idx / (3 * H_ * H_);
        const float* W = (n < H_) ? Wq : (n < 2 * H_) ? Wk : Wv;
        int nn = n & (H_ - 1);
        float v = W[(size_t)l * H_ * H_ + (size_t)nn * H_ + e];
        bf16 h, lo; split_hl(v, h, lo);
        g_wqkvh[idx] = h; g_wqkvl[idx] = lo;
        return;
    }
    int i2 = idx - NQKV;
    if (i2 < NWO) {
        float v = Wo[i2];
        bf16 h, lo; split_hl(v, h, lo);
        g_woh[i2] = h; g_wol[i2] = lo;
        return;
    }
    int i3 = i2 - NWO;
    if (i3 < NPJ) {
        float v = pj[i3];
        bf16 h, lo; split_hl(v, h, lo);
        g_pjh[i3] = h; g_pjl[i3] = lo;
        return;
    }
    int i4 = i3 - NPJ;
    if (i4 < NBQ) {
        int n = i4 % (3 * H_);
        int l = i4 / (3 * H_);
        const float* bb = (n < H_) ? bq : (n < 2 * H_) ? bk : bv;
        g_bqkv[i4] = bb[l * H_ + (n & (H_ - 1))];
        return;
    }
    int i5 = i4 - NBQ;
    if (i5 < NRT) {
        int s = i5 >> 5, j = i5 & 31;
        float th = expf(-(float)j * 0.28782313662425574f);
        float sn, cs;
        sincosf((float)s * th, &sn, &cs);
        g_rope[i5] = make_float2(cs, sn);
    }
}

__global__ __launch_bounds__(256) void dp_final_kernel(
    const float* __restrict__ x, const float* __restrict__ w,
    const float* __restrict__ pb, const int* __restrict__ lengths,
    float* __restrict__ out)
{
    int warp = threadIdx.x >> 5, lane = threadIdx.x & 31;
    int m = blockIdx.x * 8 + warp;
    if (m >= M_) return;
    const float* xr = x + (size_t)m * FD_;
    float s = 0.f;
    for (int c = lane; c < FD_; c += 32) s += xr[c] * w[c];
#pragma unroll
    for (int off = 16; off; off >>= 1) s += __shfl_xor_sync(0xffffffffu, s, off);
    if (lane == 0) {
        int b = m >> 9, sp = m & (S_ - 1);
        float mv = (sp >= lengths[b]) ? 1.f : 0.f;
        float val = (s + pb[0]) * mv;
        out[(size_t)b * S_ + sp] = ceilf(expf(val));
    }
}

// ---------------- orchestration ----------------
extern "C" void kernel_launch(void* const* d_in, const int* in_sizes, int n_in,
                              void* d_out, int out_size)
{
    const int*   x      = (const int*)  d_in[0];
    const int*   xlen   = (const int*)  d_in[1];
    const float* emb    = (const float*)d_in[2];
    const float* Wq     = (const float*)d_in[3];
    const float* bq     = (const float*)d_in[4];
    const float* Wk     = (const float*)d_in[5];
    const float* bk     = (const float*)d_in[6];
    const float* Wv     = (const float*)d_in[7];
    const float* bv     = (const float*)d_in[8];
    const float* Wo     = (const float*)d_in[9];
    const float* bo     = (const float*)d_in[10];
    const float* c1w    = (const float*)d_in[11];
    const float* c1b    = (const float*)d_in[12];
    const float* c2w    = (const float*)d_in[13];
    const float* c2b    = (const float*)d_in[14];
    const float* ln1g   = (const float*)d_in[15];
    const float* ln1b   = (const float*)d_in[16];
    const float* ln2g   = (const float*)d_in[17];
    const float* ln2b   = (const float*)d_in[18];
    const float* projw  = (const float*)d_in[19];
    const float* projb  = (const float*)d_in[20];
    const float* dpc1w  = (const float*)d_in[21];
    const float* dpc1b  = (const float*)d_in[22];
    const float* dpln1g = (const float*)d_in[23];
    const float* dpln1b = (const float*)d_in[24];
    const float* dpc2w  = (const float*)d_in[25];
    const float* dpc2b  = (const float*)d_in[26];
    const float* dpln2g = (const float*)d_in[27];
    const float* dpln2b = (const float*)d_in[28];
    const float* dppw   = (const float*)d_in[29];
    const float* dppb   = (const float*)d_in[30];
    float* out = (float*)d_out;

    float *h, *x1, *op, *cv2, *qkv, *bqkv;
    float2* rtab;
    bf16 *hh, *hl, *x1h, *x1l, *ah, *al, *midh, *midl, *mkh, *mkl, *dpxh, *dpxl;
    bf16 *qsh, *qsl, *ksh, *ksl, *vsh, *vsl;
    bf16 *wqh, *wql, *woh, *wol, *w1h, *w1l, *w2h, *w2l, *pjh, *pjl, *d1h, *d1l, *d2h, *d2l;
    cudaGetSymbolAddress((void**)&h,    g_h);
    cudaGetSymbolAddress((void**)&x1,   g_x1);
    cudaGetSymbolAddress((void**)&op,   g_op);
    cudaGetSymbolAddress((void**)&cv2,  g_cv2);
    cudaGetSymbolAddress((void**)&qkv,  g_qkv);
    cudaGetSymbolAddress((void**)&rtab, g_rope);
    cudaGetSymbolAddress((void**)&hh,   g_hh);
    cudaGetSymbolAddress((void**)&hl,   g_hl);
    cudaGetSymbolAddress((void**)&x1h,  g_x1h);
    cudaGetSymbolAddress((void**)&x1l,  g_x1l);
    cudaGetSymbolAddress((void**)&ah,   g_ah);
    cudaGetSymbolAddress((void**)&al,   g_al);
    cudaGetSymbolAddress((void**)&midh, g_midh);
    cudaGetSymbolAddress((void**)&midl, g_midl);
    cudaGetSymbolAddress((void**)&mkh,  g_mkh);
    cudaGetSymbolAddress((void**)&mkl,  g_mkl);
    cudaGetSymbolAddress((void**)&dpxh, g_dpxh);
    cudaGetSymbolAddress((void**)&dpxl, g_dpxl);
    cudaGetSymbolAddress((void**)&qsh,  g_qsh);
    cudaGetSymbolAddress((void**)&qsl,  g_qsl);
    cudaGetSymbolAddress((void**)&ksh,  g_ksh);
    cudaGetSymbolAddress((void**)&ksl,  g_ksl);
    cudaGetSymbolAddress((void**)&vsh,  g_vsh);
    cudaGetSymbolAddress((void**)&vsl,  g_vsl);
    cudaGetSymbolAddress((void**)&wqh,  g_wqkvh);
    cudaGetSymbolAddress((void**)&wql,  g_wqkvl);
    cudaGetSymbolAddress((void**)&woh,  g_woh);
    cudaGetSymbolAddress((void**)&wol,  g_wol);
    cudaGetSymbolAddress((void**)&w1h,  g_w1h);
    cudaGetSymbolAddress((void**)&w1l,  g_w1l);
    cudaGetSymbolAddress((void**)&w2h,  g_w2h);
    cudaGetSymbolAddress((void**)&w2l,  g_w2l);
    cudaGetSymbolAddress((void**)&pjh,  g_pjh);
    cudaGetSymbolAddress((void**)&pjl,  g_pjl);
    cudaGetSymbolAddress((void**)&d1h,  g_d1h);
    cudaGetSymbolAddress((void**)&d1l,  g_d1l);
    cudaGetSymbolAddress((void**)&d2h,  g_d2h);
    cudaGetSymbolAddress((void**)&d2l,  g_d2l);
    cudaGetSymbolAddress((void**)&bqkv, g_bqkv);

    cudaFuncSetAttribute((const void*)attn_kernel,
                         cudaFuncAttributeMaxDynamicSharedMemorySize, 49152);
    cudaFuncSetAttribute((const void*)hgemm_kernel,
                         cudaFuncAttributeMaxDynamicSharedMemorySize, 49152);

    {
        int tot = NW1 + NW2 + ND1 + ND2;
        prep_conv_kernel<<<(tot + 255) / 256, 256>>>(c1w, c2w, dpc1w, dpc2w);
        tot = NQKV + NWO + NPJ + NBQ + NRT;
        prep_lin_kernel<<<(tot + 255) / 256, 256>>>(Wq, Wk, Wv, Wo, projw, bq, bk, bv);
    }
    embed_kernel<<<M_ * (H_ / 4) / 256, 256>>>(x, emb, h, hh, hl);

    const int SM_G = 49152;
    dim3 gQKV(3 * H_ / 128, M_ / 64);   // (12,256)
    dim3 gH(H_ / 128, M_ / 64);         // (4,256)
    dim3 gF(F_ / 128, M_ / 64);         // (16,256)
    dim3 gMu(1, M_ / 64);
    dim3 gDp(FD_ / 128, M_ / 64);       // (2,256)
    dim3 ga(S_ / 64, NH_, B_);

    for (int l = 0; l < L_; l++) {
        size_t wOff = (size_t)l * H_ * H_;
        size_t wqOff = (size_t)l * 3 * H_ * H_;
        hgemm_kernel<<<gQKV, 256, SM_G>>>(hh, hl, wqh + wqOff, wql + wqOff,
                                          bqkv + l * 3 * H_, qkv, nullptr, nullptr,
                                          3 * H_, 9, 1, 0, 0, xlen);
        rope_split_kernel<<<M_ * 64 / 256, 256>>>(qkv, rtab);
        attn_kernel<<<ga, 128, SM_G>>>(qsh, qsl, ksh, ksl, vsh, vsl, ah, al, xlen);
        hgemm_kernel<<<gH, 256, SM_G>>>(ah, al, woh + wOff, wol + wOff,
                                        bo + l * H_, op, nullptr, nullptr,
                                        H_, 9, 1, 0, 0, xlen);
        ln_kernel<<<M_, 128>>>(op, h, ln1g + l * H_, ln1b + l * H_, x1, x1h, x1l, H_);
        hgemm_kernel<<<gF, 256, SM_G>>>(x1h, x1l,
                                        w1h + (size_t)l * F_ * 3 * H_, w1l + (size_t)l * F_ * 3 * H_,
                                        c1b + l * F_, nullptr, midh, midl,
                                        F_, 9, 3, 1, FLAG_RELU, xlen);
        hgemm_kernel<<<gH, 256, SM_G>>>(midh, midl,
                                        w2h + (size_t)l * H_ * 3 * F_, w2l + (size_t)l * H_ * 3 * F_,
                                        c2b + l * H_, cv2, nullptr, nullptr,
                                        H_, 11, 3, 1, 0, xlen);
        ln_kernel<<<M_, 128>>>(cv2, x1, ln2g + l * H_, ln2b + l * H_, h, hh, hl, H_);
    }

    hgemm_kernel<<<gMu, 256, SM_G>>>(hh, hl, pjh, pjl, projb, out, nullptr, nullptr,
                                     OUT_, 9, 1, 0, FLAG_TRANS, xlen);

    maskmul_kernel<<<M_ * H_ / 256, 256>>>(h, mkh, mkl, xlen);
    hgemm_kernel<<<gDp, 256, SM_G>>>(mkh, mkl, d1h, d1l, dpc1b, op, nullptr, nullptr,
                                     FD_, 9, 3, 1, FLAG_RELU | FLAG_MASK, xlen);
    ln_kernel<<<M_, 128>>>(op, nullptr, dpln1g, dpln1b, cv2, dpxh, dpxl, FD_);
    hgemm_kernel<<<gDp, 256, SM_G>>>(dpxh, dpxl, d2h, d2l, dpc2b, op, nullptr, nullptr,
                                     FD_, 8, 3, 1, FLAG_RELU | FLAG_MASK, xlen);
    ln_kernel<<<M_, 128>>>(op, nullptr, dpln2g, dpln2b, x1, nullptr, nullptr, FD_);
    dp_final_kernel<<<M_ / 8, 256>>>(x1, dppw, dppb, xlen,
                                     out + ((size_t)out_size - (size_t)B_ * S_));
}

// round 11
// speedup vs baseline: 1.0556x; 1.0556x over previous
#include <cuda_runtime.h>
#include <cuda_bf16.h>
#include <math.h>
#include <stdint.h>

#define B_   32
#define S_   512
#define H_   512
#define NH_  8
#define HD_  64
#define F_   2048
#define L_   6
#define OUT_ 80
#define FD_  256
#define M_   (B_*S_)   // 16384 tokens

typedef __nv_bfloat16  bf16;
typedef __nv_bfloat162 bf162;

// ---------------- scratch (static device globals) ----------------
__device__ float g_h   [M_*H_];
__device__ float g_x1  [M_*H_];
__device__ float g_op  [M_*H_];
__device__ float g_cv2 [M_*H_];
__device__ bf16  g_hh  [M_*H_],  g_hl  [M_*H_];
__device__ bf16  g_x1h [M_*H_],  g_x1l [M_*H_];
__device__ bf16  g_ah  [M_*H_],  g_al  [M_*H_];
__device__ bf16  g_midh[M_*F_],  g_midl[M_*F_];
__device__ bf16  g_mkh [M_*H_],  g_mkl [M_*H_];
__device__ bf16  g_dpxh[M_*FD_], g_dpxl[M_*FD_];
__device__ bf16  g_qsh[M_*H_], g_qsl[M_*H_];
__device__ bf16  g_ksh[M_*H_], g_ksl[M_*H_];
__device__ bf16  g_vsh[M_*H_], g_vsl[M_*H_];
__device__ bf16  g_wqkvh[L_*3*H_*H_], g_wqkvl[L_*3*H_*H_];
__device__ bf16  g_woh [L_*H_*H_],    g_wol [L_*H_*H_];
__device__ bf16  g_w1h [L_*F_*3*H_],  g_w1l [L_*F_*3*H_];
__device__ bf16  g_w2h [L_*H_*3*F_],  g_w2l [L_*H_*3*F_];
__device__ bf16  g_pjh [OUT_*H_],     g_pjl [OUT_*H_];
__device__ bf16  g_d1h [FD_*3*H_],    g_d1l [FD_*3*H_];
__device__ bf16  g_d2h [FD_*3*FD_],   g_d2l [FD_*3*FD_];
__device__ float g_bqkv[L_*3*H_];
__device__ float2 g_rope[S_*32];

#define FLAG_RELU  1
#define FLAG_MASK  2
#define FLAG_TRANS 4
#define FLAG_QKV   8

#define SWZ128(r,c) ((uint32_t)((r)*128 + ((((c) ^ ((r)&7))) << 4)))

// ---------------- helpers ----------------
__device__ __forceinline__ void split_hl(float x, bf16& h, bf16& l) {
    h = __float2bfloat16_rn(x);
    l = __float2bfloat16_rn(x - __bfloat162float(h));
}

__device__ __forceinline__ uint32_t packb(bf16 x, bf16 y) {
    return (uint32_t)__bfloat16_as_ushort(x) | ((uint32_t)__bfloat16_as_ushort(y) << 16);
}

__device__ __forceinline__ uint32_t smem_u32(const void* p) {
    uint32_t a;
    asm("{ .reg .u64 t; cvta.to.shared.u64 t, %1; cvt.u32.u64 %0, t; }" : "=r"(a) : "l"(p));
    return a;
}

__device__ __forceinline__ void cpa16(uint32_t dst, const void* src, int sz) {
    asm volatile("cp.async.cg.shared.global [%0], [%1], 16, %2;"
                 :: "r"(dst), "l"(src), "r"(sz));
}

__device__ __forceinline__ void ldsm4(uint32_t* r, uint32_t addr) {
    asm volatile("ldmatrix.sync.aligned.m8n8.x4.shared.b16 {%0,%1,%2,%3}, [%4];"
                 : "=r"(r[0]), "=r"(r[1]), "=r"(r[2]), "=r"(r[3]) : "r"(addr));
}

__device__ __forceinline__ void ldsm4t(uint32_t* r, uint32_t addr) {
    asm volatile("ldmatrix.sync.aligned.m8n8.x4.trans.shared.b16 {%0,%1,%2,%3}, [%4];"
                 : "=r"(r[0]), "=r"(r[1]), "=r"(r[2]), "=r"(r[3]) : "r"(addr));
}

__device__ __forceinline__ void mma16816(float* c, const uint32_t* a,
                                         uint32_t b0, uint32_t b1) {
    asm volatile(
        "mma.sync.aligned.m16n8k16.row.col.f32.bf16.bf16.f32 "
        "{%0,%1,%2,%3}, {%4,%5,%6,%7}, {%8,%9}, {%0,%1,%2,%3};"
        : "+f"(c[0]), "+f"(c[1]), "+f"(c[2]), "+f"(c[3])
        : "r"(a[0]), "r"(a[1]), "r"(a[2]), "r"(a[3]), "r"(b0), "r"(b1));
}

// ---------------- split-bf16 HMMA GEMM (R9 config) + fused QKV rope epilogue ----
// 128 threads, 4 warps (2x2, warp tile 32x64), CTA tile 64x128, K-chunk 32,
// single barrier per chunk, 4 CTAs/SM.
__global__ __launch_bounds__(128, 4) void hgemm_kernel(
    const bf16* __restrict__ Ahi, const bf16* __restrict__ Alo,
    const bf16* __restrict__ Whi, const bf16* __restrict__ Wlo,
    const float* __restrict__ bias,
    float* __restrict__ Cf, bf16* __restrict__ Chi, bf16* __restrict__ Clo,
    int N, int cinLog2, int nseg, int pad, int flags,
    const int* __restrict__ lengths)
{
    extern __shared__ __align__(16) char smem[];
    const uint32_t sb = smem_u32(smem);
    const uint32_t sAHI = sb, sALO = sb + 8192, sBHI = sb + 16384, sBLO = sb + 32768;

    int t = threadIdx.x, wid = t >> 5, lane = t & 31;
    int m0 = blockIdx.y * 64, n0 = blockIdx.x * 128;
    int cin  = 1 << cinLog2;
    int Kdim = nseg << cinLog2;
    int nch  = Kdim >> 5;
    int wm = (wid >> 1) * 32, wn = (wid & 1) * 64;

    float acc[2][8][4];
#pragma unroll
    for (int i = 0; i < 2; i++)
#pragma unroll
        for (int j = 0; j < 8; j++)
#pragma unroll
            for (int e = 0; e < 4; e++) acc[i][j][e] = 0.f;

    auto load_chunk = [&](int kc) {
        int kh4 = (kc & 1) * 4;
        int kk0 = kc << 5;
        int seg = kk0 >> cinLog2;
        int ci0 = kk0 & (cin - 1);
#pragma unroll
        for (int it = 0; it < 2; it++) {
            int idx = t + it * 128;
            int r = idx >> 2, c = idx & 3;
            int m = m0 + r;
            const bf16 *sh = Ahi, *sl = Alo;
            int sz = 16;
            if (nseg == 1) {
                size_t off = (size_t)m * cin + kk0 + c * 8;
                sh += off; sl += off;
            } else {
                int s = m & (S_ - 1);
                int srow = s + seg - pad;
                if (srow >= 0 && srow < S_) {
                    size_t off = (size_t)(m + srow - s) * cin + ci0 + c * 8;
                    sh += off; sl += off;
                } else sz = 0;
            }
            uint32_t d = SWZ128(r, kh4 + c);
            cpa16(sAHI + d, sh, sz);
            cpa16(sALO + d, sl, sz);
        }
#pragma unroll
        for (int it = 0; it < 4; it++) {
            int idx = t + it * 128;
            int r = idx >> 2, c = idx & 3;
            int n = n0 + r;
            int sz = (n < N) ? 16 : 0;
            size_t off = (n < N) ? ((size_t)n * Kdim + kk0 + c * 8) : 0;
            uint32_t d = SWZ128(r, kh4 + c);
            cpa16(sBHI + d, Whi + off, sz);
            cpa16(sBLO + d, Wlo + off, sz);
        }
        asm volatile("cp.async.commit_group;");
    };

    int rsel = lane & 15, chalf = lane >> 4;
    auto compute_chunk = [&](int kc) {
        int kh4 = (kc & 1) * 4;
#pragma unroll
        for (int ks = 0; ks < 2; ks++) {
            int cc = kh4 + ks * 2 + chalf;
            uint32_t ah[2][4], al[2][4];
#pragma unroll
            for (int i = 0; i < 2; i++) {
                int rr = wm + i * 16 + rsel;
                uint32_t off = SWZ128(rr, cc);
                ldsm4(ah[i], sAHI + off);
                ldsm4(al[i], sALO + off);
            }
#pragma unroll
            for (int jj = 0; jj < 4; jj++) {
                uint32_t bh[4], bl[4];
                int rr = wn + jj * 16 + rsel;
                uint32_t off = SWZ128(rr, cc);
                ldsm4(bh, sBHI + off);
                ldsm4(bl, sBLO + off);
                mma16816(acc[0][jj * 2 + 0], ah[0], bh[0], bh[2]);
                mma16816(acc[0][jj * 2 + 1], ah[0], bh[1], bh[3]);
                mma16816(acc[1][jj * 2 + 0], ah[1], bh[0], bh[2]);
                mma16816(acc[1][jj * 2 + 1], ah[1], bh[1], bh[3]);
                mma16816(acc[0][jj * 2 + 0], ah[0], bl[0], bl[2]);
                mma16816(acc[0][jj * 2 + 1], ah[0], bl[1], bl[3]);
                mma16816(acc[1][jj * 2 + 0], ah[1], bl[0], bl[2]);
                mma16816(acc[1][jj * 2 + 1], ah[1], bl[1], bl[3]);
                mma16816(acc[0][jj * 2 + 0], al[0], bh[0], bh[2]);
                mma16816(acc[0][jj * 2 + 1], al[0], bh[1], bh[3]);
                mma16816(acc[1][jj * 2 + 0], al[1], bh[0], bh[2]);
                mma16816(acc[1][jj * 2 + 1], al[1], bh[1], bh[3]);
            }
        }
    };

    load_chunk(0);
    for (int kc = 0; kc < nch; kc++) {
        asm volatile("cp.async.wait_group 0;");
        __syncthreads();
        if (kc + 1 < nch) load_chunk(kc + 1);
        compute_chunk(kc);
    }

    int r0 = lane >> 2, c0 = (lane & 3) * 2;

    // ---- fused QKV epilogue: bias + rope (register pairs) + split-store ----
    if (flags & FLAG_QKV) {
        // bias add in place
#pragma unroll
        for (int i = 0; i < 2; i++)
#pragma unroll
            for (int j = 0; j < 8; j++) {
                int nb = n0 + wn + j * 8 + c0;
                float b0 = __ldg(bias + nb), b1 = __ldg(bias + nb + 1);
                acc[i][j][0] += b0; acc[i][j][1] += b1;
                acc[i][j][2] += b0; acc[i][j][3] += b1;
            }
        int region = n0 >> 9;   // 0=q, 1=k, 2=v (tile never straddles)
        bf16 *dh, *dl;
        if (region == 0)      { dh = g_qsh; dl = g_qsl; }
        else if (region == 1) { dh = g_ksh; dl = g_ksl; }
        else                  { dh = g_vsh; dl = g_vsl; }
        if (region < 2) {
            // rope: partner col = n^32 -> acc j^4 in SAME thread; theta idx = col&31
#pragma unroll
            for (int i = 0; i < 2; i++) {
                int mA = m0 + wm + i * 16 + r0;
                int sA = mA & (S_ - 1), sB = (mA + 8) & (S_ - 1);
#pragma unroll
                for (int j = 0; j < 4; j++) {
                    int jp = j + 4;
                    int t0 = (j * 8 + c0) & 31;      // = j*8+c0 (<31)
                    const float2* rA = g_rope + sA * 32 + t0;
                    const float2* rB = g_rope + sB * 32 + t0;
#pragma unroll
                    for (int e = 0; e < 2; e++) {
                        float2 cA = rA[e], cB = rB[e];
                        float xj = acc[i][j][e],      xp = acc[i][jp][e];
                        acc[i][j][e]  = xj * cA.x - xp * cA.y;
                        acc[i][jp][e] = xp * cA.x + xj * cA.y;
                        xj = acc[i][j][e + 2]; xp = acc[i][jp][e + 2];
                        acc[i][j][e + 2]  = xj * cB.x - xp * cB.y;
                        acc[i][jp][e + 2] = xp * cB.x + xj * cB.y;
                    }
                }
            }
        }
#pragma unroll
        for (int i = 0; i < 2; i++) {
            int mA = m0 + wm + i * 16 + r0, mB = mA + 8;
#pragma unroll
            for (int j = 0; j < 8; j++) {
                int nc = (n0 + wn + j * 8 + c0) & (H_ - 1);
                bf16 h0, l0, h1, l1;
                split_hl(acc[i][j][0], h0, l0); split_hl(acc[i][j][1], h1, l1);
                *(bf162*)(dh + (size_t)mA * H_ + nc) = bf162(h0, h1);
                *(bf162*)(dl + (size_t)mA * H_ + nc) = bf162(l0, l1);
                split_hl(acc[i][j][2], h0, l0); split_hl(acc[i][j][3], h1, l1);
                *(bf162*)(dh + (size_t)mB * H_ + nc) = bf162(h0, h1);
                *(bf162*)(dl + (size_t)mB * H_ + nc) = bf162(l0, l1);
            }
        }
        return;
    }

    // ---- standard epilogue ----
#pragma unroll
    for (int i = 0; i < 2; i++) {
        int mA = m0 + wm + i * 16 + r0;
        int mB = mA + 8;
        int sA = mA & (S_ - 1), bA = mA >> 9;
        int sB = mB & (S_ - 1), bB = mB >> 9;
        float mvA = 1.f, mvB = 1.f;
        if (flags & FLAG_MASK) {
            mvA = (sA >= lengths[bA]) ? 1.f : 0.f;   // reference's inverted mask
            mvB = (sB >= lengths[bB]) ? 1.f : 0.f;
        }
#pragma unroll
        for (int j = 0; j < 8; j++) {
            int nb = n0 + wn + j * 8 + c0;
            if (nb >= N) continue;
            float b0 = __ldg(bias + nb);
            float b1 = (nb + 1 < N) ? __ldg(bias + nb + 1) : 0.f;
            float v00 = acc[i][j][0] + b0, v01 = acc[i][j][1] + b1;
            float v10 = acc[i][j][2] + b0, v11 = acc[i][j][3] + b1;
            if (flags & FLAG_RELU) {
                v00 = fmaxf(v00, 0.f); v01 = fmaxf(v01, 0.f);
                v10 = fmaxf(v10, 0.f); v11 = fmaxf(v11, 0.f);
            }
            v00 *= mvA; v01 *= mvA; v10 *= mvB; v11 *= mvB;
            if (flags & FLAG_TRANS) {
                Cf[((size_t)bA * N + nb) * S_ + sA] = v00;
                Cf[((size_t)bB * N + nb) * S_ + sB] = v10;
                if (nb + 1 < N) {
                    Cf[((size_t)bA * N + nb + 1) * S_ + sA] = v01;
                    Cf[((size_t)bB * N + nb + 1) * S_ + sB] = v11;
                }
            } else {
                if (Cf) {
                    *(float2*)(Cf + (size_t)mA * N + nb) = make_float2(v00, v01);
                    *(float2*)(Cf + (size_t)mB * N + nb) = make_float2(v10, v11);
                }
                if (Chi) {
                    bf16 h0, l0, h1, l1;
                    split_hl(v00, h0, l0); split_hl(v01, h1, l1);
                    *(bf162*)(Chi + (size_t)mA * N + nb) = bf162(h0, h1);
                    *(bf162*)(Clo + (size_t)mA * N + nb) = bf162(l0, l1);
                    split_hl(v10, h0, l0); split_hl(v11, h1, l1);
                    *(bf162*)(Chi + (size_t)mB * N + nb) = bf162(h0, h1);
                    *(bf162*)(Clo + (size_t)mB * N + nb) = bf162(l0, l1);
                }
            }
        }
    }
}

// ---------------- HMMA flash attention on pre-split planes ----------------
__global__ __launch_bounds__(128) void attn_kernel(
    const bf16* __restrict__ qsh, const bf16* __restrict__ qsl,
    const bf16* __restrict__ ksh, const bf16* __restrict__ ksl,
    const bf16* __restrict__ vsh, const bf16* __restrict__ vsl,
    bf16* __restrict__ ohi, bf16* __restrict__ olo,
    const int* __restrict__ lengths)
{
    extern __shared__ __align__(16) char sm[];
    const uint32_t sb = smem_u32(sm);
    const uint32_t QH = 0, QL = 8192, KH = 16384, KL = 24576, VH = 32768, VL = 40960;

    int t = threadIdx.x, wid = t >> 5, lane = t & 31;
    int qt = blockIdx.x, hh = blockIdx.y, b = blockIdx.z;
    int len = lengths[b];

#pragma unroll
    for (int it = 0; it < 4; it++) {
        int idx = t + it * 128;
        int r = idx >> 3, c = idx & 7;
        size_t src = ((size_t)b * S_ + qt * 64 + r) * H_ + hh * HD_ + c * 8;
        uint32_t d = SWZ128(r, c);
        cpa16(sb + QH + d, qsh + src, 16);
        cpa16(sb + QL + d, qsl + src, 16);
    }
    asm volatile("cp.async.commit_group;");
    asm volatile("cp.async.wait_group 0;");
    __syncthreads();

    int rsel = lane & 15, chalf = lane >> 4;
    uint32_t qh[4][4], ql[4][4];
#pragma unroll
    for (int ks = 0; ks < 4; ks++) {
        int rr = wid * 16 + rsel;
        uint32_t off = SWZ128(rr, ks * 2 + chalf);
        ldsm4(qh[ks], sb + QH + off);
        ldsm4(ql[ks], sb + QL + off);
    }

    float oc[8][4];
#pragma unroll
    for (int dt = 0; dt < 8; dt++)
#pragma unroll
        for (int e = 0; e < 4; e++) oc[dt][e] = 0.f;
    float m0 = -INFINITY, m1 = -INFINITY, ls0 = 0.f, ls1 = 0.f;

    int kt0 = len >> 6;
    if (kt0 > 7) kt0 = 7;

    for (int kt = kt0; kt < 8; kt++) {
        __syncthreads();
#pragma unroll
        for (int it = 0; it < 4; it++) {
            int idx = t + it * 128;
            int r = idx >> 3, c = idx & 7;
            size_t src = ((size_t)b * S_ + kt * 64 + r) * H_ + hh * HD_ + c * 8;
            uint32_t d = SWZ128(r, c);
            cpa16(sb + KH + d, ksh + src, 16);
            cpa16(sb + KL + d, ksl + src, 16);
            cpa16(sb + VH + d, vsh + src, 16);
            cpa16(sb + VL + d, vsl + src, 16);
        }
        asm volatile("cp.async.commit_group;");
        asm volatile("cp.async.wait_group 0;");
        __syncthreads();

        float sv[8][4];
#pragma unroll
        for (int jt = 0; jt < 8; jt++)
#pragma unroll
            for (int e = 0; e < 4; e++) sv[jt][e] = 0.f;
#pragma unroll
        for (int ks = 0; ks < 4; ks++) {
#pragma unroll
            for (int jj = 0; jj < 4; jj++) {
                uint32_t bh[4], bl[4];
                int rr = jj * 16 + rsel;
                uint32_t off = SWZ128(rr, ks * 2 + chalf);
                ldsm4(bh, sb + KH + off);
                ldsm4(bl, sb + KL + off);
                mma16816(sv[jj * 2 + 0], qh[ks], bh[0], bh[2]);
                mma16816(sv[jj * 2 + 1], qh[ks], bh[1], bh[3]);
                mma16816(sv[jj * 2 + 0], qh[ks], bl[0], bl[2]);
                mma16816(sv[jj * 2 + 1], qh[ks], bl[1], bl[3]);
                mma16816(sv[jj * 2 + 0], ql[ks], bh[0], bh[2]);
                mma16816(sv[jj * 2 + 1], ql[ks], bh[1], bh[3]);
            }
        }

        int colb = kt * 64 + (lane & 3) * 2;
        float rm0 = -INFINITY, rm1 = -INFINITY;
#pragma unroll
        for (int jt = 0; jt < 8; jt++) {
#pragma unroll
            for (int e = 0; e < 2; e++) {
                int kp = colb + jt * 8 + e;
                bool keep = (kp >= len);
                float v0 = sv[jt][e] * 0.125f;
                float v1 = sv[jt][2 + e] * 0.125f;
                sv[jt][e]     = keep ? v0 : -1e9f;
                sv[jt][2 + e] = keep ? v1 : -1e9f;
                rm0 = fmaxf(rm0, sv[jt][e]);
                rm1 = fmaxf(rm1, sv[jt][2 + e]);
            }
        }
        rm0 = fmaxf(rm0, __shfl_xor_sync(0xffffffffu, rm0, 1));
        rm0 = fmaxf(rm0, __shfl_xor_sync(0xffffffffu, rm0, 2));
        rm1 = fmaxf(rm1, __shfl_xor_sync(0xffffffffu, rm1, 1));
        rm1 = fmaxf(rm1, __shfl_xor_sync(0xffffffffu, rm1, 2));
        float mn0 = fmaxf(m0, rm0), mn1 = fmaxf(m1, rm1);
        float a0 = __expf(m0 - mn0), a1 = __expf(m1 - mn1);
        m0 = mn0; m1 = mn1;
        float s0 = 0.f, s1 = 0.f;
#pragma unroll
        for (int jt = 0; jt < 8; jt++) {
            sv[jt][0] = __expf(sv[jt][0] - mn0);
            sv[jt][1] = __expf(sv[jt][1] - mn0);
            sv[jt][2] = __expf(sv[jt][2] - mn1);
            sv[jt][3] = __expf(sv[jt][3] - mn1);
            s0 += sv[jt][0] + sv[jt][1];
            s1 += sv[jt][2] + sv[jt][3];
        }
        s0 += __shfl_xor_sync(0xffffffffu, s0, 1);
        s0 += __shfl_xor_sync(0xffffffffu, s0, 2);
        s1 += __shfl_xor_sync(0xffffffffu, s1, 1);
        s1 += __shfl_xor_sync(0xffffffffu, s1, 2);
        ls0 = ls0 * a0 + s0;
        ls1 = ls1 * a1 + s1;
#pragma unroll
        for (int dt = 0; dt < 8; dt++) {
            oc[dt][0] *= a0; oc[dt][1] *= a0;
            oc[dt][2] *= a1; oc[dt][3] *= a1;
        }

#pragma unroll
        for (int jp = 0; jp < 4; jp++) {
            uint32_t pah[4], pal[4];
#pragma unroll
            for (int half = 0; half < 2; half++) {
                bf16 h0, lo0, h1, lo1, h2, lo2, h3, lo3;
                split_hl(sv[2 * jp + half][0], h0, lo0);
                split_hl(sv[2 * jp + half][1], h1, lo1);
                split_hl(sv[2 * jp + half][2], h2, lo2);
                split_hl(sv[2 * jp + half][3], h3, lo3);
                pah[2 * half + 0] = packb(h0, h1);  pal[2 * half + 0] = packb(lo0, lo1);
                pah[2 * half + 1] = packb(h2, h3);  pal[2 * half + 1] = packb(lo2, lo3);
            }
            int vrow = jp * 16 + ((lane >> 3) & 1) * 8 + (lane & 7);
#pragma unroll
            for (int g = 0; g < 4; g++) {
                int cch = 2 * g + (lane >> 4);
                uint32_t off = SWZ128(vrow, cch);
                uint32_t vh[4], vl[4];
                ldsm4t(vh, sb + VH + off);
                ldsm4t(vl, sb + VL + off);
                mma16816(oc[2 * g],     pah, vh[0], vh[1]);
                mma16816(oc[2 * g + 1], pah, vh[2], vh[3]);
                mma16816(oc[2 * g],     pah, vl[0], vl[1]);
                mma16816(oc[2 * g + 1], pah, vl[2], vl[3]);
                mma16816(oc[2 * g],     pal, vh[0], vh[1]);
                mma16816(oc[2 * g + 1], pal, vh[2], vh[3]);
            }
        }
    }

    float i0 = 1.f / ls0, i1 = 1.f / ls1;
    int r0 = qt * 64 + wid * 16 + (lane >> 2);
#pragma unroll
    for (int dt = 0; dt < 8; dt++) {
        int d = hh * HD_ + dt * 8 + (lane & 3) * 2;
        size_t o0 = ((size_t)b * S_ + r0) * H_ + d;
        size_t o1 = o0 + (size_t)8 * H_;
        bf16 h0, lo0, h1, lo1;
        split_hl(oc[dt][0] * i0, h0, lo0);
        split_hl(oc[dt][1] * i0, h1, lo1);
        *(bf162*)(ohi + o0) = bf162(h0, h1);
        *(bf162*)(olo + o0) = bf162(lo0, lo1);
        split_hl(oc[dt][2] * i1, h0, lo0);
        split_hl(oc[dt][3] * i1, h1, lo1);
        *(bf162*)(ohi + o1) = bf162(h0, h1);
        *(bf162*)(olo + o1) = bf162(lo0, lo1);
    }
}

// ---------------- LayerNorm (residual add + optional split outputs) ----------------
__global__ __launch_bounds__(128) void ln_kernel(
    const float* __restrict__ x, const float* __restrict__ res,
    const float* __restrict__ g, const float* __restrict__ be,
    float* __restrict__ out, bf16* __restrict__ ohi, bf16* __restrict__ olo, int C)
{
    int m = blockIdx.x, t = threadIdx.x;
    int nv = C >> 2;
    float4 v = make_float4(0.f, 0.f, 0.f, 0.f);
    if (t < nv) {
        v = ((const float4*)(x + (size_t)m * C))[t];
        if (res) {
            float4 w = ((const float4*)(res + (size_t)m * C))[t];
            v.x += w.x; v.y += w.y; v.z += w.z; v.w += w.w;
        }
    }
    float sum = v.x + v.y + v.z + v.w;
    float sq  = v.x * v.x + v.y * v.y + v.z * v.z + v.w * v.w;
#pragma unroll
    for (int off = 16; off; off >>= 1) {
        sum += __shfl_xor_sync(0xffffffffu, sum, off);
        sq  += __shfl_xor_sync(0xffffffffu, sq,  off);
    }
    __shared__ float s1[4], s2[4];
    if ((t & 31) == 0) { s1[t >> 5] = sum; s2[t >> 5] = sq; }
    __syncthreads();
    sum = s1[0] + s1[1] + s1[2] + s1[3];
    sq  = s2[0] + s2[1] + s2[2] + s2[3];
    float mean = sum / C;
    float var  = sq / C - mean * mean;
    float inv  = rsqrtf(var + 1e-5f);
    if (t < nv) {
        float4 gv = ((const float4*)g)[t];
        float4 bv = ((const float4*)be)[t];
        float4 o4;
        o4.x = (v.x - mean) * inv * gv.x + bv.x;
        o4.y = (v.y - mean) * inv * gv.y + bv.y;
        o4.z = (v.z - mean) * inv * gv.z + bv.z;
        o4.w = (v.w - mean) * inv * gv.w + bv.w;
        if (out) ((float4*)(out + (size_t)m * C))[t] = o4;
        if (ohi) {
            bf16 h0, l0, h1, l1, h2, l2, h3, l3;
            split_hl(o4.x, h0, l0); split_hl(o4.y, h1, l1);
            split_hl(o4.z, h2, l2); split_hl(o4.w, h3, l3);
            *(bf162*)(ohi + (size_t)m * C + t * 4)     = bf162(h0, h1);
            *(bf162*)(ohi + (size_t)m * C + t * 4 + 2) = bf162(h2, h3);
            *(bf162*)(olo + (size_t)m * C + t * 4)     = bf162(l0, l1);
            *(bf162*)(olo + (size_t)m * C + t * 4 + 2) = bf162(l2, l3);
        }
    }
}

// ---------------- small kernels ----------------
__global__ __launch_bounds__(256) void embed_kernel(
    const int* __restrict__ x, const float* __restrict__ emb,
    float* __restrict__ h, bf16* __restrict__ hh, bf16* __restrict__ hl)
{
    int idx = blockIdx.x * blockDim.x + threadIdx.x;
    if (idx >= M_ * (H_ / 4)) return;
    int m = idx >> 7, c4 = idx & 127;
    int tok = x[m];
    float4 e = ((const float4*)(emb + (size_t)tok * H_))[c4];
    const float sc = 22.62741699796952f;  // sqrt(512)
    e.x *= sc; e.y *= sc; e.z *= sc; e.w *= sc;
    ((float4*)(h + (size_t)m * H_))[c4] = e;
    bf16 h0, l0, h1, l1, h2, l2, h3, l3;
    split_hl(e.x, h0, l0); split_hl(e.y, h1, l1);
    split_hl(e.z, h2, l2); split_hl(e.w, h3, l3);
    *(bf162*)(hh + (size_t)m * H_ + c4 * 4)     = bf162(h0, h1);
    *(bf162*)(hh + (size_t)m * H_ + c4 * 4 + 2) = bf162(h2, h3);
    *(bf162*)(hl + (size_t)m * H_ + c4 * 4)     = bf162(l0, l1);
    *(bf162*)(hl + (size_t)m * H_ + c4 * 4 + 2) = bf162(l2, l3);
}

__global__ __launch_bounds__(256) void maskmul_kernel(
    const float* __restrict__ in, bf16* __restrict__ ohi, bf16* __restrict__ olo,
    const int* __restrict__ lengths)
{
    int idx = blockIdx.x * blockDim.x + threadIdx.x;
    if (idx >= M_ * H_) return;
    int m = idx >> 9;
    int s = m & (S_ - 1), b = m >> 9;
    float v = in[idx] * ((s >= lengths[b]) ? 1.f : 0.f);  // inverted mask
    bf16 h, l;
    split_hl(v, h, l);
    ohi[idx] = h; olo[idx] = l;
}

#define NW1 (L_*F_*H_*3)
#define NW2 (L_*H_*F_*3)
#define ND1 (FD_*H_*3)
#define ND2 (FD_*FD_*3)
__global__ __launch_bounds__(256) void prep_conv_kernel(
    const float* __restrict__ c1w, const float* __restrict__ c2w,
    const float* __restrict__ d1w, const float* __restrict__ d2w)
{
    int idx = blockIdx.x * blockDim.x + threadIdx.x;
    const float* src; bf16 *dh, *dl; int CI; int base;
    if (idx < NW1)                        { src = c1w; dh = g_w1h; dl = g_w1l; CI = H_;  base = idx; }
    else if (idx < NW1 + NW2)             { src = c2w; dh = g_w2h; dl = g_w2l; CI = F_;  base = idx - NW1; }
    else if (idx < NW1 + NW2 + ND1)       { src = d1w; dh = g_d1h; dl = g_d1l; CI = H_;  base = idx - NW1 - NW2; }
    else if (idx < NW1 + NW2 + ND1 + ND2) { src = d2w; dh = g_d2h; dl = g_d2l; CI = FD_; base = idx - NW1 - NW2 - ND1; }
    else return;
    int kk = base % 3;
    int rest = base / 3;
    int ci = rest % CI;
    int co = rest / CI;
    float v = src[base];
    bf16 h, l; split_hl(v, h, l);
    size_t o = (size_t)co * (3 * CI) + kk * CI + ci;
    dh[o] = h; dl[o] = l;
}

#define NQKV (L_*3*H_*H_)
#define NWO  (L_*H_*H_)
#define NPJ  (OUT_*H_)
#define NBQ  (L_*3*H_)
#define NRT  (S_*32)
__global__ __launch_bounds__(256) void prep_lin_kernel(
    const float* __restrict__ Wq, const float* __restrict__ Wk,
    const float* __restrict__ Wv, const float* __restrict__ Wo,
    const float* __restrict__ pj,
    const float* __restrict__ bq, const float* __restrict__ bk,
    const float* __restrict__ bv)
{
    int idx = blockIdx.x * blockDim.x + threadIdx.x;
    if (idx < NQKV) {
        int e = idx % H_;
        int n = (idx / H_) % (3 * H_);
        int l = idx / (3 * H_ * H_);
        const float* W = (n < H_) ? Wq : (n < 2 * H_) ? Wk : Wv;
        int nn = n & (H_ - 1);
        float v = W[(size_t)l * H_ * H_ + (size_t)nn * H_ + e];
        bf16 h, lo; split_hl(v, h, lo);
        g_wqkvh[idx] = h; g_wqkvl[idx] = lo;
        return;
    }
    int i2 = idx - NQKV;
    if (i2 < NWO) {
        float v = Wo[i2];
        bf16 h, lo; split_hl(v, h, lo);
        g_woh[i2] = h; g_wol[i2] = lo;
        return;
    }
    int i3 = i2 - NWO;
    if (i3 < NPJ) {
        float v = pj[i3];
        bf16 h, lo; split_hl(v, h, lo);
        g_pjh[i3] = h; g_pjl[i3] = lo;
        return;
    }
    int i4 = i3 - NPJ;
    if (i4 < NBQ) {
        int n = i4 % (3 * H_);
        int l = i4 / (3 * H_);
        const float* bb = (n < H_) ? bq : (n < 2 * H_) ? bk : bv;
        g_bqkv[i4] = bb[l * H_ + (n & (H_ - 1))];
        return;
    }
    int i5 = i4 - NBQ;
    if (i5 < NRT) {
        int s = i5 >> 5, j = i5 & 31;
        float th = expf(-(float)j * 0.28782313662425574f);
        float sn, cs;
        sincosf((float)s * th, &sn, &cs);
        g_rope[i5] = make_float2(cs, sn);
    }
}

__global__ __launch_bounds__(256) void dp_final_kernel(
    const float* __restrict__ x, const float* __restrict__ w,
    const float* __restrict__ pb, const int* __restrict__ lengths,
    float* __restrict__ out)
{
    int warp = threadIdx.x >> 5, lane = threadIdx.x & 31;
    int m = blockIdx.x * 8 + warp;
    if (m >= M_) return;
    const float* xr = x + (size_t)m * FD_;
    float s = 0.f;
    for (int c = lane; c < FD_; c += 32) s += xr[c] * w[c];
#pragma unroll
    for (int off = 16; off; off >>= 1) s += __shfl_xor_sync(0xffffffffu, s, off);
    if (lane == 0) {
        int b = m >> 9, sp = m & (S_ - 1);
        float mv = (sp >= lengths[b]) ? 1.f : 0.f;
        float val = (s + pb[0]) * mv;
        out[(size_t)b * S_ + sp] = ceilf(expf(val));
    }
}

// ---------------- orchestration ----------------
extern "C" void kernel_launch(void* const* d_in, const int* in_sizes, int n_in,
                              void* d_out, int out_size)
{
    const int*   x      = (const int*)  d_in[0];
    const int*   xlen   = (const int*)  d_in[1];
    const float* emb    = (const float*)d_in[2];
    const float* Wq     = (const float*)d_in[3];
    const float* bq     = (const float*)d_in[4];
    const float* Wk     = (const float*)d_in[5];
    const float* bk     = (const float*)d_in[6];
    const float* Wv     = (const float*)d_in[7];
    const float* bv     = (const float*)d_in[8];
    const float* Wo     = (const float*)d_in[9];
    const float* bo     = (const float*)d_in[10];
    const float* c1w    = (const float*)d_in[11];
    const float* c1b    = (const float*)d_in[12];
    const float* c2w    = (const float*)d_in[13];
    const float* c2b    = (const float*)d_in[14];
    const float* ln1g   = (const float*)d_in[15];
    const float* ln1b   = (const float*)d_in[16];
    const float* ln2g   = (const float*)d_in[17];
    const float* ln2b   = (const float*)d_in[18];
    const float* projw  = (const float*)d_in[19];
    const float* projb  = (const float*)d_in[20];
    const float* dpc1w  = (const float*)d_in[21];
    const float* dpc1b  = (const float*)d_in[22];
    const float* dpln1g = (const float*)d_in[23];
    const float* dpln1b = (const float*)d_in[24];
    const float* dpc2w  = (const float*)d_in[25];
    const float* dpc2b  = (const float*)d_in[26];
    const float* dpln2g = (const float*)d_in[27];
    const float* dpln2b = (const float*)d_in[28];
    const float* dppw   = (const float*)d_in[29];
    const float* dppb   = (const float*)d_in[30];
    float* out = (float*)d_out;

    float *h, *x1, *op, *cv2, *bqkv;
    bf16 *hh, *hl, *x1h, *x1l, *ah, *al, *midh, *midl, *mkh, *mkl, *dpxh, *dpxl;
    bf16 *qsh, *qsl, *ksh, *ksl, *vsh, *vsl;
    bf16 *wqh, *wql, *woh, *wol, *w1h, *w1l, *w2h, *w2l, *pjh, *pjl, *d1h, *d1l, *d2h, *d2l;
    cudaGetSymbolAddress((void**)&h,    g_h);
    cudaGetSymbolAddress((void**)&x1,   g_x1);
    cudaGetSymbolAddress((void**)&op,   g_op);
    cudaGetSymbolAddress((void**)&cv2,  g_cv2);
    cudaGetSymbolAddress((void**)&hh,   g_hh);
    cudaGetSymbolAddress((void**)&hl,   g_hl);
    cudaGetSymbolAddress((void**)&x1h,  g_x1h);
    cudaGetSymbolAddress((void**)&x1l,  g_x1l);
    cudaGetSymbolAddress((void**)&ah,   g_ah);
    cudaGetSymbolAddress((void**)&al,   g_al);
    cudaGetSymbolAddress((void**)&midh, g_midh);
    cudaGetSymbolAddress((void**)&midl, g_midl);
    cudaGetSymbolAddress((void**)&mkh,  g_mkh);
    cudaGetSymbolAddress((void**)&mkl,  g_mkl);
    cudaGetSymbolAddress((void**)&dpxh, g_dpxh);
    cudaGetSymbolAddress((void**)&dpxl, g_dpxl);
    cudaGetSymbolAddress((void**)&qsh,  g_qsh);
    cudaGetSymbolAddress((void**)&qsl,  g_qsl);
    cudaGetSymbolAddress((void**)&ksh,  g_ksh);
    cudaGetSymbolAddress((void**)&ksl,  g_ksl);
    cudaGetSymbolAddress((void**)&vsh,  g_vsh);
    cudaGetSymbolAddress((void**)&vsl,  g_vsl);
    cudaGetSymbolAddress((void**)&wqh,  g_wqkvh);
    cudaGetSymbolAddress((void**)&wql,  g_wqkvl);
    cudaGetSymbolAddress((void**)&woh,  g_woh);
    cudaGetSymbolAddress((void**)&wol,  g_wol);
    cudaGetSymbolAddress((void**)&w1h,  g_w1h);
    cudaGetSymbolAddress((void**)&w1l,  g_w1l);
    cudaGetSymbolAddress((void**)&w2h,  g_w2h);
    cudaGetSymbolAddress((void**)&w2l,  g_w2l);
    cudaGetSymbolAddress((void**)&pjh,  g_pjh);
    cudaGetSymbolAddress((void**)&pjl,  g_pjl);
    cudaGetSymbolAddress((void**)&d1h,  g_d1h);
    cudaGetSymbolAddress((void**)&d1l,  g_d1l);
    cudaGetSymbolAddress((void**)&d2h,  g_d2h);
    cudaGetSymbolAddress((void**)&d2l,  g_d2l);
    cudaGetSymbolAddress((void**)&bqkv, g_bqkv);

    cudaFuncSetAttribute((const void*)attn_kernel,
                         cudaFuncAttributeMaxDynamicSharedMemorySize, 49152);
    cudaFuncSetAttribute((const void*)hgemm_kernel,
                         cudaFuncAttributeMaxDynamicSharedMemorySize, 49152);

    {
        int tot = NW1 + NW2 + ND1 + ND2;
        prep_conv_kernel<<<(tot + 255) / 256, 256>>>(c1w, c2w, dpc1w, dpc2w);
        tot = NQKV + NWO + NPJ + NBQ + NRT;
        prep_lin_kernel<<<(tot + 255) / 256, 256>>>(Wq, Wk, Wv, Wo, projw, bq, bk, bv);
    }
    embed_kernel<<<M_ * (H_ / 4) / 256, 256>>>(x, emb, h, hh, hl);

    const int SM_G = 49152;
    dim3 gQKV(3 * H_ / 128, M_ / 64);   // (12,256)
    dim3 gH(H_ / 128, M_ / 64);         // (4,256)
    dim3 gF(F_ / 128, M_ / 64);         // (16,256)
    dim3 gMu(1, M_ / 64);
    dim3 gDp(FD_ / 128, M_ / 64);       // (2,256)
    dim3 ga(S_ / 64, NH_, B_);

    for (int l = 0; l < L_; l++) {
        size_t wOff = (size_t)l * H_ * H_;
        size_t wqOff = (size_t)l * 3 * H_ * H_;
        hgemm_kernel<<<gQKV, 128, SM_G>>>(hh, hl, wqh + wqOff, wql + wqOff,
                                          bqkv + l * 3 * H_, nullptr, nullptr, nullptr,
                                          3 * H_, 9, 1, 0, FLAG_QKV, xlen);
        attn_kernel<<<ga, 128, SM_G>>>(qsh, qsl, ksh, ksl, vsh, vsl, ah, al, xlen);
        hgemm_kernel<<<gH, 128, SM_G>>>(ah, al, woh + wOff, wol + wOff,
                                        bo + l * H_, op, nullptr, nullptr,
                                        H_, 9, 1, 0, 0, xlen);
        ln_kernel<<<M_, 128>>>(op, h, ln1g + l * H_, ln1b + l * H_, x1, x1h, x1l, H_);
        hgemm_kernel<<<gF, 128, SM_G>>>(x1h, x1l,
                                        w1h + (size_t)l * F_ * 3 * H_, w1l + (size_t)l * F_ * 3 * H_,
                                        c1b + l * F_, nullptr, midh, midl,
                                        F_, 9, 3, 1, FLAG_RELU, xlen);
        hgemm_kernel<<<gH, 128, SM_G>>>(midh, midl,
                                        w2h + (size_t)l * H_ * 3 * F_, w2l + (size_t)l * H_ * 3 * F_,
                                        c2b + l * H_, cv2, nullptr, nullptr,
                                        H_, 11, 3, 1, 0, xlen);
        ln_kernel<<<M_, 128>>>(cv2, x1, ln2g + l * H_, ln2b + l * H_, h, hh, hl, H_);
    }

    hgemm_kernel<<<gMu, 128, SM_G>>>(hh, hl, pjh, pjl, projb, out, nullptr, nullptr,
                                     OUT_, 9, 1, 0, FLAG_TRANS, xlen);

    maskmul_kernel<<<M_ * H_ / 256, 256>>>(h, mkh, mkl, xlen);
    hgemm_kernel<<<gDp, 128, SM_G>>>(mkh, mkl, d1h, d1l, dpc1b, op, nullptr, nullptr,
                                     FD_, 9, 3, 1, FLAG_RELU | FLAG_MASK, xlen);
    ln_kernel<<<M_, 128>>>(op, nullptr, dpln1g, dpln1b, cv2, dpxh, dpxl, FD_);
    hgemm_kernel<<<gDp, 128, SM_G>>>(dpxh, dpxl, d2h, d2l, dpc2b, op, nullptr, nullptr,
                                     FD_, 8, 3, 1, FLAG_RELU | FLAG_MASK, xlen);
    ln_kernel<<<M_, 128>>>(op, nullptr, dpln2g, dpln2b, x1, nullptr, nullptr, FD_);
    dp_final_kernel<<<M_ / 8, 256>>>(x1, dppw, dppb, xlen,
                                     out + ((size_t)out_size - (size_t)B_ * S_));
}

// round 12
// speedup vs baseline: 1.0574x; 1.0018x over previous
#include <cuda_runtime.h>
#include <cuda_bf16.h>
#include <math.h>
#include <stdint.h>

#define B_   32
#define S_   512
#define H_   512
#define NH_  8
#define HD_  64
#define F_   2048
#define L_   6
#define OUT_ 80
#define FD_  256
#define M_   (B_*S_)   // 16384 tokens

typedef __nv_bfloat16  bf16;
typedef __nv_bfloat162 bf162;

// ---------------- scratch (static device globals) ----------------
__device__ float g_h   [M_*H_];
__device__ float g_x1  [M_*H_];
__device__ float g_op  [M_*H_];
__device__ float g_cv2 [M_*H_];
__device__ bf16  g_hh  [M_*H_],  g_hl  [M_*H_];
__device__ bf16  g_x1h [M_*H_],  g_x1l [M_*H_];
__device__ bf16  g_ah  [M_*H_],  g_al  [M_*H_];
__device__ bf16  g_midh[M_*F_],  g_midl[M_*F_];
__device__ bf16  g_mkh [M_*H_],  g_mkl [M_*H_];
__device__ bf16  g_dpxh[M_*FD_], g_dpxl[M_*FD_];
__device__ bf16  g_qsh[M_*H_], g_qsl[M_*H_];
__device__ bf16  g_ksh[M_*H_], g_ksl[M_*H_];
__device__ bf16  g_vsh[M_*H_], g_vsl[M_*H_];
__device__ bf16  g_wqkvh[L_*3*H_*H_], g_wqkvl[L_*3*H_*H_];
__device__ bf16  g_woh [L_*H_*H_],    g_wol [L_*H_*H_];
__device__ bf16  g_w1h [L_*F_*3*H_],  g_w1l [L_*F_*3*H_];
__device__ bf16  g_w2h [L_*H_*3*F_],  g_w2l [L_*H_*3*F_];
__device__ bf16  g_pjh [OUT_*H_],     g_pjl [OUT_*H_];
__device__ bf16  g_d1h [FD_*3*H_],    g_d1l [FD_*3*H_];
__device__ bf16  g_d2h [FD_*3*FD_],   g_d2l [FD_*3*FD_];
__device__ float g_bqkv[L_*3*H_];
__device__ float2 g_rope[S_*32];

#define FLAG_RELU  1
#define FLAG_MASK  2
#define FLAG_TRANS 4
#define FLAG_QKV   8

#define SWZ128(r,c) ((uint32_t)((r)*128 + ((((c) ^ ((r)&7))) << 4)))

// ---------------- helpers ----------------
__device__ __forceinline__ void split_hl(float x, bf16& h, bf16& l) {
    h = __float2bfloat16_rn(x);
    l = __float2bfloat16_rn(x - __bfloat162float(h));
}

__device__ __forceinline__ uint32_t packb(bf16 x, bf16 y) {
    return (uint32_t)__bfloat16_as_ushort(x) | ((uint32_t)__bfloat16_as_ushort(y) << 16);
}

__device__ __forceinline__ uint32_t smem_u32(const void* p) {
    uint32_t a;
    asm("{ .reg .u64 t; cvta.to.shared.u64 t, %1; cvt.u32.u64 %0, t; }" : "=r"(a) : "l"(p));
    return a;
}

__device__ __forceinline__ void cpa16(uint32_t dst, const void* src, int sz) {
    asm volatile("cp.async.cg.shared.global [%0], [%1], 16, %2;"
                 :: "r"(dst), "l"(src), "r"(sz));
}

__device__ __forceinline__ void ldsm4(uint32_t* r, uint32_t addr) {
    asm volatile("ldmatrix.sync.aligned.m8n8.x4.shared.b16 {%0,%1,%2,%3}, [%4];"
                 : "=r"(r[0]), "=r"(r[1]), "=r"(r[2]), "=r"(r[3]) : "r"(addr));
}

__device__ __forceinline__ void ldsm4t(uint32_t* r, uint32_t addr) {
    asm volatile("ldmatrix.sync.aligned.m8n8.x4.trans.shared.b16 {%0,%1,%2,%3}, [%4];"
                 : "=r"(r[0]), "=r"(r[1]), "=r"(r[2]), "=r"(r[3]) : "r"(addr));
}

__device__ __forceinline__ void mma16816(float* c, const uint32_t* a,
                                         uint32_t b0, uint32_t b1) {
    asm volatile(
        "mma.sync.aligned.m16n8k16.row.col.f32.bf16.bf16.f32 "
        "{%0,%1,%2,%3}, {%4,%5,%6,%7}, {%8,%9}, {%0,%1,%2,%3};"
        : "+f"(c[0]), "+f"(c[1]), "+f"(c[2]), "+f"(c[3])
        : "r"(a[0]), "r"(a[1]), "r"(a[2]), "r"(a[3]), "r"(b0), "r"(b1));
}

// ---------------- split-bf16 HMMA GEMM (R11, unchanged) ----------------
__global__ __launch_bounds__(128, 4) void hgemm_kernel(
    const bf16* __restrict__ Ahi, const bf16* __restrict__ Alo,
    const bf16* __restrict__ Whi, const bf16* __restrict__ Wlo,
    const float* __restrict__ bias,
    float* __restrict__ Cf, bf16* __restrict__ Chi, bf16* __restrict__ Clo,
    int N, int cinLog2, int nseg, int pad, int flags,
    const int* __restrict__ lengths)
{
    extern __shared__ __align__(16) char smem[];
    const uint32_t sb = smem_u32(smem);
    const uint32_t sAHI = sb, sALO = sb + 8192, sBHI = sb + 16384, sBLO = sb + 32768;

    int t = threadIdx.x, wid = t >> 5, lane = t & 31;
    int m0 = blockIdx.y * 64, n0 = blockIdx.x * 128;
    int cin  = 1 << cinLog2;
    int Kdim = nseg << cinLog2;
    int nch  = Kdim >> 5;
    int wm = (wid >> 1) * 32, wn = (wid & 1) * 64;

    float acc[2][8][4];
#pragma unroll
    for (int i = 0; i < 2; i++)
#pragma unroll
        for (int j = 0; j < 8; j++)
#pragma unroll
            for (int e = 0; e < 4; e++) acc[i][j][e] = 0.f;

    auto load_chunk = [&](int kc) {
        int kh4 = (kc & 1) * 4;
        int kk0 = kc << 5;
        int seg = kk0 >> cinLog2;
        int ci0 = kk0 & (cin - 1);
#pragma unroll
        for (int it = 0; it < 2; it++) {
            int idx = t + it * 128;
            int r = idx >> 2, c = idx & 3;
            int m = m0 + r;
            const bf16 *sh = Ahi, *sl = Alo;
            int sz = 16;
            if (nseg == 1) {
                size_t off = (size_t)m * cin + kk0 + c * 8;
                sh += off; sl += off;
            } else {
                int s = m & (S_ - 1);
                int srow = s + seg - pad;
                if (srow >= 0 && srow < S_) {
                    size_t off = (size_t)(m + srow - s) * cin + ci0 + c * 8;
                    sh += off; sl += off;
                } else sz = 0;
            }
            uint32_t d = SWZ128(r, kh4 + c);
            cpa16(sAHI + d, sh, sz);
            cpa16(sALO + d, sl, sz);
        }
#pragma unroll
        for (int it = 0; it < 4; it++) {
            int idx = t + it * 128;
            int r = idx >> 2, c = idx & 3;
            int n = n0 + r;
            int sz = (n < N) ? 16 : 0;
            size_t off = (n < N) ? ((size_t)n * Kdim + kk0 + c * 8) : 0;
            uint32_t d = SWZ128(r, kh4 + c);
            cpa16(sBHI + d, Whi + off, sz);
            cpa16(sBLO + d, Wlo + off, sz);
        }
        asm volatile("cp.async.commit_group;");
    };

    int rsel = lane & 15, chalf = lane >> 4;
    auto compute_chunk = [&](int kc) {
        int kh4 = (kc & 1) * 4;
#pragma unroll
        for (int ks = 0; ks < 2; ks++) {
            int cc = kh4 + ks * 2 + chalf;
            uint32_t ah[2][4], al[2][4];
#pragma unroll
            for (int i = 0; i < 2; i++) {
                int rr = wm + i * 16 + rsel;
                uint32_t off = SWZ128(rr, cc);
                ldsm4(ah[i], sAHI + off);
                ldsm4(al[i], sALO + off);
            }
#pragma unroll
            for (int jj = 0; jj < 4; jj++) {
                uint32_t bh[4], bl[4];
                int rr = wn + jj * 16 + rsel;
                uint32_t off = SWZ128(rr, cc);
                ldsm4(bh, sBHI + off);
                ldsm4(bl, sBLO + off);
                mma16816(acc[0][jj * 2 + 0], ah[0], bh[0], bh[2]);
                mma16816(acc[0][jj * 2 + 1], ah[0], bh[1], bh[3]);
                mma16816(acc[1][jj * 2 + 0], ah[1], bh[0], bh[2]);
                mma16816(acc[1][jj * 2 + 1], ah[1], bh[1], bh[3]);
                mma16816(acc[0][jj * 2 + 0], ah[0], bl[0], bl[2]);
                mma16816(acc[0][jj * 2 + 1], ah[0], bl[1], bl[3]);
                mma16816(acc[1][jj * 2 + 0], ah[1], bl[0], bl[2]);
                mma16816(acc[1][jj * 2 + 1], ah[1], bl[1], bl[3]);
                mma16816(acc[0][jj * 2 + 0], al[0], bh[0], bh[2]);
                mma16816(acc[0][jj * 2 + 1], al[0], bh[1], bh[3]);
                mma16816(acc[1][jj * 2 + 0], al[1], bh[0], bh[2]);
                mma16816(acc[1][jj * 2 + 1], al[1], bh[1], bh[3]);
            }
        }
    };

    load_chunk(0);
    for (int kc = 0; kc < nch; kc++) {
        asm volatile("cp.async.wait_group 0;");
        __syncthreads();
        if (kc + 1 < nch) load_chunk(kc + 1);
        compute_chunk(kc);
    }

    int r0 = lane >> 2, c0 = (lane & 3) * 2;

    // ---- fused QKV epilogue: bias + rope (register pairs) + split-store ----
    if (flags & FLAG_QKV) {
#pragma unroll
        for (int i = 0; i < 2; i++)
#pragma unroll
            for (int j = 0; j < 8; j++) {
                int nb = n0 + wn + j * 8 + c0;
                float b0 = __ldg(bias + nb), b1 = __ldg(bias + nb + 1);
                acc[i][j][0] += b0; acc[i][j][1] += b1;
                acc[i][j][2] += b0; acc[i][j][3] += b1;
            }
        int region = n0 >> 9;   // 0=q, 1=k, 2=v
        bf16 *dh, *dl;
        if (region == 0)      { dh = g_qsh; dl = g_qsl; }
        else if (region == 1) { dh = g_ksh; dl = g_ksl; }
        else                  { dh = g_vsh; dl = g_vsl; }
        if (region < 2) {
#pragma unroll
            for (int i = 0; i < 2; i++) {
                int mA = m0 + wm + i * 16 + r0;
                int sA = mA & (S_ - 1), sB = (mA + 8) & (S_ - 1);
#pragma unroll
                for (int j = 0; j < 4; j++) {
                    int jp = j + 4;
                    int t0 = (j * 8 + c0) & 31;
                    const float2* rA = g_rope + sA * 32 + t0;
                    const float2* rB = g_rope + sB * 32 + t0;
#pragma unroll
                    for (int e = 0; e < 2; e++) {
                        float2 cA = rA[e], cB = rB[e];
                        float xj = acc[i][j][e],      xp = acc[i][jp][e];
                        acc[i][j][e]  = xj * cA.x - xp * cA.y;
                        acc[i][jp][e] = xp * cA.x + xj * cA.y;
                        xj = acc[i][j][e + 2]; xp = acc[i][jp][e + 2];
                        acc[i][j][e + 2]  = xj * cB.x - xp * cB.y;
                        acc[i][jp][e + 2] = xp * cB.x + xj * cB.y;
                    }
                }
            }
        }
#pragma unroll
        for (int i = 0; i < 2; i++) {
            int mA = m0 + wm + i * 16 + r0, mB = mA + 8;
#pragma unroll
            for (int j = 0; j < 8; j++) {
                int nc = (n0 + wn + j * 8 + c0) & (H_ - 1);
                bf16 h0, l0, h1, l1;
                split_hl(acc[i][j][0], h0, l0); split_hl(acc[i][j][1], h1, l1);
                *(bf162*)(dh + (size_t)mA * H_ + nc) = bf162(h0, h1);
                *(bf162*)(dl + (size_t)mA * H_ + nc) = bf162(l0, l1);
                split_hl(acc[i][j][2], h0, l0); split_hl(acc[i][j][3], h1, l1);
                *(bf162*)(dh + (size_t)mB * H_ + nc) = bf162(h0, h1);
                *(bf162*)(dl + (size_t)mB * H_ + nc) = bf162(l0, l1);
            }
        }
        return;
    }

    // ---- standard epilogue ----
#pragma unroll
    for (int i = 0; i < 2; i++) {
        int mA = m0 + wm + i * 16 + r0;
        int mB = mA + 8;
        int sA = mA & (S_ - 1), bA = mA >> 9;
        int sB = mB & (S_ - 1), bB = mB >> 9;
        float mvA = 1.f, mvB = 1.f;
        if (flags & FLAG_MASK) {
            mvA = (sA >= lengths[bA]) ? 1.f : 0.f;   // reference's inverted mask
            mvB = (sB >= lengths[bB]) ? 1.f : 0.f;
        }
#pragma unroll
        for (int j = 0; j < 8; j++) {
            int nb = n0 + wn + j * 8 + c0;
            if (nb >= N) continue;
            float b0 = __ldg(bias + nb);
            float b1 = (nb + 1 < N) ? __ldg(bias + nb + 1) : 0.f;
            float v00 = acc[i][j][0] + b0, v01 = acc[i][j][1] + b1;
            float v10 = acc[i][j][2] + b0, v11 = acc[i][j][3] + b1;
            if (flags & FLAG_RELU) {
                v00 = fmaxf(v00, 0.f); v01 = fmaxf(v01, 0.f);
                v10 = fmaxf(v10, 0.f); v11 = fmaxf(v11, 0.f);
            }
            v00 *= mvA; v01 *= mvA; v10 *= mvB; v11 *= mvB;
            if (flags & FLAG_TRANS) {
                Cf[((size_t)bA * N + nb) * S_ + sA] = v00;
                Cf[((size_t)bB * N + nb) * S_ + sB] = v10;
                if (nb + 1 < N) {
                    Cf[((size_t)bA * N + nb + 1) * S_ + sA] = v01;
                    Cf[((size_t)bB * N + nb + 1) * S_ + sB] = v11;
                }
            } else {
                if (Cf) {
                    *(float2*)(Cf + (size_t)mA * N + nb) = make_float2(v00, v01);
                    *(float2*)(Cf + (size_t)mB * N + nb) = make_float2(v10, v11);
                }
                if (Chi) {
                    bf16 h0, l0, h1, l1;
                    split_hl(v00, h0, l0); split_hl(v01, h1, l1);
                    *(bf162*)(Chi + (size_t)mA * N + nb) = bf162(h0, h1);
                    *(bf162*)(Clo + (size_t)mA * N + nb) = bf162(l0, l1);
                    split_hl(v10, h0, l0); split_hl(v11, h1, l1);
                    *(bf162*)(Chi + (size_t)mB * N + nb) = bf162(h0, h1);
                    *(bf162*)(Clo + (size_t)mB * N + nb) = bf162(l0, l1);
                }
            }
        }
    }
}

// ---------------- HMMA flash attention on pre-split planes ----------------
__global__ __launch_bounds__(128) void attn_kernel(
    const bf16* __restrict__ qsh, const bf16* __restrict__ qsl,
    const bf16* __restrict__ ksh, const bf16* __restrict__ ksl,
    const bf16* __restrict__ vsh, const bf16* __restrict__ vsl,
    bf16* __restrict__ ohi, bf16* __restrict__ olo,
    const int* __restrict__ lengths)
{
    extern __shared__ __align__(16) char sm[];
    const uint32_t sb = smem_u32(sm);
    const uint32_t QH = 0, QL = 8192, KH = 16384, KL = 24576, VH = 32768, VL = 40960;

    int t = threadIdx.x, wid = t >> 5, lane = t & 31;
    int qt = blockIdx.x, hh = blockIdx.y, b = blockIdx.z;
    int len = lengths[b];

#pragma unroll
    for (int it = 0; it < 4; it++) {
        int idx = t + it * 128;
        int r = idx >> 3, c = idx & 7;
        size_t src = ((size_t)b * S_ + qt * 64 + r) * H_ + hh * HD_ + c * 8;
        uint32_t d = SWZ128(r, c);
        cpa16(sb + QH + d, qsh + src, 16);
        cpa16(sb + QL + d, qsl + src, 16);
    }
    asm volatile("cp.async.commit_group;");
    asm volatile("cp.async.wait_group 0;");
    __syncthreads();

    int rsel = lane & 15, chalf = lane >> 4;
    uint32_t qh[4][4], ql[4][4];
#pragma unroll
    for (int ks = 0; ks < 4; ks++) {
        int rr = wid * 16 + rsel;
        uint32_t off = SWZ128(rr, ks * 2 + chalf);
        ldsm4(qh[ks], sb + QH + off);
        ldsm4(ql[ks], sb + QL + off);
    }

    float oc[8][4];
#pragma unroll
    for (int dt = 0; dt < 8; dt++)
#pragma unroll
        for (int e = 0; e < 4; e++) oc[dt][e] = 0.f;
    float m0 = -INFINITY, m1 = -INFINITY, ls0 = 0.f, ls1 = 0.f;

    int kt0 = len >> 6;
    if (kt0 > 7) kt0 = 7;

    for (int kt = kt0; kt < 8; kt++) {
        __syncthreads();
#pragma unroll
        for (int it = 0; it < 4; it++) {
            int idx = t + it * 128;
            int r = idx >> 3, c = idx & 7;
            size_t src = ((size_t)b * S_ + kt * 64 + r) * H_ + hh * HD_ + c * 8;
            uint32_t d = SWZ128(r, c);
            cpa16(sb + KH + d, ksh + src, 16);
            cpa16(sb + KL + d, ksl + src, 16);
            cpa16(sb + VH + d, vsh + src, 16);
            cpa16(sb + VL + d, vsl + src, 16);
        }
        asm volatile("cp.async.commit_group;");
        asm volatile("cp.async.wait_group 0;");
        __syncthreads();

        float sv[8][4];
#pragma unroll
        for (int jt = 0; jt < 8; jt++)
#pragma unroll
            for (int e = 0; e < 4; e++) sv[jt][e] = 0.f;
#pragma unroll
        for (int ks = 0; ks < 4; ks++) {
#pragma unroll
            for (int jj = 0; jj < 4; jj++) {
                uint32_t bh[4], bl[4];
                int rr = jj * 16 + rsel;
                uint32_t off = SWZ128(rr, ks * 2 + chalf);
                ldsm4(bh, sb + KH + off);
                ldsm4(bl, sb + KL + off);
                mma16816(sv[jj * 2 + 0], qh[ks], bh[0], bh[2]);
                mma16816(sv[jj * 2 + 1], qh[ks], bh[1], bh[3]);
                mma16816(sv[jj * 2 + 0], qh[ks], bl[0], bl[2]);
                mma16816(sv[jj * 2 + 1], qh[ks], bl[1], bl[3]);
                mma16816(sv[jj * 2 + 0], ql[ks], bh[0], bh[2]);
                mma16816(sv[jj * 2 + 1], ql[ks], bh[1], bh[3]);
            }
        }

        int colb = kt * 64 + (lane & 3) * 2;
        float rm0 = -INFINITY, rm1 = -INFINITY;
#pragma unroll
        for (int jt = 0; jt < 8; jt++) {
#pragma unroll
            for (int e = 0; e < 2; e++) {
                int kp = colb + jt * 8 + e;
                bool keep = (kp >= len);
                float v0 = sv[jt][e] * 0.125f;
                float v1 = sv[jt][2 + e] * 0.125f;
                sv[jt][e]     = keep ? v0 : -1e9f;
                sv[jt][2 + e] = keep ? v1 : -1e9f;
                rm0 = fmaxf(rm0, sv[jt][e]);
                rm1 = fmaxf(rm1, sv[jt][2 + e]);
            }
        }
        rm0 = fmaxf(rm0, __shfl_xor_sync(0xffffffffu, rm0, 1));
        rm0 = fmaxf(rm0, __shfl_xor_sync(0xffffffffu, rm0, 2));
        rm1 = fmaxf(rm1, __shfl_xor_sync(0xffffffffu, rm1, 1));
        rm1 = fmaxf(rm1, __shfl_xor_sync(0xffffffffu, rm1, 2));
        float mn0 = fmaxf(m0, rm0), mn1 = fmaxf(m1, rm1);
        float a0 = __expf(m0 - mn0), a1 = __expf(m1 - mn1);
        m0 = mn0; m1 = mn1;
        float s0 = 0.f, s1 = 0.f;
#pragma unroll
        for (int jt = 0; jt < 8; jt++) {
            sv[jt][0] = __expf(sv[jt][0] - mn0);
            sv[jt][1] = __expf(sv[jt][1] - mn0);
            sv[jt][2] = __expf(sv[jt][2] - mn1);
            sv[jt][3] = __expf(sv[jt][3] - mn1);
            s0 += sv[jt][0] + sv[jt][1];
            s1 += sv[jt][2] + sv[jt][3];
        }
        s0 += __shfl_xor_sync(0xffffffffu, s0, 1);
        s0 += __shfl_xor_sync(0xffffffffu, s0, 2);
        s1 += __shfl_xor_sync(0xffffffffu, s1, 1);
        s1 += __shfl_xor_sync(0xffffffffu, s1, 2);
        ls0 = ls0 * a0 + s0;
        ls1 = ls1 * a1 + s1;
#pragma unroll
        for (int dt = 0; dt < 8; dt++) {
            oc[dt][0] *= a0; oc[dt][1] *= a0;
            oc[dt][2] *= a1; oc[dt][3] *= a1;
        }

#pragma unroll
        for (int jp = 0; jp < 4; jp++) {
            uint32_t pah[4], pal[4];
#pragma unroll
            for (int half = 0; half < 2; half++) {
                bf16 h0, lo0, h1, lo1, h2, lo2, h3, lo3;
                split_hl(sv[2 * jp + half][0], h0, lo0);
                split_hl(sv[2 * jp + half][1], h1, lo1);
                split_hl(sv[2 * jp + half][2], h2, lo2);
                split_hl(sv[2 * jp + half][3], h3, lo3);
                pah[2 * half + 0] = packb(h0, h1);  pal[2 * half + 0] = packb(lo0, lo1);
                pah[2 * half + 1] = packb(h2, h3);  pal[2 * half + 1] = packb(lo2, lo3);
            }
            int vrow = jp * 16 + ((lane >> 3) & 1) * 8 + (lane & 7);
#pragma unroll
            for (int g = 0; g < 4; g++) {
                int cch = 2 * g + (lane >> 4);
                uint32_t off = SWZ128(vrow, cch);
                uint32_t vh[4], vl[4];
                ldsm4t(vh, sb + VH + off);
                ldsm4t(vl, sb + VL + off);
                mma16816(oc[2 * g],     pah, vh[0], vh[1]);
                mma16816(oc[2 * g + 1], pah, vh[2], vh[3]);
                mma16816(oc[2 * g],     pah, vl[0], vl[1]);
                mma16816(oc[2 * g + 1], pah, vl[2], vl[3]);
                mma16816(oc[2 * g],     pal, vh[0], vh[1]);
                mma16816(oc[2 * g + 1], pal, vh[2], vh[3]);
            }
        }
    }

    float i0 = 1.f / ls0, i1 = 1.f / ls1;
    int r0 = qt * 64 + wid * 16 + (lane >> 2);
#pragma unroll
    for (int dt = 0; dt < 8; dt++) {
        int d = hh * HD_ + dt * 8 + (lane & 3) * 2;
        size_t o0 = ((size_t)b * S_ + r0) * H_ + d;
        size_t o1 = o0 + (size_t)8 * H_;
        bf16 h0, lo0, h1, lo1;
        split_hl(oc[dt][0] * i0, h0, lo0);
        split_hl(oc[dt][1] * i0, h1, lo1);
        *(bf162*)(ohi + o0) = bf162(h0, h1);
        *(bf162*)(olo + o0) = bf162(lo0, lo1);
        split_hl(oc[dt][2] * i1, h0, lo0);
        split_hl(oc[dt][3] * i1, h1, lo1);
        *(bf162*)(ohi + o1) = bf162(h0, h1);
        *(bf162*)(olo + o1) = bf162(lo0, lo1);
    }
}

// ------- LayerNorm, 2 rows/block; optional residual, split and mask-split outs ----
__global__ __launch_bounds__(256) void ln_kernel(
    const float* __restrict__ x, const float* __restrict__ res,
    const float* __restrict__ g, const float* __restrict__ be,
    float* __restrict__ out, bf16* __restrict__ ohi, bf16* __restrict__ olo, int C,
    const int* __restrict__ lengths, bf16* __restrict__ mhx, bf16* __restrict__ mlx)
{
    int rb = threadIdx.x >> 7;                 // row within block (0/1)
    int m  = blockIdx.x * 2 + rb;
    int t  = threadIdx.x & 127;
    int nv = C >> 2;
    float4 v = make_float4(0.f, 0.f, 0.f, 0.f);
    if (t < nv) {
        v = ((const float4*)(x + (size_t)m * C))[t];
        if (res) {
            float4 w = ((const float4*)(res + (size_t)m * C))[t];
            v.x += w.x; v.y += w.y; v.z += w.z; v.w += w.w;
        }
    }
    float sum = v.x + v.y + v.z + v.w;
    float sq  = v.x * v.x + v.y * v.y + v.z * v.z + v.w * v.w;
#pragma unroll
    for (int off = 16; off; off >>= 1) {
        sum += __shfl_xor_sync(0xffffffffu, sum, off);
        sq  += __shfl_xor_sync(0xffffffffu, sq,  off);
    }
    __shared__ float s1[2][4], s2[2][4];
    if ((t & 31) == 0) { s1[rb][t >> 5] = sum; s2[rb][t >> 5] = sq; }
    __syncthreads();
    sum = s1[rb][0] + s1[rb][1] + s1[rb][2] + s1[rb][3];
    sq  = s2[rb][0] + s2[rb][1] + s2[rb][2] + s2[rb][3];
    float mean = sum / C;
    float var  = sq / C - mean * mean;
    float inv  = rsqrtf(var + 1e-5f);
    if (t < nv) {
        float4 gv = ((const float4*)g)[t];
        float4 bv = ((const float4*)be)[t];
        float4 o4;
        o4.x = (v.x - mean) * inv * gv.x + bv.x;
        o4.y = (v.y - mean) * inv * gv.y + bv.y;
        o4.z = (v.z - mean) * inv * gv.z + bv.z;
        o4.w = (v.w - mean) * inv * gv.w + bv.w;
        if (out) ((float4*)(out + (size_t)m * C))[t] = o4;
        bf16 h0, l0, h1, l1, h2, l2, h3, l3;
        if (ohi) {
            split_hl(o4.x, h0, l0); split_hl(o4.y, h1, l1);
            split_hl(o4.z, h2, l2); split_hl(o4.w, h3, l3);
            *(bf162*)(ohi + (size_t)m * C + t * 4)     = bf162(h0, h1);
            *(bf162*)(ohi + (size_t)m * C + t * 4 + 2) = bf162(h2, h3);
            *(bf162*)(olo + (size_t)m * C + t * 4)     = bf162(l0, l1);
            *(bf162*)(olo + (size_t)m * C + t * 4 + 2) = bf162(l2, l3);
        }
        if (mhx) {   // fused maskmul: mask-split outputs (reference's inverted mask)
            int s = m & (S_ - 1), b = m >> 9;
            float mv = (s >= lengths[b]) ? 1.f : 0.f;
            split_hl(o4.x * mv, h0, l0); split_hl(o4.y * mv, h1, l1);
            split_hl(o4.z * mv, h2, l2); split_hl(o4.w * mv, h3, l3);
            *(bf162*)(mhx + (size_t)m * C + t * 4)     = bf162(h0, h1);
            *(bf162*)(mhx + (size_t)m * C + t * 4 + 2) = bf162(h2, h3);
            *(bf162*)(mlx + (size_t)m * C + t * 4)     = bf162(l0, l1);
            *(bf162*)(mlx + (size_t)m * C + t * 4 + 2) = bf162(l2, l3);
        }
    }
}

// ---------------- small kernels ----------------
__global__ __launch_bounds__(256) void embed_kernel(
    const int* __restrict__ x, const float* __restrict__ emb,
    float* __restrict__ h, bf16* __restrict__ hh, bf16* __restrict__ hl)
{
    int idx = blockIdx.x * blockDim.x + threadIdx.x;
    if (idx >= M_ * (H_ / 4)) return;
    int m = idx >> 7, c4 = idx & 127;
    int tok = x[m];
    float4 e = ((const float4*)(emb + (size_t)tok * H_))[c4];
    const float sc = 22.62741699796952f;  // sqrt(512)
    e.x *= sc; e.y *= sc; e.z *= sc; e.w *= sc;
    ((float4*)(h + (size_t)m * H_))[c4] = e;
    bf16 h0, l0, h1, l1, h2, l2, h3, l3;
    split_hl(e.x, h0, l0); split_hl(e.y, h1, l1);
    split_hl(e.z, h2, l2); split_hl(e.w, h3, l3);
    *(bf162*)(hh + (size_t)m * H_ + c4 * 4)     = bf162(h0, h1);
    *(bf162*)(hh + (size_t)m * H_ + c4 * 4 + 2) = bf162(h2, h3);
    *(bf162*)(hl + (size_t)m * H_ + c4 * 4)     = bf162(l0, l1);
    *(bf162*)(hl + (size_t)m * H_ + c4 * 4 + 2) = bf162(l2, l3);
}

#define NW1 (L_*F_*H_*3)
#define NW2 (L_*H_*F_*3)
#define ND1 (FD_*H_*3)
#define ND2 (FD_*FD_*3)
__global__ __launch_bounds__(256) void prep_conv_kernel(
    const float* __restrict__ c1w, const float* __restrict__ c2w,
    const float* __restrict__ d1w, const float* __restrict__ d2w)
{
    int idx = blockIdx.x * blockDim.x + threadIdx.x;
    const float* src; bf16 *dh, *dl; int CI; int base;
    if (idx < NW1)                        { src = c1w; dh = g_w1h; dl = g_w1l; CI = H_;  base = idx; }
    else if (idx < NW1 + NW2)             { src = c2w; dh = g_w2h; dl = g_w2l; CI = F_;  base = idx - NW1; }
    else if (idx < NW1 + NW2 + ND1)       { src = d1w; dh = g_d1h; dl = g_d1l; CI = H_;  base = idx - NW1 - NW2; }
    else if (idx < NW1 + NW2 + ND1 + ND2) { src = d2w; dh = g_d2h; dl = g_d2l; CI = FD_; base = idx - NW1 - NW2 - ND1; }
    else return;
    int kk = base % 3;
    int rest = base / 3;
    int ci = rest % CI;
    int co = rest / CI;
    float v = src[base];
    bf16 h, l; split_hl(v, h, l);
    size_t o = (size_t)co * (3 * CI) + kk * CI + ci;
    dh[o] = h; dl[o] = l;
}

#define NQKV (L_*3*H_*H_)
#define NWO  (L_*H_*H_)
#define NPJ  (OUT_*H_)
#define NBQ  (L_*3*H_)
#define NRT  (S_*32)
__global__ __launch_bounds__(256) void prep_lin_kernel(
    const float* __restrict__ Wq, const float* __restrict__ Wk,
    const float* __restrict__ Wv, const float* __restrict__ Wo,
    const float* __restrict__ pj,
    const float* __restrict__ bq, const float* __restrict__ bk,
    const float* __restrict__ bv)
{
    int idx = blockIdx.x * blockDim.x + threadIdx.x;
    if (idx < NQKV) {
        int e = idx % H_;
        int n = (idx / H_) % (3 * H_);
        int l = idx / (3 * H_ * H_);
        const float* W = (n < H_) ? Wq : (n < 2 * H_) ? Wk : Wv;
        int nn = n & (H_ - 1);
        float v = W[(size_t)l * H_ * H_ + (size_t)nn * H_ + e];
        bf16 h, lo; split_hl(v, h, lo);
        g_wqkvh[idx] = h; g_wqkvl[idx] = lo;
        return;
    }
    int i2 = idx - NQKV;
    if (i2 < NWO) {
        float v = Wo[i2];
        bf16 h, lo; split_hl(v, h, lo);
        g_woh[i2] = h; g_wol[i2] = lo;
        return;
    }
    int i3 = i2 - NWO;
    if (i3 < NPJ) {
        float v = pj[i3];
        bf16 h, lo; split_hl(v, h, lo);
        g_pjh[i3] = h; g_pjl[i3] = lo;
        return;
    }
    int i4 = i3 - NPJ;
    if (i4 < NBQ) {
        int n = i4 % (3 * H_);
        int l = i4 / (3 * H_);
        const float* bb = (n < H_) ? bq : (n < 2 * H_) ? bk : bv;
        g_bqkv[i4] = bb[l * H_ + (n & (H_ - 1))];
        return;
    }
    int i5 = i4 - NBQ;
    if (i5 < NRT) {
        int s = i5 >> 5, j = i5 & 31;
        float th = expf(-(float)j * 0.28782313662425574f);
        float sn, cs;
        sincosf((float)s * th, &sn, &cs);
        g_rope[i5] = make_float2(cs, sn);
    }
}

__global__ __launch_bounds__(256) void dp_final_kernel(
    const float* __restrict__ x, const float* __restrict__ w,
    const float* __restrict__ pb, const int* __restrict__ lengths,
    float* __restrict__ out)
{
    int warp = threadIdx.x >> 5, lane = threadIdx.x & 31;
    int m = blockIdx.x * 8 + warp;
    if (m >= M_) return;
    const float* xr = x + (size_t)m * FD_;
    float s = 0.f;
    for (int c = lane; c < FD_; c += 32) s += xr[c] * w[c];
#pragma unroll
    for (int off = 16; off; off >>= 1) s += __shfl_xor_sync(0xffffffffu, s, off);
    if (lane == 0) {
        int b = m >> 9, sp = m & (S_ - 1);
        float mv = (sp >= lengths[b]) ? 1.f : 0.f;
        float val = (s + pb[0]) * mv;
        out[(size_t)b * S_ + sp] = ceilf(expf(val));
    }
}

// ---------------- orchestration ----------------
extern "C" void kernel_launch(void* const* d_in, const int* in_sizes, int n_in,
                              void* d_out, int out_size)
{
    const int*   x      = (const int*)  d_in[0];
    const int*   xlen   = (const int*)  d_in[1];
    const float* emb    = (const float*)d_in[2];
    const float* Wq     = (const float*)d_in[3];
    const float* bq     = (const float*)d_in[4];
    const float* Wk     = (const float*)d_in[5];
    const float* bk     = (const float*)d_in[6];
    const float* Wv     = (const float*)d_in[7];
    const float* bv     = (const float*)d_in[8];
    const float* Wo     = (const float*)d_in[9];
    const float* bo     = (const float*)d_in[10];
    const float* c1w    = (const float*)d_in[11];
    const float* c1b    = (const float*)d_in[12];
    const float* c2w    = (const float*)d_in[13];
    const float* c2b    = (const float*)d_in[14];
    const float* ln1g   = (const float*)d_in[15];
    const float* ln1b   = (const float*)d_in[16];
    const float* ln2g   = (const float*)d_in[17];
    const float* ln2b   = (const float*)d_in[18];
    const float* projw  = (const float*)d_in[19];
    const float* projb  = (const float*)d_in[20];
    const float* dpc1w  = (const float*)d_in[21];
    const float* dpc1b  = (const float*)d_in[22];
    const float* dpln1g = (const float*)d_in[23];
    const float* dpln1b = (const float*)d_in[24];
    const float* dpc2w  = (const float*)d_in[25];
    const float* dpc2b  = (const float*)d_in[26];
    const float* dpln2g = (const float*)d_in[27];
    const float* dpln2b = (const float*)d_in[28];
    const float* dppw   = (const float*)d_in[29];
    const float* dppb   = (const float*)d_in[30];
    float* out = (float*)d_out;

    float *h, *x1, *op, *cv2, *bqkv;
    bf16 *hh, *hl, *x1h, *x1l, *ah, *al, *midh, *midl, *mkh, *mkl, *dpxh, *dpxl;
    bf16 *qsh, *qsl, *ksh, *ksl, *vsh, *vsl;
    bf16 *wqh, *wql, *woh, *wol, *w1h, *w1l, *w2h, *w2l, *pjh, *pjl, *d1h, *d1l, *d2h, *d2l;
    cudaGetSymbolAddress((void**)&h,    g_h);
    cudaGetSymbolAddress((void**)&x1,   g_x1);
    cudaGetSymbolAddress((void**)&op,   g_op);
    cudaGetSymbolAddress((void**)&cv2,  g_cv2);
    cudaGetSymbolAddress((void**)&hh,   g_hh);
    cudaGetSymbolAddress((void**)&hl,   g_hl);
    cudaGetSymbolAddress((void**)&x1h,  g_x1h);
    cudaGetSymbolAddress((void**)&x1l,  g_x1l);
    cudaGetSymbolAddress((void**)&ah,   g_ah);
    cudaGetSymbolAddress((void**)&al,   g_al);
    cudaGetSymbolAddress((void**)&midh, g_midh);
    cudaGetSymbolAddress((void**)&midl, g_midl);
    cudaGetSymbolAddress((void**)&mkh,  g_mkh);
    cudaGetSymbolAddress((void**)&mkl,  g_mkl);
    cudaGetSymbolAddress((void**)&dpxh, g_dpxh);
    cudaGetSymbolAddress((void**)&dpxl, g_dpxl);
    cudaGetSymbolAddress((void**)&qsh,  g_qsh);
    cudaGetSymbolAddress((void**)&qsl,  g_qsl);
    cudaGetSymbolAddress((void**)&ksh,  g_ksh);
    cudaGetSymbolAddress((void**)&ksl,  g_ksl);
    cudaGetSymbolAddress((void**)&vsh,  g_vsh);
    cudaGetSymbolAddress((void**)&vsl,  g_vsl);
    cudaGetSymbolAddress((void**)&wqh,  g_wqkvh);
    cudaGetSymbolAddress((void**)&wql,  g_wqkvl);
    cudaGetSymbolAddress((void**)&woh,  g_woh);
    cudaGetSymbolAddress((void**)&wol,  g_wol);
    cudaGetSymbolAddress((void**)&w1h,  g_w1h);
    cudaGetSymbolAddress((void**)&w1l,  g_w1l);
    cudaGetSymbolAddress((void**)&w2h,  g_w2h);
    cudaGetSymbolAddress((void**)&w2l,  g_w2l);
    cudaGetSymbolAddress((void**)&pjh,  g_pjh);
    cudaGetSymbolAddress((void**)&pjl,  g_pjl);
    cudaGetSymbolAddress((void**)&d1h,  g_d1h);
    cudaGetSymbolAddress((void**)&d1l,  g_d1l);
    cudaGetSymbolAddress((void**)&d2h,  g_d2h);
    cudaGetSymbolAddress((void**)&d2l,  g_d2l);
    cudaGetSymbolAddress((void**)&bqkv, g_bqkv);

    cudaFuncSetAttribute((const void*)attn_kernel,
                         cudaFuncAttributeMaxDynamicSharedMemorySize, 49152);
    cudaFuncSetAttribute((const void*)hgemm_kernel,
                         cudaFuncAttributeMaxDynamicSharedMemorySize, 49152);

    {
        int tot = NW1 + NW2 + ND1 + ND2;
        prep_conv_kernel<<<(tot + 255) / 256, 256>>>(c1w, c2w, dpc1w, dpc2w);
        tot = NQKV + NWO + NPJ + NBQ + NRT;
        prep_lin_kernel<<<(tot + 255) / 256, 256>>>(Wq, Wk, Wv, Wo, projw, bq, bk, bv);
    }
    embed_kernel<<<M_ * (H_ / 4) / 256, 256>>>(x, emb, h, hh, hl);

    const int SM_G = 49152;
    dim3 gQKV(3 * H_ / 128, M_ / 64);   // (12,256)
    dim3 gH(H_ / 128, M_ / 64);         // (4,256)
    dim3 gF(F_ / 128, M_ / 64);         // (16,256)
    dim3 gMu(1, M_ / 64);
    dim3 gDp(FD_ / 128, M_ / 64);       // (2,256)
    dim3 ga(S_ / 64, NH_, B_);
    const int LNB = M_ / 2;             // 2 rows per LN block

    for (int l = 0; l < L_; l++) {
        size_t wOff = (size_t)l * H_ * H_;
        size_t wqOff = (size_t)l * 3 * H_ * H_;
        bool last = (l == L_ - 1);
        hgemm_kernel<<<gQKV, 128, SM_G>>>(hh, hl, wqh + wqOff, wql + wqOff,
                                          bqkv + l * 3 * H_, nullptr, nullptr, nullptr,
                                          3 * H_, 9, 1, 0, FLAG_QKV, xlen);
        attn_kernel<<<ga, 128, SM_G>>>(qsh, qsl, ksh, ksl, vsh, vsl, ah, al, xlen);
        hgemm_kernel<<<gH, 128, SM_G>>>(ah, al, woh + wOff, wol + wOff,
                                        bo + l * H_, op, nullptr, nullptr,
                                        H_, 9, 1, 0, 0, xlen);
        ln_kernel<<<LNB, 256>>>(op, h, ln1g + l * H_, ln1b + l * H_,
                                x1, x1h, x1l, H_, nullptr, nullptr, nullptr);
        hgemm_kernel<<<gF, 128, SM_G>>>(x1h, x1l,
                                        w1h + (size_t)l * F_ * 3 * H_, w1l + (size_t)l * F_ * 3 * H_,
                                        c1b + l * F_, nullptr, midh, midl,
                                        F_, 9, 3, 1, FLAG_RELU, xlen);
        hgemm_kernel<<<gH, 128, SM_G>>>(midh, midl,
                                        w2h + (size_t)l * H_ * 3 * F_, w2l + (size_t)l * H_ * 3 * F_,
                                        c2b + l * H_, cv2, nullptr, nullptr,
                                        H_, 11, 3, 1, 0, xlen);
        // final layer: also emit masked split planes for the duration predictor
        ln_kernel<<<LNB, 256>>>(cv2, x1, ln2g + l * H_, ln2b + l * H_,
                                h, hh, hl, H_,
                                last ? xlen : nullptr,
                                last ? mkh : nullptr,
                                last ? mkl : nullptr);
    }

    // mu = pointwise conv (transposed store to (B,OUT,S))
    hgemm_kernel<<<gMu, 128, SM_G>>>(hh, hl, pjh, pjl, projb, out, nullptr, nullptr,
                                     OUT_, 9, 1, 0, FLAG_TRANS, xlen);

    // duration predictor (maskmul fused into last ln2 above)
    hgemm_kernel<<<gDp, 128, SM_G>>>(mkh, mkl, d1h, d1l, dpc1b, op, nullptr, nullptr,
                                     FD_, 9, 3, 1, FLAG_RELU | FLAG_MASK, xlen);
    ln_kernel<<<LNB, 256>>>(op, nullptr, dpln1g, dpln1b, cv2, dpxh, dpxl, FD_,
                            nullptr, nullptr, nullptr);
    hgemm_kernel<<<gDp, 128, SM_G>>>(dpxh, dpxl, d2h, d2l, dpc2b, op, nullptr, nullptr,
                                     FD_, 8, 3, 1, FLAG_RELU | FLAG_MASK, xlen);
    ln_kernel<<<LNB, 256>>>(op, nullptr, dpln2g, dpln2b, x1, nullptr, nullptr, FD_,
                            nullptr, nullptr, nullptr);
    dp_final_kernel<<<M_ / 8, 256>>>(x1, dppw, dppb, xlen,
                                     out + ((size_t)out_size - (size_t)B_ * S_));
}

// round 13
// speedup vs baseline: 1.0576x; 1.0002x over previous
#include <cuda_runtime.h>
#include <cuda_bf16.h>
#include <math.h>
#include <stdint.h>

#define B_   32
#define S_   512
#define H_   512
#define NH_  8
#define HD_  64
#define F_   2048
#define L_   6
#define OUT_ 80
#define FD_  256
#define M_   (B_*S_)   // 16384 tokens

typedef __nv_bfloat16  bf16;
typedef __nv_bfloat162 bf162;

// ---------------- scratch (static device globals) ----------------
__device__ float g_h   [M_*H_];
__device__ float g_x1  [M_*H_];
__device__ float g_op  [M_*H_];
__device__ float g_cv2 [M_*H_];
__device__ bf16  g_hh  [M_*H_],  g_hl  [M_*H_];
__device__ bf16  g_x1h [M_*H_],  g_x1l [M_*H_];
__device__ bf16  g_ah  [M_*H_],  g_al  [M_*H_];
__device__ bf16  g_midh[M_*F_],  g_midl[M_*F_];
__device__ bf16  g_mkh [M_*H_],  g_mkl [M_*H_];
__device__ bf16  g_dpxh[M_*FD_], g_dpxl[M_*FD_];
__device__ bf16  g_qsh[M_*H_], g_qsl[M_*H_];
__device__ bf16  g_ksh[M_*H_], g_ksl[M_*H_];
__device__ bf16  g_vsh[M_*H_], g_vsl[M_*H_];
__device__ bf16  g_wqkvh[L_*3*H_*H_], g_wqkvl[L_*3*H_*H_];
__device__ bf16  g_woh [L_*H_*H_],    g_wol [L_*H_*H_];
__device__ bf16  g_w1h [L_*F_*3*H_],  g_w1l [L_*F_*3*H_];
__device__ bf16  g_w2h [L_*H_*3*F_],  g_w2l [L_*H_*3*F_];
__device__ bf16  g_pjh [OUT_*H_],     g_pjl [OUT_*H_];
__device__ bf16  g_d1h [FD_*3*H_],    g_d1l [FD_*3*H_];
__device__ bf16  g_d2h [FD_*3*FD_],   g_d2l [FD_*3*FD_];
__device__ float g_bqkv[L_*3*H_];
__device__ float2 g_rope[S_*32];

#define FLAG_RELU  1
#define FLAG_MASK  2
#define FLAG_TRANS 4
#define FLAG_QKV   8

#define SWZ128(r,c) ((uint32_t)((r)*128 + ((((c) ^ ((r)&7))) << 4)))

// ---------------- helpers ----------------
__device__ __forceinline__ void split_hl(float x, bf16& h, bf16& l) {
    h = __float2bfloat16_rn(x);
    l = __float2bfloat16_rn(x - __bfloat162float(h));
}

__device__ __forceinline__ uint32_t packb(bf16 x, bf16 y) {
    return (uint32_t)__bfloat16_as_ushort(x) | ((uint32_t)__bfloat16_as_ushort(y) << 16);
}

__device__ __forceinline__ uint32_t smem_u32(const void* p) {
    uint32_t a;
    asm("{ .reg .u64 t; cvta.to.shared.u64 t, %1; cvt.u32.u64 %0, t; }" : "=r"(a) : "l"(p));
    return a;
}

__device__ __forceinline__ void cpa16(uint32_t dst, const void* src, int sz) {
    asm volatile("cp.async.cg.shared.global [%0], [%1], 16, %2;"
                 :: "r"(dst), "l"(src), "r"(sz));
}

__device__ __forceinline__ void ldsm4(uint32_t* r, uint32_t addr) {
    asm volatile("ldmatrix.sync.aligned.m8n8.x4.shared.b16 {%0,%1,%2,%3}, [%4];"
                 : "=r"(r[0]), "=r"(r[1]), "=r"(r[2]), "=r"(r[3]) : "r"(addr));
}

__device__ __forceinline__ void ldsm4t(uint32_t* r, uint32_t addr) {
    asm volatile("ldmatrix.sync.aligned.m8n8.x4.trans.shared.b16 {%0,%1,%2,%3}, [%4];"
                 : "=r"(r[0]), "=r"(r[1]), "=r"(r[2]), "=r"(r[3]) : "r"(addr));
}

__device__ __forceinline__ void mma16816(float* c, const uint32_t* a,
                                         uint32_t b0, uint32_t b1) {
    asm volatile(
        "mma.sync.aligned.m16n8k16.row.col.f32.bf16.bf16.f32 "
        "{%0,%1,%2,%3}, {%4,%5,%6,%7}, {%8,%9}, {%0,%1,%2,%3};"
        : "+f"(c[0]), "+f"(c[1]), "+f"(c[2]), "+f"(c[3])
        : "r"(a[0]), "r"(a[1]), "r"(a[2]), "r"(a[3]), "r"(b0), "r"(b1));
}

// ---------------- split-bf16 HMMA GEMM (best-known config, unchanged) ----------------
__global__ __launch_bounds__(128, 4) void hgemm_kernel(
    const bf16* __restrict__ Ahi, const bf16* __restrict__ Alo,
    const bf16* __restrict__ Whi, const bf16* __restrict__ Wlo,
    const float* __restrict__ bias,
    float* __restrict__ Cf, bf16* __restrict__ Chi, bf16* __restrict__ Clo,
    int N, int cinLog2, int nseg, int pad, int flags,
    const int* __restrict__ lengths)
{
    extern __shared__ __align__(16) char smem[];
    const uint32_t sb = smem_u32(smem);
    const uint32_t sAHI = sb, sALO = sb + 8192, sBHI = sb + 16384, sBLO = sb + 32768;

    int t = threadIdx.x, wid = t >> 5, lane = t & 31;
    int m0 = blockIdx.y * 64, n0 = blockIdx.x * 128;
    int cin  = 1 << cinLog2;
    int Kdim = nseg << cinLog2;
    int nch  = Kdim >> 5;
    int wm = (wid >> 1) * 32, wn = (wid & 1) * 64;

    float acc[2][8][4];
#pragma unroll
    for (int i = 0; i < 2; i++)
#pragma unroll
        for (int j = 0; j < 8; j++)
#pragma unroll
            for (int e = 0; e < 4; e++) acc[i][j][e] = 0.f;

    auto load_chunk = [&](int kc) {
        int kh4 = (kc & 1) * 4;
        int kk0 = kc << 5;
        int seg = kk0 >> cinLog2;
        int ci0 = kk0 & (cin - 1);
#pragma unroll
        for (int it = 0; it < 2; it++) {
            int idx = t + it * 128;
            int r = idx >> 2, c = idx & 3;
            int m = m0 + r;
            const bf16 *sh = Ahi, *sl = Alo;
            int sz = 16;
            if (nseg == 1) {
                size_t off = (size_t)m * cin + kk0 + c * 8;
                sh += off; sl += off;
            } else {
                int s = m & (S_ - 1);
                int srow = s + seg - pad;
                if (srow >= 0 && srow < S_) {
                    size_t off = (size_t)(m + srow - s) * cin + ci0 + c * 8;
                    sh += off; sl += off;
                } else sz = 0;
            }
            uint32_t d = SWZ128(r, kh4 + c);
            cpa16(sAHI + d, sh, sz);
            cpa16(sALO + d, sl, sz);
        }
#pragma unroll
        for (int it = 0; it < 4; it++) {
            int idx = t + it * 128;
            int r = idx >> 2, c = idx & 3;
            int n = n0 + r;
            int sz = (n < N) ? 16 : 0;
            size_t off = (n < N) ? ((size_t)n * Kdim + kk0 + c * 8) : 0;
            uint32_t d = SWZ128(r, kh4 + c);
            cpa16(sBHI + d, Whi + off, sz);
            cpa16(sBLO + d, Wlo + off, sz);
        }
        asm volatile("cp.async.commit_group;");
    };

    int rsel = lane & 15, chalf = lane >> 4;
    auto compute_chunk = [&](int kc) {
        int kh4 = (kc & 1) * 4;
#pragma unroll
        for (int ks = 0; ks < 2; ks++) {
            int cc = kh4 + ks * 2 + chalf;
            uint32_t ah[2][4], al[2][4];
#pragma unroll
            for (int i = 0; i < 2; i++) {
                int rr = wm + i * 16 + rsel;
                uint32_t off = SWZ128(rr, cc);
                ldsm4(ah[i], sAHI + off);
                ldsm4(al[i], sALO + off);
            }
#pragma unroll
            for (int jj = 0; jj < 4; jj++) {
                uint32_t bh[4], bl[4];
                int rr = wn + jj * 16 + rsel;
                uint32_t off = SWZ128(rr, cc);
                ldsm4(bh, sBHI + off);
                ldsm4(bl, sBLO + off);
                mma16816(acc[0][jj * 2 + 0], ah[0], bh[0], bh[2]);
                mma16816(acc[0][jj * 2 + 1], ah[0], bh[1], bh[3]);
                mma16816(acc[1][jj * 2 + 0], ah[1], bh[0], bh[2]);
                mma16816(acc[1][jj * 2 + 1], ah[1], bh[1], bh[3]);
                mma16816(acc[0][jj * 2 + 0], ah[0], bl[0], bl[2]);
                mma16816(acc[0][jj * 2 + 1], ah[0], bl[1], bl[3]);
                mma16816(acc[1][jj * 2 + 0], ah[1], bl[0], bl[2]);
                mma16816(acc[1][jj * 2 + 1], ah[1], bl[1], bl[3]);
                mma16816(acc[0][jj * 2 + 0], al[0], bh[0], bh[2]);
                mma16816(acc[0][jj * 2 + 1], al[0], bh[1], bh[3]);
                mma16816(acc[1][jj * 2 + 0], al[1], bh[0], bh[2]);
                mma16816(acc[1][jj * 2 + 1], al[1], bh[1], bh[3]);
            }
        }
    };

    load_chunk(0);
    for (int kc = 0; kc < nch; kc++) {
        asm volatile("cp.async.wait_group 0;");
        __syncthreads();
        if (kc + 1 < nch) load_chunk(kc + 1);
        compute_chunk(kc);
    }

    int r0 = lane >> 2, c0 = (lane & 3) * 2;

    // ---- fused QKV epilogue: bias + rope (register pairs) + split-store ----
    if (flags & FLAG_QKV) {
#pragma unroll
        for (int i = 0; i < 2; i++)
#pragma unroll
            for (int j = 0; j < 8; j++) {
                int nb = n0 + wn + j * 8 + c0;
                float b0 = __ldg(bias + nb), b1 = __ldg(bias + nb + 1);
                acc[i][j][0] += b0; acc[i][j][1] += b1;
                acc[i][j][2] += b0; acc[i][j][3] += b1;
            }
        int region = n0 >> 9;   // 0=q, 1=k, 2=v
        bf16 *dh, *dl;
        if (region == 0)      { dh = g_qsh; dl = g_qsl; }
        else if (region == 1) { dh = g_ksh; dl = g_ksl; }
        else                  { dh = g_vsh; dl = g_vsl; }
        if (region < 2) {
#pragma unroll
            for (int i = 0; i < 2; i++) {
                int mA = m0 + wm + i * 16 + r0;
                int sA = mA & (S_ - 1), sB = (mA + 8) & (S_ - 1);
#pragma unroll
                for (int j = 0; j < 4; j++) {
                    int jp = j + 4;
                    int t0 = (j * 8 + c0) & 31;
                    const float2* rA = g_rope + sA * 32 + t0;
                    const float2* rB = g_rope + sB * 32 + t0;
#pragma unroll
                    for (int e = 0; e < 2; e++) {
                        float2 cA = rA[e], cB = rB[e];
                        float xj = acc[i][j][e],      xp = acc[i][jp][e];
                        acc[i][j][e]  = xj * cA.x - xp * cA.y;
                        acc[i][jp][e] = xp * cA.x + xj * cA.y;
                        xj = acc[i][j][e + 2]; xp = acc[i][jp][e + 2];
                        acc[i][j][e + 2]  = xj * cB.x - xp * cB.y;
                        acc[i][jp][e + 2] = xp * cB.x + xj * cB.y;
                    }
                }
            }
        }
#pragma unroll
        for (int i = 0; i < 2; i++) {
            int mA = m0 + wm + i * 16 + r0, mB = mA + 8;
#pragma unroll
            for (int j = 0; j < 8; j++) {
                int nc = (n0 + wn + j * 8 + c0) & (H_ - 1);
                bf16 h0, l0, h1, l1;
                split_hl(acc[i][j][0], h0, l0); split_hl(acc[i][j][1], h1, l1);
                *(bf162*)(dh + (size_t)mA * H_ + nc) = bf162(h0, h1);
                *(bf162*)(dl + (size_t)mA * H_ + nc) = bf162(l0, l1);
                split_hl(acc[i][j][2], h0, l0); split_hl(acc[i][j][3], h1, l1);
                *(bf162*)(dh + (size_t)mB * H_ + nc) = bf162(h0, h1);
                *(bf162*)(dl + (size_t)mB * H_ + nc) = bf162(l0, l1);
            }
        }
        return;
    }

    // ---- standard epilogue ----
#pragma unroll
    for (int i = 0; i < 2; i++) {
        int mA = m0 + wm + i * 16 + r0;
        int mB = mA + 8;
        int sA = mA & (S_ - 1), bA = mA >> 9;
        int sB = mB & (S_ - 1), bB = mB >> 9;
        float mvA = 1.f, mvB = 1.f;
        if (flags & FLAG_MASK) {
            mvA = (sA >= lengths[bA]) ? 1.f : 0.f;   // reference's inverted mask
            mvB = (sB >= lengths[bB]) ? 1.f : 0.f;
        }
#pragma unroll
        for (int j = 0; j < 8; j++) {
            int nb = n0 + wn + j * 8 + c0;
            if (nb >= N) continue;
            float b0 = __ldg(bias + nb);
            float b1 = (nb + 1 < N) ? __ldg(bias + nb + 1) : 0.f;
            float v00 = acc[i][j][0] + b0, v01 = acc[i][j][1] + b1;
            float v10 = acc[i][j][2] + b0, v11 = acc[i][j][3] + b1;
            if (flags & FLAG_RELU) {
                v00 = fmaxf(v00, 0.f); v01 = fmaxf(v01, 0.f);
                v10 = fmaxf(v10, 0.f); v11 = fmaxf(v11, 0.f);
            }
            v00 *= mvA; v01 *= mvA; v10 *= mvB; v11 *= mvB;
            if (flags & FLAG_TRANS) {
                Cf[((size_t)bA * N + nb) * S_ + sA] = v00;
                Cf[((size_t)bB * N + nb) * S_ + sB] = v10;
                if (nb + 1 < N) {
                    Cf[((size_t)bA * N + nb + 1) * S_ + sA] = v01;
                    Cf[((size_t)bB * N + nb + 1) * S_ + sB] = v11;
                }
            } else {
                if (Cf) {
                    *(float2*)(Cf + (size_t)mA * N + nb) = make_float2(v00, v01);
                    *(float2*)(Cf + (size_t)mB * N + nb) = make_float2(v10, v11);
                }
                if (Chi) {
                    bf16 h0, l0, h1, l1;
                    split_hl(v00, h0, l0); split_hl(v01, h1, l1);
                    *(bf162*)(Chi + (size_t)mA * N + nb) = bf162(h0, h1);
                    *(bf162*)(Clo + (size_t)mA * N + nb) = bf162(l0, l1);
                    split_hl(v10, h0, l0); split_hl(v11, h1, l1);
                    *(bf162*)(Chi + (size_t)mB * N + nb) = bf162(h0, h1);
                    *(bf162*)(Clo + (size_t)mB * N + nb) = bf162(l0, l1);
                }
            }
        }
    }
}

// ---------------- HMMA flash attention, double-buffered K/V prefetch ----------------
// smem: Q 16KB + 2 stages x (KH,KL,VH,VL = 32KB) = 80KB, 2 CTAs/SM.
__global__ __launch_bounds__(128, 2) void attn_kernel(
    const bf16* __restrict__ qsh, const bf16* __restrict__ qsl,
    const bf16* __restrict__ ksh, const bf16* __restrict__ ksl,
    const bf16* __restrict__ vsh, const bf16* __restrict__ vsl,
    bf16* __restrict__ ohi, bf16* __restrict__ olo,
    const int* __restrict__ lengths)
{
    extern __shared__ __align__(16) char sm[];
    const uint32_t sb = smem_u32(sm);
    const uint32_t QH = 0, QL = 8192;
    const uint32_t ST0 = 16384, STSZ = 32768;   // stage bases: 16384, 49152

    int t = threadIdx.x, wid = t >> 5, lane = t & 31;
    int qt = blockIdx.x, hh = blockIdx.y, b = blockIdx.z;
    int len = lengths[b];

    int kt0 = len >> 6;
    if (kt0 > 7) kt0 = 7;

    // issue Q (group 1) then first K/V stage (group 2)
#pragma unroll
    for (int it = 0; it < 4; it++) {
        int idx = t + it * 128;
        int r = idx >> 3, c = idx & 7;
        size_t src = ((size_t)b * S_ + qt * 64 + r) * H_ + hh * HD_ + c * 8;
        uint32_t d = SWZ128(r, c);
        cpa16(sb + QH + d, qsh + src, 16);
        cpa16(sb + QL + d, qsl + src, 16);
    }
    asm volatile("cp.async.commit_group;");

    auto load_kv = [&](int kt, int stg) {
        uint32_t base = sb + ST0 + stg * STSZ;
#pragma unroll
        for (int it = 0; it < 4; it++) {
            int idx = t + it * 128;
            int r = idx >> 3, c = idx & 7;
            size_t src = ((size_t)b * S_ + kt * 64 + r) * H_ + hh * HD_ + c * 8;
            uint32_t d = SWZ128(r, c);
            cpa16(base + d,         ksh + src, 16);
            cpa16(base + 8192 + d,  ksl + src, 16);
            cpa16(base + 16384 + d, vsh + src, 16);
            cpa16(base + 24576 + d, vsl + src, 16);
        }
        asm volatile("cp.async.commit_group;");
    };
    load_kv(kt0, 0);

    // Q ready after waiting down to 1 pending group
    asm volatile("cp.async.wait_group 1;");
    __syncthreads();

    int rsel = lane & 15, chalf = lane >> 4;
    uint32_t qh[4][4], ql[4][4];
#pragma unroll
    for (int ks = 0; ks < 4; ks++) {
        int rr = wid * 16 + rsel;
        uint32_t off = SWZ128(rr, ks * 2 + chalf);
        ldsm4(qh[ks], sb + QH + off);
        ldsm4(ql[ks], sb + QL + off);
    }

    float oc[8][4];
#pragma unroll
    for (int dt = 0; dt < 8; dt++)
#pragma unroll
        for (int e = 0; e < 4; e++) oc[dt][e] = 0.f;
    float m0 = -INFINITY, m1 = -INFINITY, ls0 = 0.f, ls1 = 0.f;

    for (int kt = kt0; kt < 8; kt++) {
        int stg = (kt - kt0) & 1;
        uint32_t KB = sb + ST0 + stg * STSZ;
        asm volatile("cp.async.wait_group 0;");
        __syncthreads();
        if (kt + 1 < 8) load_kv(kt + 1, stg ^ 1);   // prefetch overlaps compute

        // ---- S = Q K^T ----
        float sv[8][4];
#pragma unroll
        for (int jt = 0; jt < 8; jt++)
#pragma unroll
            for (int e = 0; e < 4; e++) sv[jt][e] = 0.f;
#pragma unroll
        for (int ks = 0; ks < 4; ks++) {
#pragma unroll
            for (int jj = 0; jj < 4; jj++) {
                uint32_t bh[4], bl[4];
                int rr = jj * 16 + rsel;
                uint32_t off = SWZ128(rr, ks * 2 + chalf);
                ldsm4(bh, KB + off);
                ldsm4(bl, KB + 8192 + off);
                mma16816(sv[jj * 2 + 0], qh[ks], bh[0], bh[2]);
                mma16816(sv[jj * 2 + 1], qh[ks], bh[1], bh[3]);
                mma16816(sv[jj * 2 + 0], qh[ks], bl[0], bl[2]);
                mma16816(sv[jj * 2 + 1], qh[ks], bl[1], bl[3]);
                mma16816(sv[jj * 2 + 0], ql[ks], bh[0], bh[2]);
                mma16816(sv[jj * 2 + 1], ql[ks], bh[1], bh[3]);
            }
        }

        // ---- scale + inverted mask + online softmax ----
        int colb = kt * 64 + (lane & 3) * 2;
        float rm0 = -INFINITY, rm1 = -INFINITY;
#pragma unroll
        for (int jt = 0; jt < 8; jt++) {
#pragma unroll
            for (int e = 0; e < 2; e++) {
                int kp = colb + jt * 8 + e;
                bool keep = (kp >= len);
                float v0 = sv[jt][e] * 0.125f;
                float v1 = sv[jt][2 + e] * 0.125f;
                sv[jt][e]     = keep ? v0 : -1e9f;
                sv[jt][2 + e] = keep ? v1 : -1e9f;
                rm0 = fmaxf(rm0, sv[jt][e]);
                rm1 = fmaxf(rm1, sv[jt][2 + e]);
            }
        }
        rm0 = fmaxf(rm0, __shfl_xor_sync(0xffffffffu, rm0, 1));
        rm0 = fmaxf(rm0, __shfl_xor_sync(0xffffffffu, rm0, 2));
        rm1 = fmaxf(rm1, __shfl_xor_sync(0xffffffffu, rm1, 1));
        rm1 = fmaxf(rm1, __shfl_xor_sync(0xffffffffu, rm1, 2));
        float mn0 = fmaxf(m0, rm0), mn1 = fmaxf(m1, rm1);
        float a0 = __expf(m0 - mn0), a1 = __expf(m1 - mn1);
        m0 = mn0; m1 = mn1;
        float s0 = 0.f, s1 = 0.f;
#pragma unroll
        for (int jt = 0; jt < 8; jt++) {
            sv[jt][0] = __expf(sv[jt][0] - mn0);
            sv[jt][1] = __expf(sv[jt][1] - mn0);
            sv[jt][2] = __expf(sv[jt][2] - mn1);
            sv[jt][3] = __expf(sv[jt][3] - mn1);
            s0 += sv[jt][0] + sv[jt][1];
            s1 += sv[jt][2] + sv[jt][3];
        }
        s0 += __shfl_xor_sync(0xffffffffu, s0, 1);
        s0 += __shfl_xor_sync(0xffffffffu, s0, 2);
        s1 += __shfl_xor_sync(0xffffffffu, s1, 1);
        s1 += __shfl_xor_sync(0xffffffffu, s1, 2);
        ls0 = ls0 * a0 + s0;
        ls1 = ls1 * a1 + s1;
#pragma unroll
        for (int dt = 0; dt < 8; dt++) {
            oc[dt][0] *= a0; oc[dt][1] *= a0;
            oc[dt][2] *= a1; oc[dt][3] *= a1;
        }

        // ---- O += P V ----
        uint32_t VB = KB + 16384;
#pragma unroll
        for (int jp = 0; jp < 4; jp++) {
            uint32_t pah[4], pal[4];
#pragma unroll
            for (int half = 0; half < 2; half++) {
                bf16 h0, lo0, h1, lo1, h2, lo2, h3, lo3;
                split_hl(sv[2 * jp + half][0], h0, lo0);
                split_hl(sv[2 * jp + half][1], h1, lo1);
                split_hl(sv[2 * jp + half][2], h2, lo2);
                split_hl(sv[2 * jp + half][3], h3, lo3);
                pah[2 * half + 0] = packb(h0, h1);  pal[2 * half + 0] = packb(lo0, lo1);
                pah[2 * half + 1] = packb(h2, h3);  pal[2 * half + 1] = packb(lo2, lo3);
            }
            int vrow = jp * 16 + ((lane >> 3) & 1) * 8 + (lane & 7);
#pragma unroll
            for (int g = 0; g < 4; g++) {
                int cch = 2 * g + (lane >> 4);
                uint32_t off = SWZ128(vrow, cch);
                uint32_t vh[4], vl[4];
                ldsm4t(vh, VB + off);
                ldsm4t(vl, VB + 8192 + off);
                mma16816(oc[2 * g],     pah, vh[0], vh[1]);
                mma16816(oc[2 * g + 1], pah, vh[2], vh[3]);
                mma16816(oc[2 * g],     pah, vl[0], vl[1]);
                mma16816(oc[2 * g + 1], pah, vl[2], vl[3]);
                mma16816(oc[2 * g],     pal, vh[0], vh[1]);
                mma16816(oc[2 * g + 1], pal, vh[2], vh[3]);
            }
        }
        __syncthreads();   // fence reads before this stage is overwritten (kt+2)
    }

    float i0 = 1.f / ls0, i1 = 1.f / ls1;
    int r0 = qt * 64 + wid * 16 + (lane >> 2);
#pragma unroll
    for (int dt = 0; dt < 8; dt++) {
        int d = hh * HD_ + dt * 8 + (lane & 3) * 2;
        size_t o0 = ((size_t)b * S_ + r0) * H_ + d;
        size_t o1 = o0 + (size_t)8 * H_;
        bf16 h0, lo0, h1, lo1;
        split_hl(oc[dt][0] * i0, h0, lo0);
        split_hl(oc[dt][1] * i0, h1, lo1);
        *(bf162*)(ohi + o0) = bf162(h0, h1);
        *(bf162*)(olo + o0) = bf162(lo0, lo1);
        split_hl(oc[dt][2] * i1, h0, lo0);
        split_hl(oc[dt][3] * i1, h1, lo1);
        *(bf162*)(ohi + o1) = bf162(h0, h1);
        *(bf162*)(olo + o1) = bf162(lo0, lo1);
    }
}

// ------- LayerNorm, 2 rows/block; optional residual, split and mask-split outs ----
__global__ __launch_bounds__(256) void ln_kernel(
    const float* __restrict__ x, const float* __restrict__ res,
    const float* __restrict__ g, const float* __restrict__ be,
    float* __restrict__ out, bf16* __restrict__ ohi, bf16* __restrict__ olo, int C,
    const int* __restrict__ lengths, bf16* __restrict__ mhx, bf16* __restrict__ mlx)
{
    int rb = threadIdx.x >> 7;
    int m  = blockIdx.x * 2 + rb;
    int t  = threadIdx.x & 127;
    int nv = C >> 2;
    float4 v = make_float4(0.f, 0.f, 0.f, 0.f);
    if (t < nv) {
        v = ((const float4*)(x + (size_t)m * C))[t];
        if (res) {
            float4 w = ((const float4*)(res + (size_t)m * C))[t];
            v.x += w.x; v.y += w.y; v.z += w.z; v.w += w.w;
        }
    }
    float sum = v.x + v.y + v.z + v.w;
    float sq  = v.x * v.x + v.y * v.y + v.z * v.z + v.w * v.w;
#pragma unroll
    for (int off = 16; off; off >>= 1) {
        sum += __shfl_xor_sync(0xffffffffu, sum, off);
        sq  += __shfl_xor_sync(0xffffffffu, sq,  off);
    }
    __shared__ float s1[2][4], s2[2][4];
    if ((t & 31) == 0) { s1[rb][t >> 5] = sum; s2[rb][t >> 5] = sq; }
    __syncthreads();
    sum = s1[rb][0] + s1[rb][1] + s1[rb][2] + s1[rb][3];
    sq  = s2[rb][0] + s2[rb][1] + s2[rb][2] + s2[rb][3];
    float mean = sum / C;
    float var  = sq / C - mean * mean;
    float inv  = rsqrtf(var + 1e-5f);
    if (t < nv) {
        float4 gv = ((const float4*)g)[t];
        float4 bv = ((const float4*)be)[t];
        float4 o4;
        o4.x = (v.x - mean) * inv * gv.x + bv.x;
        o4.y = (v.y - mean) * inv * gv.y + bv.y;
        o4.z = (v.z - mean) * inv * gv.z + bv.z;
        o4.w = (v.w - mean) * inv * gv.w + bv.w;
        if (out) ((float4*)(out + (size_t)m * C))[t] = o4;
        bf16 h0, l0, h1, l1, h2, l2, h3, l3;
        if (ohi) {
            split_hl(o4.x, h0, l0); split_hl(o4.y, h1, l1);
            split_hl(o4.z, h2, l2); split_hl(o4.w, h3, l3);
            *(bf162*)(ohi + (size_t)m * C + t * 4)     = bf162(h0, h1);
            *(bf162*)(ohi + (size_t)m * C + t * 4 + 2) = bf162(h2, h3);
            *(bf162*)(olo + (size_t)m * C + t * 4)     = bf162(l0, l1);
            *(bf162*)(olo + (size_t)m * C + t * 4 + 2) = bf162(l2, l3);
        }
        if (mhx) {
            int s = m & (S_ - 1), b = m >> 9;
            float mv = (s >= lengths[b]) ? 1.f : 0.f;   // inverted mask
            split_hl(o4.x * mv, h0, l0); split_hl(o4.y * mv, h1, l1);
            split_hl(o4.z * mv, h2, l2); split_hl(o4.w * mv, h3, l3);
            *(bf162*)(mhx + (size_t)m * C + t * 4)     = bf162(h0, h1);
            *(bf162*)(mhx + (size_t)m * C + t * 4 + 2) = bf162(h2, h3);
            *(bf162*)(mlx + (size_t)m * C + t * 4)     = bf162(l0, l1);
            *(bf162*)(mlx + (size_t)m * C + t * 4 + 2) = bf162(l2, l3);
        }
    }
}

// ---------------- small kernels ----------------
__global__ __launch_bounds__(256) void embed_kernel(
    const int* __restrict__ x, const float* __restrict__ emb,
    float* __restrict__ h, bf16* __restrict__ hh, bf16* __restrict__ hl)
{
    int idx = blockIdx.x * blockDim.x + threadIdx.x;
    if (idx >= M_ * (H_ / 4)) return;
    int m = idx >> 7, c4 = idx & 127;
    int tok = x[m];
    float4 e = ((const float4*)(emb + (size_t)tok * H_))[c4];
    const float sc = 22.62741699796952f;  // sqrt(512)
    e.x *= sc; e.y *= sc; e.z *= sc; e.w *= sc;
    ((float4*)(h + (size_t)m * H_))[c4] = e;
    bf16 h0, l0, h1, l1, h2, l2, h3, l3;
    split_hl(e.x, h0, l0); split_hl(e.y, h1, l1);
    split_hl(e.z, h2, l2); split_hl(e.w, h3, l3);
    *(bf162*)(hh + (size_t)m * H_ + c4 * 4)     = bf162(h0, h1);
    *(bf162*)(hh + (size_t)m * H_ + c4 * 4 + 2) = bf162(h2, h3);
    *(bf162*)(hl + (size_t)m * H_ + c4 * 4)     = bf162(l0, l1);
    *(bf162*)(hl + (size_t)m * H_ + c4 * 4 + 2) = bf162(l2, l3);
}

#define NW1 (L_*F_*H_*3)
#define NW2 (L_*H_*F_*3)
#define ND1 (FD_*H_*3)
#define ND2 (FD_*FD_*3)
__global__ __launch_bounds__(256) void prep_conv_kernel(
    const float* __restrict__ c1w, const float* __restrict__ c2w,
    const float* __restrict__ d1w, const float* __restrict__ d2w)
{
    int idx = blockIdx.x * blockDim.x + threadIdx.x;
    const float* src; bf16 *dh, *dl; int CI; int base;
    if (idx < NW1)                        { src = c1w; dh = g_w1h; dl = g_w1l; CI = H_;  base = idx; }
    else if (idx < NW1 + NW2)             { src = c2w; dh = g_w2h; dl = g_w2l; CI = F_;  base = idx - NW1; }
    else if (idx < NW1 + NW2 + ND1)       { src = d1w; dh = g_d1h; dl = g_d1l; CI = H_;  base = idx - NW1 - NW2; }
    else if (idx < NW1 + NW2 + ND1 + ND2) { src = d2w; dh = g_d2h; dl = g_d2l; CI = FD_; base = idx - NW1 - NW2 - ND1; }
    else return;
    int kk = base % 3;
    int rest = base / 3;
    int ci = rest % CI;
    int co = rest / CI;
    float v = src[base];
    bf16 h, l; split_hl(v, h, l);
    size_t o = (size_t)co * (3 * CI) + kk * CI + ci;
    dh[o] = h; dl[o] = l;
}

#define NQKV (L_*3*H_*H_)
#define NWO  (L_*H_*H_)
#define NPJ  (OUT_*H_)
#define NBQ  (L_*3*H_)
#define NRT  (S_*32)
__global__ __launch_bounds__(256) void prep_lin_kernel(
    const float* __restrict__ Wq, const float* __restrict__ Wk,
    const float* __restrict__ Wv, const float* __restrict__ Wo,
    const float* __restrict__ pj,
    const float* __restrict__ bq, const float* __restrict__ bk,
    const float* __restrict__ bv)
{
    int idx = blockIdx.x * blockDim.x + threadIdx.x;
    if (idx < NQKV) {
        int e = idx % H_;
        int n = (idx / H_) % (3 * H_);
        int l = idx / (3 * H_ * H_);
        const float* W = (n < H_) ? Wq : (n < 2 * H_) ? Wk : Wv;
        int nn = n & (H_ - 1);
        float v = W[(size_t)l * H_ * H_ + (size_t)nn * H_ + e];
        bf16 h, lo; split_hl(v, h, lo);
        g_wqkvh[idx] = h; g_wqkvl[idx] = lo;
        return;
    }
    int i2 = idx - NQKV;
    if (i2 < NWO) {
        float v = Wo[i2];
        bf16 h, lo; split_hl(v, h, lo);
        g_woh[i2] = h; g_wol[i2] = lo;
        return;
    }
    int i3 = i2 - NWO;
    if (i3 < NPJ) {
        float v = pj[i3];
        bf16 h, lo; split_hl(v, h, lo);
        g_pjh[i3] = h; g_pjl[i3] = lo;
        return;
    }
    int i4 = i3 - NPJ;
    if (i4 < NBQ) {
        int n = i4 % (3 * H_);
        int l = i4 / (3 * H_);
        const float* bb = (n < H_) ? bq : (n < 2 * H_) ? bk : bv;
        g_bqkv[i4] = bb[l * H_ + (n & (H_ - 1))];
        return;
    }
    int i5 = i4 - NBQ;
    if (i5 < NRT) {
        int s = i5 >> 5, j = i5 & 31;
        float th = expf(-(float)j * 0.28782313662425574f);
        float sn, cs;
        sincosf((float)s * th, &sn, &cs);
        g_rope[i5] = make_float2(cs, sn);
    }
}

__global__ __launch_bounds__(256) void dp_final_kernel(
    const float* __restrict__ x, const float* __restrict__ w,
    const float* __restrict__ pb, const int* __restrict__ lengths,
    float* __restrict__ out)
{
    int warp = threadIdx.x >> 5, lane = threadIdx.x & 31;
    int m = blockIdx.x * 8 + warp;
    if (m >= M_) return;
    const float* xr = x + (size_t)m * FD_;
    float s = 0.f;
    for (int c = lane; c < FD_; c += 32) s += xr[c] * w[c];
#pragma unroll
    for (int off = 16; off; off >>= 1) s += __shfl_xor_sync(0xffffffffu, s, off);
    if (lane == 0) {
        int b = m >> 9, sp = m & (S_ - 1);
        float mv = (sp >= lengths[b]) ? 1.f : 0.f;
        float val = (s + pb[0]) * mv;
        out[(size_t)b * S_ + sp] = ceilf(expf(val));
    }
}

// ---------------- orchestration ----------------
extern "C" void kernel_launch(void* const* d_in, const int* in_sizes, int n_in,
                              void* d_out, int out_size)
{
    const int*   x      = (const int*)  d_in[0];
    const int*   xlen   = (const int*)  d_in[1];
    const float* emb    = (const float*)d_in[2];
    const float* Wq     = (const float*)d_in[3];
    const float* bq     = (const float*)d_in[4];
    const float* Wk     = (const float*)d_in[5];
    const float* bk     = (const float*)d_in[6];
    const float* Wv     = (const float*)d_in[7];
    const float* bv     = (const float*)d_in[8];
    const float* Wo     = (const float*)d_in[9];
    const float* bo     = (const float*)d_in[10];
    const float* c1w    = (const float*)d_in[11];
    const float* c1b    = (const float*)d_in[12];
    const float* c2w    = (const float*)d_in[13];
    const float* c2b    = (const float*)d_in[14];
    const float* ln1g   = (const float*)d_in[15];
    const float* ln1b   = (const float*)d_in[16];
    const float* ln2g   = (const float*)d_in[17];
    const float* ln2b   = (const float*)d_in[18];
    const float* projw  = (const float*)d_in[19];
    const float* projb  = (const float*)d_in[20];
    const float* dpc1w  = (const float*)d_in[21];
    const float* dpc1b  = (const float*)d_in[22];
    const float* dpln1g = (const float*)d_in[23];
    const float* dpln1b = (const float*)d_in[24];
    const float* dpc2w  = (const float*)d_in[25];
    const float* dpc2b  = (const float*)d_in[26];
    const float* dpln2g = (const float*)d_in[27];
    const float* dpln2b = (const float*)d_in[28];
    const float* dppw   = (const float*)d_in[29];
    const float* dppb   = (const float*)d_in[30];
    float* out = (float*)d_out;

    float *h, *x1, *op, *cv2, *bqkv;
    bf16 *hh, *hl, *x1h, *x1l, *ah, *al, *midh, *midl, *mkh, *mkl, *dpxh, *dpxl;
    bf16 *qsh, *qsl, *ksh, *ksl, *vsh, *vsl;
    bf16 *wqh, *wql, *woh, *wol, *w1h, *w1l, *w2h, *w2l, *pjh, *pjl, *d1h, *d1l, *d2h, *d2l;
    cudaGetSymbolAddress((void**)&h,    g_h);
    cudaGetSymbolAddress((void**)&x1,   g_x1);
    cudaGetSymbolAddress((void**)&op,   g_op);
    cudaGetSymbolAddress((void**)&cv2,  g_cv2);
    cudaGetSymbolAddress((void**)&hh,   g_hh);
    cudaGetSymbolAddress((void**)&hl,   g_hl);
    cudaGetSymbolAddress((void**)&x1h,  g_x1h);
    cudaGetSymbolAddress((void**)&x1l,  g_x1l);
    cudaGetSymbolAddress((void**)&ah,   g_ah);
    cudaGetSymbolAddress((void**)&al,   g_al);
    cudaGetSymbolAddress((void**)&midh, g_midh);
    cudaGetSymbolAddress((void**)&midl, g_midl);
    cudaGetSymbolAddress((void**)&mkh,  g_mkh);
    cudaGetSymbolAddress((void**)&mkl,  g_mkl);
    cudaGetSymbolAddress((void**)&dpxh, g_dpxh);
    cudaGetSymbolAddress((void**)&dpxl, g_dpxl);
    cudaGetSymbolAddress((void**)&qsh,  g_qsh);
    cudaGetSymbolAddress((void**)&qsl,  g_qsl);
    cudaGetSymbolAddress((void**)&ksh,  g_ksh);
    cudaGetSymbolAddress((void**)&ksl,  g_ksl);
    cudaGetSymbolAddress((void**)&vsh,  g_vsh);
    cudaGetSymbolAddress((void**)&vsl,  g_vsl);
    cudaGetSymbolAddress((void**)&wqh,  g_wqkvh);
    cudaGetSymbolAddress((void**)&wql,  g_wqkvl);
    cudaGetSymbolAddress((void**)&woh,  g_woh);
    cudaGetSymbolAddress((void**)&wol,  g_wol);
    cudaGetSymbolAddress((void**)&w1h,  g_w1h);
    cudaGetSymbolAddress((void**)&w1l,  g_w1l);
    cudaGetSymbolAddress((void**)&w2h,  g_w2h);
    cudaGetSymbolAddress((void**)&w2l,  g_w2l);
    cudaGetSymbolAddress((void**)&pjh,  g_pjh);
    cudaGetSymbolAddress((void**)&pjl,  g_pjl);
    cudaGetSymbolAddress((void**)&d1h,  g_d1h);
    cudaGetSymbolAddress((void**)&d1l,  g_d1l);
    cudaGetSymbolAddress((void**)&d2h,  g_d2h);
    cudaGetSymbolAddress((void**)&d2l,  g_d2l);
    cudaGetSymbolAddress((void**)&bqkv, g_bqkv);

    cudaFuncSetAttribute((const void*)attn_kernel,
                         cudaFuncAttributeMaxDynamicSharedMemorySize, 81920);
    cudaFuncSetAttribute((const void*)hgemm_kernel,
                         cudaFuncAttributeMaxDynamicSharedMemorySize, 49152);

    {
        int tot = NW1 + NW2 + ND1 + ND2;
        prep_conv_kernel<<<(tot + 255) / 256, 256>>>(c1w, c2w, dpc1w, dpc2w);
        tot = NQKV + NWO + NPJ + NBQ + NRT;
        prep_lin_kernel<<<(tot + 255) / 256, 256>>>(Wq, Wk, Wv, Wo, projw, bq, bk, bv);
    }
    embed_kernel<<<M_ * (H_ / 4) / 256, 256>>>(x, emb, h, hh, hl);

    const int SM_G = 49152;
    const int SM_A = 81920;
    dim3 gQKV(3 * H_ / 128, M_ / 64);   // (12,256)
    dim3 gH(H_ / 128, M_ / 64);         // (4,256)
    dim3 gF(F_ / 128, M_ / 64);         // (16,256)
    dim3 gMu(1, M_ / 64);
    dim3 gDp(FD_ / 128, M_ / 64);       // (2,256)
    dim3 ga(S_ / 64, NH_, B_);
    const int LNB = M_ / 2;

    for (int l = 0; l < L_; l++) {
        size_t wOff = (size_t)l * H_ * H_;
        size_t wqOff = (size_t)l * 3 * H_ * H_;
        bool last = (l == L_ - 1);
        hgemm_kernel<<<gQKV, 128, SM_G>>>(hh, hl, wqh + wqOff, wql + wqOff,
                                          bqkv + l * 3 * H_, nullptr, nullptr, nullptr,
                                          3 * H_, 9, 1, 0, FLAG_QKV, xlen);
        attn_kernel<<<ga, 128, SM_A>>>(qsh, qsl, ksh, ksl, vsh, vsl, ah, al, xlen);
        hgemm_kernel<<<gH, 128, SM_G>>>(ah, al, woh + wOff, wol + wOff,
                                        bo + l * H_, op, nullptr, nullptr,
                                        H_, 9, 1, 0, 0, xlen);
        ln_kernel<<<LNB, 256>>>(op, h, ln1g + l * H_, ln1b + l * H_,
                                x1, x1h, x1l, H_, nullptr, nullptr, nullptr);
        hgemm_kernel<<<gF, 128, SM_G>>>(x1h, x1l,
                                        w1h + (size_t)l * F_ * 3 * H_, w1l + (size_t)l * F_ * 3 * H_,
                                        c1b + l * F_, nullptr, midh, midl,
                                        F_, 9, 3, 1, FLAG_RELU, xlen);
        hgemm_kernel<<<gH, 128, SM_G>>>(midh, midl,
                                        w2h + (size_t)l * H_ * 3 * F_, w2l + (size_t)l * H_ * 3 * F_,
                                        c2b + l * H_, cv2, nullptr, nullptr,
                                        H_, 11, 3, 1, 0, xlen);
        ln_kernel<<<LNB, 256>>>(cv2, x1, ln2g + l * H_, ln2b + l * H_,
                                h, hh, hl, H_,
                                last ? xlen : nullptr,
                                last ? mkh : nullptr,
                                last ? mkl : nullptr);
    }

    hgemm_kernel<<<gMu, 128, SM_G>>>(hh, hl, pjh, pjl, projb, out, nullptr, nullptr,
                                     OUT_, 9, 1, 0, FLAG_TRANS, xlen);

    hgemm_kernel<<<gDp, 128, SM_G>>>(mkh, mkl, d1h, d1l, dpc1b, op, nullptr, nullptr,
                                     FD_, 9, 3, 1, FLAG_RELU | FLAG_MASK, xlen);
    ln_kernel<<<LNB, 256>>>(op, nullptr, dpln1g, dpln1b, cv2, dpxh, dpxl, FD_,
                            nullptr, nullptr, nullptr);
    hgemm_kernel<<<gDp, 128, SM_G>>>(dpxh, dpxl, d2h, d2l, dpc2b, op, nullptr, nullptr,
                                     FD_, 8, 3, 1, FLAG_RELU | FLAG_MASK, xlen);
    ln_kernel<<<LNB, 256>>>(op, nullptr, dpln2g, dpln2b, x1, nullptr, nullptr, FD_,
                            nullptr, nullptr, nullptr);
    dp_final_kernel<<<M_ / 8, 256>>>(x1, dppw, dppb, xlen,
                                     out + ((size_t)out_size - (size_t)B_ * S_));
}

// round 14
// speedup vs baseline: 1.5266x; 1.4435x over previous
#include <cuda_runtime.h>
#include <cuda_fp16.h>
#include <math.h>
#include <stdint.h>

#define B_   32
#define S_   512
#define H_   512
#define NH_  8
#define HD_  64
#define F_   2048
#define L_   6
#define OUT_ 80
#define FD_  256
#define M_   (B_*S_)   // 16384 tokens

typedef __half  f16;

// ---------------- scratch (static device globals) ----------------
__device__ float g_h   [M_*H_];
__device__ float g_x1  [M_*H_];
__device__ float g_op  [M_*H_];
__device__ float g_cv2 [M_*H_];
__device__ f16   g_hf  [M_*H_];
__device__ f16   g_x1f [M_*H_];
__device__ f16   g_af  [M_*H_];
__device__ f16   g_midf[M_*F_];
__device__ f16   g_mkf [M_*H_];
__device__ f16   g_dpxf[M_*FD_];
__device__ f16   g_qsf[M_*H_], g_ksf[M_*H_], g_vsf[M_*H_];
__device__ f16   g_wqkvh[L_*3*H_*H_], g_wqkvl[L_*3*H_*H_];
__device__ f16   g_woh [L_*H_*H_],    g_wol [L_*H_*H_];
__device__ f16   g_w1h [L_*F_*3*H_],  g_w1l [L_*F_*3*H_];
__device__ f16   g_w2h [L_*H_*3*F_],  g_w2l [L_*H_*3*F_];
__device__ f16   g_pjh [OUT_*H_],     g_pjl [OUT_*H_];
__device__ f16   g_d1h [FD_*3*H_],    g_d1l [FD_*3*H_];
__device__ f16   g_d2h [FD_*3*FD_],   g_d2l [FD_*3*FD_];
__device__ float g_bqkv[L_*3*H_];
__device__ float2 g_rope[S_*32];

#define FLAG_RELU  1
#define FLAG_MASK  2
#define FLAG_TRANS 4
#define FLAG_QKV   8

#define SWZ128(r,c) ((uint32_t)((r)*128 + ((((c) ^ ((r)&7))) << 4)))

// ---------------- helpers ----------------
__device__ __forceinline__ void split_w(float x, f16& h, f16& l) {
    h = __float2half_rn(x);
    l = __float2half_rn(x - __half2float(h));
}

__device__ __forceinline__ uint32_t packh(f16 x, f16 y) {
    return (uint32_t)__half_as_ushort(x) | ((uint32_t)__half_as_ushort(y) << 16);
}

__device__ __forceinline__ uint32_t smem_u32(const void* p) {
    uint32_t a;
    asm("{ .reg .u64 t; cvta.to.shared.u64 t, %1; cvt.u32.u64 %0, t; }" : "=r"(a) : "l"(p));
    return a;
}

__device__ __forceinline__ void cpa16(uint32_t dst, const void* src, int sz) {
    asm volatile("cp.async.cg.shared.global [%0], [%1], 16, %2;"
                 :: "r"(dst), "l"(src), "r"(sz));
}

__device__ __forceinline__ void ldsm4(uint32_t* r, uint32_t addr) {
    asm volatile("ldmatrix.sync.aligned.m8n8.x4.shared.b16 {%0,%1,%2,%3}, [%4];"
                 : "=r"(r[0]), "=r"(r[1]), "=r"(r[2]), "=r"(r[3]) : "r"(addr));
}

__device__ __forceinline__ void ldsm4t(uint32_t* r, uint32_t addr) {
    asm volatile("ldmatrix.sync.aligned.m8n8.x4.trans.shared.b16 {%0,%1,%2,%3}, [%4];"
                 : "=r"(r[0]), "=r"(r[1]), "=r"(r[2]), "=r"(r[3]) : "r"(addr));
}

__device__ __forceinline__ void mma16816(float* c, const uint32_t* a,
                                         uint32_t b0, uint32_t b1) {
    asm volatile(
        "mma.sync.aligned.m16n8k16.row.col.f32.f16.f16.f32 "
        "{%0,%1,%2,%3}, {%4,%5,%6,%7}, {%8,%9}, {%0,%1,%2,%3};"
        : "+f"(c[0]), "+f"(c[1]), "+f"(c[2]), "+f"(c[3])
        : "r"(a[0]), "r"(a[1]), "r"(a[2]), "r"(a[3]), "r"(b0), "r"(b1));
}

// ---------------- fp16 HMMA GEMM: A single-plane, W dual-plane, 2 passes ----------
// 128 threads, 4 warps (2x2, warp tile 32x64), CTA tile 64x128, K-chunk 32.
// smem: A 8K | Bhi 16K | Blo 16K = 40KB, 4 CTAs/SM.
__global__ __launch_bounds__(128, 4) void hgemm_kernel(
    const f16* __restrict__ Af,
    const f16* __restrict__ Whi, const f16* __restrict__ Wlo,
    const float* __restrict__ bias,
    float* __restrict__ Cf, f16* __restrict__ Cq,
    int N, int cinLog2, int nseg, int pad, int flags,
    const int* __restrict__ lengths)
{
    extern __shared__ __align__(16) char smem[];
    const uint32_t sb = smem_u32(smem);
    const uint32_t sA = sb, sBHI = sb + 8192, sBLO = sb + 24576;

    int t = threadIdx.x, wid = t >> 5, lane = t & 31;
    int m0 = blockIdx.y * 64, n0 = blockIdx.x * 128;
    int cin  = 1 << cinLog2;
    int Kdim = nseg << cinLog2;
    int nch  = Kdim >> 5;
    int wm = (wid >> 1) * 32, wn = (wid & 1) * 64;

    float acc[2][8][4];
#pragma unroll
    for (int i = 0; i < 2; i++)
#pragma unroll
        for (int j = 0; j < 8; j++)
#pragma unroll
            for (int e = 0; e < 4; e++) acc[i][j][e] = 0.f;

    auto load_chunk = [&](int kc) {
        int kh4 = (kc & 1) * 4;
        int kk0 = kc << 5;
        int seg = kk0 >> cinLog2;
        int ci0 = kk0 & (cin - 1);
        // A: 64 rows x 4 chunks of 16B, single plane (256 sites, 2 iters)
#pragma unroll
        for (int it = 0; it < 2; it++) {
            int idx = t + it * 128;
            int r = idx >> 2, c = idx & 3;
            int m = m0 + r;
            const f16* sh = Af;
            int sz = 16;
            if (nseg == 1) {
                sh += (size_t)m * cin + kk0 + c * 8;
            } else {
                int s = m & (S_ - 1);
                int srow = s + seg - pad;
                if (srow >= 0 && srow < S_)
                    sh += (size_t)(m + srow - s) * cin + ci0 + c * 8;
                else sz = 0;
            }
            cpa16(sA + SWZ128(r, kh4 + c), sh, sz);
        }
        // B: 128 rows x 4 chunks, dual plane
#pragma unroll
        for (int it = 0; it < 4; it++) {
            int idx = t + it * 128;
            int r = idx >> 2, c = idx & 3;
            int n = n0 + r;
            int sz = (n < N) ? 16 : 0;
            size_t off = (n < N) ? ((size_t)n * Kdim + kk0 + c * 8) : 0;
            uint32_t d = SWZ128(r, kh4 + c);
            cpa16(sBHI + d, Whi + off, sz);
            cpa16(sBLO + d, Wlo + off, sz);
        }
        asm volatile("cp.async.commit_group;");
    };

    int rsel = lane & 15, chalf = lane >> 4;
    auto compute_chunk = [&](int kc) {
        int kh4 = (kc & 1) * 4;
#pragma unroll
        for (int ks = 0; ks < 2; ks++) {
            int cc = kh4 + ks * 2 + chalf;
            uint32_t av[2][4];
#pragma unroll
            for (int i = 0; i < 2; i++) {
                int rr = wm + i * 16 + rsel;
                ldsm4(av[i], sA + SWZ128(rr, cc));
            }
#pragma unroll
            for (int jj = 0; jj < 4; jj++) {
                uint32_t bh[4], bl[4];
                int rr = wn + jj * 16 + rsel;
                uint32_t off = SWZ128(rr, cc);
                ldsm4(bh, sBHI + off);
                ldsm4(bl, sBLO + off);
                mma16816(acc[0][jj * 2 + 0], av[0], bh[0], bh[2]);
                mma16816(acc[0][jj * 2 + 1], av[0], bh[1], bh[3]);
                mma16816(acc[1][jj * 2 + 0], av[1], bh[0], bh[2]);
                mma16816(acc[1][jj * 2 + 1], av[1], bh[1], bh[3]);
                mma16816(acc[0][jj * 2 + 0], av[0], bl[0], bl[2]);
                mma16816(acc[0][jj * 2 + 1], av[0], bl[1], bl[3]);
                mma16816(acc[1][jj * 2 + 0], av[1], bl[0], bl[2]);
                mma16816(acc[1][jj * 2 + 1], av[1], bl[1], bl[3]);
            }
        }
    };

    load_chunk(0);
    for (int kc = 0; kc < nch; kc++) {
        asm volatile("cp.async.wait_group 0;");
        __syncthreads();
        if (kc + 1 < nch) load_chunk(kc + 1);
        compute_chunk(kc);
    }

    int r0 = lane >> 2, c0 = (lane & 3) * 2;

    // ---- fused QKV epilogue: bias + rope (register pairs) + f16 store ----
    if (flags & FLAG_QKV) {
#pragma unroll
        for (int i = 0; i < 2; i++)
#pragma unroll
            for (int j = 0; j < 8; j++) {
                int nb = n0 + wn + j * 8 + c0;
                float b0 = __ldg(bias + nb), b1 = __ldg(bias + nb + 1);
                acc[i][j][0] += b0; acc[i][j][1] += b1;
                acc[i][j][2] += b0; acc[i][j][3] += b1;
            }
        int region = n0 >> 9;   // 0=q, 1=k, 2=v
        f16* df = (region == 0) ? g_qsf : (region == 1) ? g_ksf : g_vsf;
        if (region < 2) {
#pragma unroll
            for (int i = 0; i < 2; i++) {
                int mA = m0 + wm + i * 16 + r0;
                int sA2 = mA & (S_ - 1), sB2 = (mA + 8) & (S_ - 1);
#pragma unroll
                for (int j = 0; j < 4; j++) {
                    int jp = j + 4;
                    int t0 = (j * 8 + c0) & 31;
                    const float2* rA = g_rope + sA2 * 32 + t0;
                    const float2* rB = g_rope + sB2 * 32 + t0;
#pragma unroll
                    for (int e = 0; e < 2; e++) {
                        float2 cA = rA[e], cB = rB[e];
                        float xj = acc[i][j][e],      xp = acc[i][jp][e];
                        acc[i][j][e]  = xj * cA.x - xp * cA.y;
                        acc[i][jp][e] = xp * cA.x + xj * cA.y;
                        xj = acc[i][j][e + 2]; xp = acc[i][jp][e + 2];
                        acc[i][j][e + 2]  = xj * cB.x - xp * cB.y;
                        acc[i][jp][e + 2] = xp * cB.x + xj * cB.y;
                    }
                }
            }
        }
#pragma unroll
        for (int i = 0; i < 2; i++) {
            int mA = m0 + wm + i * 16 + r0, mB = mA + 8;
#pragma unroll
            for (int j = 0; j < 8; j++) {
                int nc = (n0 + wn + j * 8 + c0) & (H_ - 1);
                *(uint32_t*)(df + (size_t)mA * H_ + nc) =
                    packh(__float2half_rn(acc[i][j][0]), __float2half_rn(acc[i][j][1]));
                *(uint32_t*)(df + (size_t)mB * H_ + nc) =
                    packh(__float2half_rn(acc[i][j][2]), __float2half_rn(acc[i][j][3]));
            }
        }
        return;
    }

    // ---- standard epilogue ----
#pragma unroll
    for (int i = 0; i < 2; i++) {
        int mA = m0 + wm + i * 16 + r0;
        int mB = mA + 8;
        int sA2 = mA & (S_ - 1), bA = mA >> 9;
        int sB2 = mB & (S_ - 1), bB = mB >> 9;
        float mvA = 1.f, mvB = 1.f;
        if (flags & FLAG_MASK) {
            mvA = (sA2 >= lengths[bA]) ? 1.f : 0.f;   // reference's inverted mask
            mvB = (sB2 >= lengths[bB]) ? 1.f : 0.f;
        }
#pragma unroll
        for (int j = 0; j < 8; j++) {
            int nb = n0 + wn + j * 8 + c0;
            if (nb >= N) continue;
            float b0 = __ldg(bias + nb);
            float b1 = (nb + 1 < N) ? __ldg(bias + nb + 1) : 0.f;
            float v00 = acc[i][j][0] + b0, v01 = acc[i][j][1] + b1;
            float v10 = acc[i][j][2] + b0, v11 = acc[i][j][3] + b1;
            if (flags & FLAG_RELU) {
                v00 = fmaxf(v00, 0.f); v01 = fmaxf(v01, 0.f);
                v10 = fmaxf(v10, 0.f); v11 = fmaxf(v11, 0.f);
            }
            v00 *= mvA; v01 *= mvA; v10 *= mvB; v11 *= mvB;
            if (flags & FLAG_TRANS) {
                Cf[((size_t)bA * N + nb) * S_ + sA2] = v00;
                Cf[((size_t)bB * N + nb) * S_ + sB2] = v10;
                if (nb + 1 < N) {
                    Cf[((size_t)bA * N + nb + 1) * S_ + sA2] = v01;
                    Cf[((size_t)bB * N + nb + 1) * S_ + sB2] = v11;
                }
            } else {
                if (Cf) {
                    *(float2*)(Cf + (size_t)mA * N + nb) = make_float2(v00, v01);
                    *(float2*)(Cf + (size_t)mB * N + nb) = make_float2(v10, v11);
                }
                if (Cq) {
                    *(uint32_t*)(Cq + (size_t)mA * N + nb) =
                        packh(__float2half_rn(v00), __float2half_rn(v01));
                    *(uint32_t*)(Cq + (size_t)mB * N + nb) =
                        packh(__float2half_rn(v10), __float2half_rn(v11));
                }
            }
        }
    }
}

// ---------------- fp16 flash attention: single planes, 1 pass per GEMM ----------
// smem: Q 8K + 2 stages x (K 8K + V 8K) = 40KB, 4 CTAs/SM.
__global__ __launch_bounds__(128, 4) void attn_kernel(
    const f16* __restrict__ qsf, const f16* __restrict__ ksf,
    const f16* __restrict__ vsf,
    f16* __restrict__ of, const int* __restrict__ lengths)
{
    extern __shared__ __align__(16) char sm[];
    const uint32_t sb = smem_u32(sm);
    const uint32_t QF = 0;
    const uint32_t ST0 = 8192, STSZ = 16384;

    int t = threadIdx.x, wid = t >> 5, lane = t & 31;
    int qt = blockIdx.x, hh = blockIdx.y, b = blockIdx.z;
    int len = lengths[b];

    int kt0 = len >> 6;
    if (kt0 > 7) kt0 = 7;

#pragma unroll
    for (int it = 0; it < 4; it++) {
        int idx = t + it * 128;
        int r = idx >> 3, c = idx & 7;
        size_t src = ((size_t)b * S_ + qt * 64 + r) * H_ + hh * HD_ + c * 8;
        cpa16(sb + QF + SWZ128(r, c), qsf + src, 16);
    }
    asm volatile("cp.async.commit_group;");

    auto load_kv = [&](int kt, int stg) {
        uint32_t base = sb + ST0 + stg * STSZ;
#pragma unroll
        for (int it = 0; it < 4; it++) {
            int idx = t + it * 128;
            int r = idx >> 3, c = idx & 7;
            size_t src = ((size_t)b * S_ + kt * 64 + r) * H_ + hh * HD_ + c * 8;
            uint32_t d = SWZ128(r, c);
            cpa16(base + d,        ksf + src, 16);
            cpa16(base + 8192 + d, vsf + src, 16);
        }
        asm volatile("cp.async.commit_group;");
    };
    load_kv(kt0, 0);

    asm volatile("cp.async.wait_group 1;");
    __syncthreads();

    int rsel = lane & 15, chalf = lane >> 4;
    uint32_t qf[4][4];
#pragma unroll
    for (int ks = 0; ks < 4; ks++) {
        int rr = wid * 16 + rsel;
        ldsm4(qf[ks], sb + QF + SWZ128(rr, ks * 2 + chalf));
    }

    float oc[8][4];
#pragma unroll
    for (int dt = 0; dt < 8; dt++)
#pragma unroll
        for (int e = 0; e < 4; e++) oc[dt][e] = 0.f;
    float m0 = -INFINITY, m1 = -INFINITY, ls0 = 0.f, ls1 = 0.f;

    for (int kt = kt0; kt < 8; kt++) {
        int stg = (kt - kt0) & 1;
        uint32_t KB = sb + ST0 + stg * STSZ;
        asm volatile("cp.async.wait_group 0;");
        __syncthreads();
        if (kt + 1 < 8) load_kv(kt + 1, stg ^ 1);

        // ---- S = Q K^T (single pass) ----
        float sv[8][4];
#pragma unroll
        for (int jt = 0; jt < 8; jt++)
#pragma unroll
            for (int e = 0; e < 4; e++) sv[jt][e] = 0.f;
#pragma unroll
        for (int ks = 0; ks < 4; ks++) {
#pragma unroll
            for (int jj = 0; jj < 4; jj++) {
                uint32_t bk[4];
                int rr = jj * 16 + rsel;
                ldsm4(bk, KB + SWZ128(rr, ks * 2 + chalf));
                mma16816(sv[jj * 2 + 0], qf[ks], bk[0], bk[2]);
                mma16816(sv[jj * 2 + 1], qf[ks], bk[1], bk[3]);
            }
        }

        // ---- scale + inverted mask + online softmax ----
        int colb = kt * 64 + (lane & 3) * 2;
        float rm0 = -INFINITY, rm1 = -INFINITY;
#pragma unroll
        for (int jt = 0; jt < 8; jt++) {
#pragma unroll
            for (int e = 0; e < 2; e++) {
                int kp = colb + jt * 8 + e;
                bool keep = (kp >= len);
                float v0 = sv[jt][e] * 0.125f;
                float v1 = sv[jt][2 + e] * 0.125f;
                sv[jt][e]     = keep ? v0 : -1e9f;
                sv[jt][2 + e] = keep ? v1 : -1e9f;
                rm0 = fmaxf(rm0, sv[jt][e]);
                rm1 = fmaxf(rm1, sv[jt][2 + e]);
            }
        }
        rm0 = fmaxf(rm0, __shfl_xor_sync(0xffffffffu, rm0, 1));
        rm0 = fmaxf(rm0, __shfl_xor_sync(0xffffffffu, rm0, 2));
        rm1 = fmaxf(rm1, __shfl_xor_sync(0xffffffffu, rm1, 1));
        rm1 = fmaxf(rm1, __shfl_xor_sync(0xffffffffu, rm1, 2));
        float mn0 = fmaxf(m0, rm0), mn1 = fmaxf(m1, rm1);
        float a0 = __expf(m0 - mn0), a1 = __expf(m1 - mn1);
        m0 = mn0; m1 = mn1;
        float s0 = 0.f, s1 = 0.f;
#pragma unroll
        for (int jt = 0; jt < 8; jt++) {
            sv[jt][0] = __expf(sv[jt][0] - mn0);
            sv[jt][1] = __expf(sv[jt][1] - mn0);
            sv[jt][2] = __expf(sv[jt][2] - mn1);
            sv[jt][3] = __expf(sv[jt][3] - mn1);
            s0 += sv[jt][0] + sv[jt][1];
            s1 += sv[jt][2] + sv[jt][3];
        }
        s0 += __shfl_xor_sync(0xffffffffu, s0, 1);
        s0 += __shfl_xor_sync(0xffffffffu, s0, 2);
        s1 += __shfl_xor_sync(0xffffffffu, s1, 1);
        s1 += __shfl_xor_sync(0xffffffffu, s1, 2);
        ls0 = ls0 * a0 + s0;
        ls1 = ls1 * a1 + s1;
#pragma unroll
        for (int dt = 0; dt < 8; dt++) {
            oc[dt][0] *= a0; oc[dt][1] *= a0;
            oc[dt][2] *= a1; oc[dt][3] *= a1;
        }

        // ---- O += P V (single pass) ----
        uint32_t VB = KB + 8192;
#pragma unroll
        for (int jp = 0; jp < 4; jp++) {
            uint32_t pa[4];
#pragma unroll
            for (int half = 0; half < 2; half++) {
                pa[2 * half + 0] = packh(__float2half_rn(sv[2 * jp + half][0]),
                                         __float2half_rn(sv[2 * jp + half][1]));
                pa[2 * half + 1] = packh(__float2half_rn(sv[2 * jp + half][2]),
                                         __float2half_rn(sv[2 * jp + half][3]));
            }
            int vrow = jp * 16 + ((lane >> 3) & 1) * 8 + (lane & 7);
#pragma unroll
            for (int g = 0; g < 4; g++) {
                int cch = 2 * g + (lane >> 4);
                uint32_t vv[4];
                ldsm4t(vv, VB + SWZ128(vrow, cch));
                mma16816(oc[2 * g],     pa, vv[0], vv[1]);
                mma16816(oc[2 * g + 1], pa, vv[2], vv[3]);
            }
        }
        __syncthreads();
    }

    float i0 = 1.f / ls0, i1 = 1.f / ls1;
    int r0 = qt * 64 + wid * 16 + (lane >> 2);
#pragma unroll
    for (int dt = 0; dt < 8; dt++) {
        int d = hh * HD_ + dt * 8 + (lane & 3) * 2;
        size_t o0 = ((size_t)b * S_ + r0) * H_ + d;
        size_t o1 = o0 + (size_t)8 * H_;
        *(uint32_t*)(of + o0) = packh(__float2half_rn(oc[dt][0] * i0),
                                      __float2half_rn(oc[dt][1] * i0));
        *(uint32_t*)(of + o1) = packh(__float2half_rn(oc[dt][2] * i1),
                                      __float2half_rn(oc[dt][3] * i1));
    }
}

// ------- LayerNorm, 2 rows/block; optional residual, f16 and masked-f16 outs ----
__global__ __launch_bounds__(256) void ln_kernel(
    const float* __restrict__ x, const float* __restrict__ res,
    const float* __restrict__ g, const float* __restrict__ be,
    float* __restrict__ out, f16* __restrict__ of, int C,
    const int* __restrict__ lengths, f16* __restrict__ mf)
{
    int rb = threadIdx.x >> 7;
    int m  = blockIdx.x * 2 + rb;
    int t  = threadIdx.x & 127;
    int nv = C >> 2;
    float4 v = make_float4(0.f, 0.f, 0.f, 0.f);
    if (t < nv) {
        v = ((const float4*)(x + (size_t)m * C))[t];
        if (res) {
            float4 w = ((const float4*)(res + (size_t)m * C))[t];
            v.x += w.x; v.y += w.y; v.z += w.z; v.w += w.w;
        }
    }
    float sum = v.x + v.y + v.z + v.w;
    float sq  = v.x * v.x + v.y * v.y + v.z * v.z + v.w * v.w;
#pragma unroll
    for (int off = 16; off; off >>= 1) {
        sum += __shfl_xor_sync(0xffffffffu, sum, off);
        sq  += __shfl_xor_sync(0xffffffffu, sq,  off);
    }
    __shared__ float s1[2][4], s2[2][4];
    if ((t & 31) == 0) { s1[rb][t >> 5] = sum; s2[rb][t >> 5] = sq; }
    __syncthreads();
    sum = s1[rb][0] + s1[rb][1] + s1[rb][2] + s1[rb][3];
    sq  = s2[rb][0] + s2[rb][1] + s2[rb][2] + s2[rb][3];
    float mean = sum / C;
    float var  = sq / C - mean * mean;
    float inv  = rsqrtf(var + 1e-5f);
    if (t < nv) {
        float4 gv = ((const float4*)g)[t];
        float4 bv = ((const float4*)be)[t];
        float4 o4;
        o4.x = (v.x - mean) * inv * gv.x + bv.x;
        o4.y = (v.y - mean) * inv * gv.y + bv.y;
        o4.z = (v.z - mean) * inv * gv.z + bv.z;
        o4.w = (v.w - mean) * inv * gv.w + bv.w;
        if (out) ((float4*)(out + (size_t)m * C))[t] = o4;
        if (of) {
            *(uint32_t*)(of + (size_t)m * C + t * 4) =
                packh(__float2half_rn(o4.x), __float2half_rn(o4.y));
            *(uint32_t*)(of + (size_t)m * C + t * 4 + 2) =
                packh(__float2half_rn(o4.z), __float2half_rn(o4.w));
        }
        if (mf) {
            int s = m & (S_ - 1), b = m >> 9;
            float mv = (s >= lengths[b]) ? 1.f : 0.f;   // inverted mask
            *(uint32_t*)(mf + (size_t)m * C + t * 4) =
                packh(__float2half_rn(o4.x * mv), __float2half_rn(o4.y * mv));
            *(uint32_t*)(mf + (size_t)m * C + t * 4 + 2) =
                packh(__float2half_rn(o4.z * mv), __float2half_rn(o4.w * mv));
        }
    }
}

// ---------------- small kernels ----------------
__global__ __launch_bounds__(256) void embed_kernel(
    const int* __restrict__ x, const float* __restrict__ emb,
    float* __restrict__ h, f16* __restrict__ hf)
{
    int idx = blockIdx.x * blockDim.x + threadIdx.x;
    if (idx >= M_ * (H_ / 4)) return;
    int m = idx >> 7, c4 = idx & 127;
    int tok = x[m];
    float4 e = ((const float4*)(emb + (size_t)tok * H_))[c4];
    const float sc = 22.62741699796952f;  // sqrt(512)
    e.x *= sc; e.y *= sc; e.z *= sc; e.w *= sc;
    ((float4*)(h + (size_t)m * H_))[c4] = e;
    *(uint32_t*)(hf + (size_t)m * H_ + c4 * 4) =
        packh(__float2half_rn(e.x), __float2half_rn(e.y));
    *(uint32_t*)(hf + (size_t)m * H_ + c4 * 4 + 2) =
        packh(__float2half_rn(e.z), __float2half_rn(e.w));
}

#define NW1 (L_*F_*H_*3)
#define NW2 (L_*H_*F_*3)
#define ND1 (FD_*H_*3)
#define ND2 (FD_*FD_*3)
__global__ __launch_bounds__(256) void prep_conv_kernel(
    const float* __restrict__ c1w, const float* __restrict__ c2w,
    const float* __restrict__ d1w, const float* __restrict__ d2w)
{
    int idx = blockIdx.x * blockDim.x + threadIdx.x;
    const float* src; f16 *dh, *dl; int CI; int base;
    if (idx < NW1)                        { src = c1w; dh = g_w1h; dl = g_w1l; CI = H_;  base = idx; }
    else if (idx < NW1 + NW2)             { src = c2w; dh = g_w2h; dl = g_w2l; CI = F_;  base = idx - NW1; }
    else if (idx < NW1 + NW2 + ND1)       { src = d1w; dh = g_d1h; dl = g_d1l; CI = H_;  base = idx - NW1 - NW2; }
    else if (idx < NW1 + NW2 + ND1 + ND2) { src = d2w; dh = g_d2h; dl = g_d2l; CI = FD_; base = idx - NW1 - NW2 - ND1; }
    else return;
    int kk = base % 3;
    int rest = base / 3;
    int ci = rest % CI;
    int co = rest / CI;
    f16 h, l; split_w(src[base], h, l);
    size_t o = (size_t)co * (3 * CI) + kk * CI + ci;
    dh[o] = h; dl[o] = l;
}

#define NQKV (L_*3*H_*H_)
#define NWO  (L_*H_*H_)
#define NPJ  (OUT_*H_)
#define NBQ  (L_*3*H_)
#define NRT  (S_*32)
__global__ __launch_bounds__(256) void prep_lin_kernel(
    const float* __restrict__ Wq, const float* __restrict__ Wk,
    const float* __restrict__ Wv, const float* __restrict__ Wo,
    const float* __restrict__ pj,
    const float* __restrict__ bq, const float* __restrict__ bk,
    const float* __restrict__ bv)
{
    int idx = blockIdx.x * blockDim.x + threadIdx.x;
    if (idx < NQKV) {
        int e = idx % H_;
        int n = (idx / H_) % (3 * H_);
        int l = idx / (3 * H_ * H_);
        const float* W = (n < H_) ? Wq : (n < 2 * H_) ? Wk : Wv;
        int nn = n & (H_ - 1);
        f16 h, lo; split_w(W[(size_t)l * H_ * H_ + (size_t)nn * H_ + e], h, lo);
        g_wqkvh[idx] = h; g_wqkvl[idx] = lo;
        return;
    }
    int i2 = idx - NQKV;
    if (i2 < NWO) {
        f16 h, lo; split_w(Wo[i2], h, lo);
        g_woh[i2] = h; g_wol[i2] = lo;
        return;
    }
    int i3 = i2 - NWO;
    if (i3 < NPJ) {
        f16 h, lo; split_w(pj[i3], h, lo);
        g_pjh[i3] = h; g_pjl[i3] = lo;
        return;
    }
    int i4 = i3 - NPJ;
    if (i4 < NBQ) {
        int n = i4 % (3 * H_);
        int l = i4 / (3 * H_);
        const float* bb = (n < H_) ? bq : (n < 2 * H_) ? bk : bv;
        g_bqkv[i4] = bb[l * H_ + (n & (H_ - 1))];
        return;
    }
    int i5 = i4 - NBQ;
    if (i5 < NRT) {
        int s = i5 >> 5, j = i5 & 31;
        float th = expf(-(float)j * 0.28782313662425574f);
        float sn, cs;
        sincosf((float)s * th, &sn, &cs);
        g_rope[i5] = make_float2(cs, sn);
    }
}

__global__ __launch_bounds__(256) void dp_final_kernel(
    const float* __restrict__ x, const float* __restrict__ w,
    const float* __restrict__ pb, const int* __restrict__ lengths,
    float* __restrict__ out)
{
    int warp = threadIdx.x >> 5, lane = threadIdx.x & 31;
    int m = blockIdx.x * 8 + warp;
    if (m >= M_) return;
    const float* xr = x + (size_t)m * FD_;
    float s = 0.f;
    for (int c = lane; c < FD_; c += 32) s += xr[c] * w[c];
#pragma unroll
    for (int off = 16; off; off >>= 1) s += __shfl_xor_sync(0xffffffffu, s, off);
    if (lane == 0) {
        int b = m >> 9, sp = m & (S_ - 1);
        float mv = (sp >= lengths[b]) ? 1.f : 0.f;
        float val = (s + pb[0]) * mv;
        out[(size_t)b * S_ + sp] = ceilf(expf(val));
    }
}

// ---------------- orchestration ----------------
extern "C" void kernel_launch(void* const* d_in, const int* in_sizes, int n_in,
                              void* d_out, int out_size)
{
    const int*   x      = (const int*)  d_in[0];
    const int*   xlen   = (const int*)  d_in[1];
    const float* emb    = (const float*)d_in[2];
    const float* Wq     = (const float*)d_in[3];
    const float* bq     = (const float*)d_in[4];
    const float* Wk     = (const float*)d_in[5];
    const float* bk     = (const float*)d_in[6];
    const float* Wv     = (const float*)d_in[7];
    const float* bv     = (const float*)d_in[8];
    const float* Wo     = (const float*)d_in[9];
    const float* bo     = (const float*)d_in[10];
    const float* c1w    = (const float*)d_in[11];
    const float* c1b    = (const float*)d_in[12];
    const float* c2w    = (const float*)d_in[13];
    const float* c2b    = (const float*)d_in[14];
    const float* ln1g   = (const float*)d_in[15];
    const float* ln1b   = (const float*)d_in[16];
    const float* ln2g   = (const float*)d_in[17];
    const float* ln2b   = (const float*)d_in[18];
    const float* projw  = (const float*)d_in[19];
    const float* projb  = (const float*)d_in[20];
    const float* dpc1w  = (const float*)d_in[21];
    const float* dpc1b  = (const float*)d_in[22];
    const float* dpln1g = (const float*)d_in[23];
    const float* dpln1b = (const float*)d_in[24];
    const float* dpc2w  = (const float*)d_in[25];
    const float* dpc2b  = (const float*)d_in[26];
    const float* dpln2g = (const float*)d_in[27];
    const float* dpln2b = (const float*)d_in[28];
    const float* dppw   = (const float*)d_in[29];
    const float* dppb   = (const float*)d_in[30];
    float* out = (float*)d_out;

    float *h, *x1, *op, *cv2, *bqkv;
    f16 *hf, *x1f, *af, *midf, *mkf, *dpxf, *qsf, *ksf, *vsf;
    f16 *wqh, *wql, *woh, *wol, *w1h, *w1l, *w2h, *w2l, *pjh, *pjl, *d1h, *d1l, *d2h, *d2l;
    cudaGetSymbolAddress((void**)&h,    g_h);
    cudaGetSymbolAddress((void**)&x1,   g_x1);
    cudaGetSymbolAddress((void**)&op,   g_op);
    cudaGetSymbolAddress((void**)&cv2,  g_cv2);
    cudaGetSymbolAddress((void**)&hf,   g_hf);
    cudaGetSymbolAddress((void**)&x1f,  g_x1f);
    cudaGetSymbolAddress((void**)&af,   g_af);
    cudaGetSymbolAddress((void**)&midf, g_midf);
    cudaGetSymbolAddress((void**)&mkf,  g_mkf);
    cudaGetSymbolAddress((void**)&dpxf, g_dpxf);
    cudaGetSymbolAddress((void**)&qsf,  g_qsf);
    cudaGetSymbolAddress((void**)&ksf,  g_ksf);
    cudaGetSymbolAddress((void**)&vsf,  g_vsf);
    cudaGetSymbolAddress((void**)&wqh,  g_wqkvh);
    cudaGetSymbolAddress((void**)&wql,  g_wqkvl);
    cudaGetSymbolAddress((void**)&woh,  g_woh);
    cudaGetSymbolAddress((void**)&wol,  g_wol);
    cudaGetSymbolAddress((void**)&w1h,  g_w1h);
    cudaGetSymbolAddress((void**)&w1l,  g_w1l);
    cudaGetSymbolAddress((void**)&w2h,  g_w2h);
    cudaGetSymbolAddress((void**)&w2l,  g_w2l);
    cudaGetSymbolAddress((void**)&pjh,  g_pjh);
    cudaGetSymbolAddress((void**)&pjl,  g_pjl);
    cudaGetSymbolAddress((void**)&d1h,  g_d1h);
    cudaGetSymbolAddress((void**)&d1l,  g_d1l);
    cudaGetSymbolAddress((void**)&d2h,  g_d2h);
    cudaGetSymbolAddress((void**)&d2l,  g_d2l);
    cudaGetSymbolAddress((void**)&bqkv, g_bqkv);

    cudaFuncSetAttribute((const void*)attn_kernel,
                         cudaFuncAttributeMaxDynamicSharedMemorySize, 40960);
    cudaFuncSetAttribute((const void*)hgemm_kernel,
                         cudaFuncAttributeMaxDynamicSharedMemorySize, 40960);

    {
        int tot = NW1 + NW2 + ND1 + ND2;
        prep_conv_kernel<<<(tot + 255) / 256, 256>>>(c1w, c2w, dpc1w, dpc2w);
        tot = NQKV + NWO + NPJ + NBQ + NRT;
        prep_lin_kernel<<<(tot + 255) / 256, 256>>>(Wq, Wk, Wv, Wo, projw, bq, bk, bv);
    }
    embed_kernel<<<M_ * (H_ / 4) / 256, 256>>>(x, emb, h, hf);

    const int SM_G = 40960;
    const int SM_A = 40960;
    dim3 gQKV(3 * H_ / 128, M_ / 64);   // (12,256)
    dim3 gH(H_ / 128, M_ / 64);         // (4,256)
    dim3 gF(F_ / 128, M_ / 64);         // (16,256)
    dim3 gMu(1, M_ / 64);
    dim3 gDp(FD_ / 128, M_ / 64);       // (2,256)
    dim3 ga(S_ / 64, NH_, B_);
    const int LNB = M_ / 2;

    for (int l = 0; l < L_; l++) {
        size_t wOff = (size_t)l * H_ * H_;
        size_t wqOff = (size_t)l * 3 * H_ * H_;
        bool last = (l == L_ - 1);
        hgemm_kernel<<<gQKV, 128, SM_G>>>(hf, wqh + wqOff, wql + wqOff,
                                          bqkv + l * 3 * H_, nullptr, nullptr,
                                          3 * H_, 9, 1, 0, FLAG_QKV, xlen);
        attn_kernel<<<ga, 128, SM_A>>>(qsf, ksf, vsf, af, xlen);
        hgemm_kernel<<<gH, 128, SM_G>>>(af, woh + wOff, wol + wOff,
                                        bo + l * H_, op, nullptr,
                                        H_, 9, 1, 0, 0, xlen);
        ln_kernel<<<LNB, 256>>>(op, h, ln1g + l * H_, ln1b + l * H_,
                                x1, x1f, H_, nullptr, nullptr);
        hgemm_kernel<<<gF, 128, SM_G>>>(x1f,
                                        w1h + (size_t)l * F_ * 3 * H_, w1l + (size_t)l * F_ * 3 * H_,
                                        c1b + l * F_, nullptr, midf,
                                        F_, 9, 3, 1, FLAG_RELU, xlen);
        hgemm_kernel<<<gH, 128, SM_G>>>(midf,
                                        w2h + (size_t)l * H_ * 3 * F_, w2l + (size_t)l * H_ * 3 * F_,
                                        c2b + l * H_, cv2, nullptr,
                                        H_, 11, 3, 1, 0, xlen);
        ln_kernel<<<LNB, 256>>>(cv2, x1, ln2g + l * H_, ln2b + l * H_,
                                h, hf, H_,
                                last ? xlen : nullptr,
                                last ? mkf : nullptr);
    }

    hgemm_kernel<<<gMu, 128, SM_G>>>(hf, pjh, pjl, projb, out, nullptr,
                                     OUT_, 9, 1, 0, FLAG_TRANS, xlen);

    hgemm_kernel<<<gDp, 128, SM_G>>>(mkf, d1h, d1l, dpc1b, op, nullptr,
                                     FD_, 9, 3, 1, FLAG_RELU | FLAG_MASK, xlen);
    ln_kernel<<<LNB, 256>>>(op, nullptr, dpln1g, dpln1b, cv2, dpxf, FD_,
                            nullptr, nullptr);
    hgemm_kernel<<<gDp, 128, SM_G>>>(dpxf, d2h, d2l, dpc2b, op, nullptr,
                                     FD_, 8, 3, 1, FLAG_RELU | FLAG_MASK, xlen);
    ln_kernel<<<LNB, 256>>>(op, nullptr, dpln2g, dpln2b, x1, nullptr, FD_,
                            nullptr, nullptr);
    dp_final_kernel<<<M_ / 8, 256>>>(x1, dppw, dppb, xlen,
                                     out + ((size_t)out_size - (size_t)B_ * S_));
}

// round 16
// speedup vs baseline: 1.5898x; 1.0414x over previous
#include <cuda_runtime.h>
#include <cuda_fp16.h>
#include <math.h>
#include <stdint.h>

#define B_   32
#define S_   512
#define H_   512
#define NH_  8
#define HD_  64
#define F_   2048
#define L_   6
#define OUT_ 80
#define FD_  256
#define M_   (B_*S_)   // 16384 tokens

typedef __half  f16;

// ---------------- scratch (static device globals) ----------------
__device__ float g_h   [M_*H_];
__device__ float g_x1  [M_*H_];
__device__ float g_op  [M_*H_];
__device__ float g_cv2 [M_*H_];
__device__ f16   g_hf  [M_*H_];
__device__ f16   g_x1f [M_*H_];
__device__ f16   g_af  [M_*H_];
__device__ f16   g_midf[M_*F_];
__device__ f16   g_mkf [M_*H_];
__device__ f16   g_dpxf[M_*FD_];
__device__ f16   g_qsf[M_*H_], g_ksf[M_*H_], g_vsf[M_*H_];
__device__ f16   g_wqkvh[L_*3*H_*H_], g_wqkvl[L_*3*H_*H_];
__device__ f16   g_woh [L_*H_*H_],    g_wol [L_*H_*H_];
__device__ f16   g_w1h [L_*F_*3*H_],  g_w1l [L_*F_*3*H_];
__device__ f16   g_w2h [L_*H_*3*F_],  g_w2l [L_*H_*3*F_];
__device__ f16   g_pjh [OUT_*H_],     g_pjl [OUT_*H_];
__device__ f16   g_d1h [FD_*3*H_],    g_d1l [FD_*3*H_];
__device__ f16   g_d2h [FD_*3*FD_],   g_d2l [FD_*3*FD_];
__device__ float g_bqkv[L_*3*H_];
__device__ float2 g_rope[S_*32];

#define FLAG_RELU  1
#define FLAG_MASK  2
#define FLAG_TRANS 4
#define FLAG_QKV   8

#define SWZ128(r,c) ((uint32_t)((r)*128 + ((((c) ^ ((r)&7))) << 4)))

// ---------------- helpers ----------------
__device__ __forceinline__ void split_w(float x, f16& h, f16& l) {
    h = __float2half_rn(x);
    l = __float2half_rn(x - __half2float(h));
}

__device__ __forceinline__ uint32_t packh(f16 x, f16 y) {
    return (uint32_t)__half_as_ushort(x) | ((uint32_t)__half_as_ushort(y) << 16);
}

__device__ __forceinline__ uint32_t smem_u32(const void* p) {
    uint32_t a;
    asm("{ .reg .u64 t; cvta.to.shared.u64 t, %1; cvt.u32.u64 %0, t; }" : "=r"(a) : "l"(p));
    return a;
}

__device__ __forceinline__ void cpa16(uint32_t dst, const void* src, int sz) {
    asm volatile("cp.async.cg.shared.global [%0], [%1], 16, %2;"
                 :: "r"(dst), "l"(src), "r"(sz));
}

__device__ __forceinline__ void ldsm4(uint32_t* r, uint32_t addr) {
    asm volatile("ldmatrix.sync.aligned.m8n8.x4.shared.b16 {%0,%1,%2,%3}, [%4];"
                 : "=r"(r[0]), "=r"(r[1]), "=r"(r[2]), "=r"(r[3]) : "r"(addr));
}

__device__ __forceinline__ void ldsm4t(uint32_t* r, uint32_t addr) {
    asm volatile("ldmatrix.sync.aligned.m8n8.x4.trans.shared.b16 {%0,%1,%2,%3}, [%4];"
                 : "=r"(r[0]), "=r"(r[1]), "=r"(r[2]), "=r"(r[3]) : "r"(addr));
}

__device__ __forceinline__ void mma16816(float* c, const uint32_t* a,
                                         uint32_t b0, uint32_t b1) {
    asm volatile(
        "mma.sync.aligned.m16n8k16.row.col.f32.f16.f16.f32 "
        "{%0,%1,%2,%3}, {%4,%5,%6,%7}, {%8,%9}, {%0,%1,%2,%3};"
        : "+f"(c[0]), "+f"(c[1]), "+f"(c[2]), "+f"(c[3])
        : "r"(a[0]), "r"(a[1]), "r"(a[2]), "r"(a[3]), "r"(b0), "r"(b1));
}

// ---------------- fp16 HMMA GEMM: A single-plane, W dual-plane, 2 passes ----------
// 128 threads, 4 warps (2x2, warp tile 32x64), CTA tile 64x128, K-chunk 32.
// smem: A 8K | Bhi 16K | Blo 16K = 40KB, 4 CTAs/SM.
// Tile skips: QKV k/v tiles never read by attention -> return; fully-masked
// dp tiles -> skip compute, epilogue writes zeros via mask.
__global__ __launch_bounds__(128, 4) void hgemm_kernel(
    const f16* __restrict__ Af,
    const f16* __restrict__ Whi, const f16* __restrict__ Wlo,
    const float* __restrict__ bias,
    float* __restrict__ Cf, f16* __restrict__ Cq,
    int N, int cinLog2, int nseg, int pad, int flags,
    const int* __restrict__ lengths)
{
    extern __shared__ __align__(16) char smem[];
    const uint32_t sb = smem_u32(smem);
    const uint32_t sA = sb, sBHI = sb + 8192, sBLO = sb + 24576;

    int t = threadIdx.x, wid = t >> 5, lane = t & 31;
    int m0 = blockIdx.y * 64, n0 = blockIdx.x * 128;
    int cin  = 1 << cinLog2;
    int Kdim = nseg << cinLog2;
    int nch  = Kdim >> 5;
    int wm = (wid >> 1) * 32, wn = (wid & 1) * 64;

    // ---- zero-risk tile skips ----
    bool skip_compute = false;
    {
        int bb = m0 >> 9;
        int s0 = m0 & (S_ - 1);
        if (flags & FLAG_QKV) {
            int region = n0 >> 9;               // 0=q, 1=k, 2=v
            // k/v tiles fully below len are never read by attention (kt0 = len>>6)
            if (region >= 1 && (s0 >> 6) < (lengths[bb] >> 6)) return;
        } else if (flags & FLAG_MASK) {
            // outputs fully zeroed by inverted mask: skip loads/MMAs, write zeros
            if (s0 + 63 < lengths[bb]) skip_compute = true;
        }
    }

    float acc[2][8][4];
#pragma unroll
    for (int i = 0; i < 2; i++)
#pragma unroll
        for (int j = 0; j < 8; j++)
#pragma unroll
            for (int e = 0; e < 4; e++) acc[i][j][e] = 0.f;

    auto load_chunk = [&](int kc) {
        int kh4 = (kc & 1) * 4;
        int kk0 = kc << 5;
        int seg = kk0 >> cinLog2;
        int ci0 = kk0 & (cin - 1);
#pragma unroll
        for (int it = 0; it < 2; it++) {
            int idx = t + it * 128;
            int r = idx >> 2, c = idx & 3;
            int m = m0 + r;
            const f16* sh = Af;
            int sz = 16;
            if (nseg == 1) {
                sh += (size_t)m * cin + kk0 + c * 8;
            } else {
                int s = m & (S_ - 1);
                int srow = s + seg - pad;
                if (srow >= 0 && srow < S_)
                    sh += (size_t)(m + srow - s) * cin + ci0 + c * 8;
                else sz = 0;
            }
            cpa16(sA + SWZ128(r, kh4 + c), sh, sz);
        }
#pragma unroll
        for (int it = 0; it < 4; it++) {
            int idx = t + it * 128;
            int r = idx >> 2, c = idx & 3;
            int n = n0 + r;
            int sz = (n < N) ? 16 : 0;
            size_t off = (n < N) ? ((size_t)n * Kdim + kk0 + c * 8) : 0;
            uint32_t d = SWZ128(r, kh4 + c);
            cpa16(sBHI + d, Whi + off, sz);
            cpa16(sBLO + d, Wlo + off, sz);
        }
        asm volatile("cp.async.commit_group;");
    };

    int rsel = lane & 15, chalf = lane >> 4;
    auto compute_chunk = [&](int kc) {
        int kh4 = (kc & 1) * 4;
#pragma unroll
        for (int ks = 0; ks < 2; ks++) {
            int cc = kh4 + ks * 2 + chalf;
            uint32_t av[2][4];
#pragma unroll
            for (int i = 0; i < 2; i++) {
                int rr = wm + i * 16 + rsel;
                ldsm4(av[i], sA + SWZ128(rr, cc));
            }
#pragma unroll
            for (int jj = 0; jj < 4; jj++) {
                uint32_t bh[4], bl[4];
                int rr = wn + jj * 16 + rsel;
                uint32_t off = SWZ128(rr, cc);
                ldsm4(bh, sBHI + off);
                ldsm4(bl, sBLO + off);
                mma16816(acc[0][jj * 2 + 0], av[0], bh[0], bh[2]);
                mma16816(acc[0][jj * 2 + 1], av[0], bh[1], bh[3]);
                mma16816(acc[1][jj * 2 + 0], av[1], bh[0], bh[2]);
                mma16816(acc[1][jj * 2 + 1], av[1], bh[1], bh[3]);
                mma16816(acc[0][jj * 2 + 0], av[0], bl[0], bl[2]);
                mma16816(acc[0][jj * 2 + 1], av[0], bl[1], bl[3]);
                mma16816(acc[1][jj * 2 + 0], av[1], bl[0], bl[2]);
                mma16816(acc[1][jj * 2 + 1], av[1], bl[1], bl[3]);
            }
        }
    };

    if (!skip_compute) {
        load_chunk(0);
        for (int kc = 0; kc < nch; kc++) {
            asm volatile("cp.async.wait_group 0;");
            __syncthreads();
            if (kc + 1 < nch) load_chunk(kc + 1);
            compute_chunk(kc);
        }
    }

    int r0 = lane >> 2, c0 = (lane & 3) * 2;

    // ---- fused QKV epilogue: bias + rope (register pairs) + f16 store ----
    if (flags & FLAG_QKV) {
#pragma unroll
        for (int i = 0; i < 2; i++)
#pragma unroll
            for (int j = 0; j < 8; j++) {
                int nb = n0 + wn + j * 8 + c0;
                float b0 = __ldg(bias + nb), b1 = __ldg(bias + nb + 1);
                acc[i][j][0] += b0; acc[i][j][1] += b1;
                acc[i][j][2] += b0; acc[i][j][3] += b1;
            }
        int region = n0 >> 9;   // 0=q, 1=k, 2=v
        f16* df = (region == 0) ? g_qsf : (region == 1) ? g_ksf : g_vsf;
        if (region < 2) {
#pragma unroll
            for (int i = 0; i < 2; i++) {
                int mA = m0 + wm + i * 16 + r0;
                int sA2 = mA & (S_ - 1), sB2 = (mA + 8) & (S_ - 1);
#pragma unroll
                for (int j = 0; j < 4; j++) {
                    int jp = j + 4;
                    int t0 = (j * 8 + c0) & 31;
                    const float2* rA = g_rope + sA2 * 32 + t0;
                    const float2* rB = g_rope + sB2 * 32 + t0;
#pragma unroll
                    for (int e = 0; e < 2; e++) {
                        float2 cA = rA[e], cB = rB[e];
                        float xj = acc[i][j][e],      xp = acc[i][jp][e];
                        acc[i][j][e]  = xj * cA.x - xp * cA.y;
                        acc[i][jp][e] = xp * cA.x + xj * cA.y;
                        xj = acc[i][j][e + 2]; xp = acc[i][jp][e + 2];
                        acc[i][j][e + 2]  = xj * cB.x - xp * cB.y;
                        acc[i][jp][e + 2] = xp * cB.x + xj * cB.y;
                    }
                }
            }
        }
#pragma unroll
        for (int i = 0; i < 2; i++) {
            int mA = m0 + wm + i * 16 + r0, mB = mA + 8;
#pragma unroll
            for (int j = 0; j < 8; j++) {
                int nc = (n0 + wn + j * 8 + c0) & (H_ - 1);
                *(uint32_t*)(df + (size_t)mA * H_ + nc) =
                    packh(__float2half_rn(acc[i][j][0]), __float2half_rn(acc[i][j][1]));
                *(uint32_t*)(df + (size_t)mB * H_ + nc) =
                    packh(__float2half_rn(acc[i][j][2]), __float2half_rn(acc[i][j][3]));
            }
        }
        return;
    }

    // ---- standard epilogue ----
#pragma unroll
    for (int i = 0; i < 2; i++) {
        int mA = m0 + wm + i * 16 + r0;
        int mB = mA + 8;
        int sA2 = mA & (S_ - 1), bA = mA >> 9;
        int sB2 = mB & (S_ - 1), bB = mB >> 9;
        float mvA = 1.f, mvB = 1.f;
        if (flags & FLAG_MASK) {
            mvA = (sA2 >= lengths[bA]) ? 1.f : 0.f;   // reference's inverted mask
            mvB = (sB2 >= lengths[bB]) ? 1.f : 0.f;
        }
#pragma unroll
        for (int j = 0; j < 8; j++) {
            int nb = n0 + wn + j * 8 + c0;
            if (nb >= N) continue;
            float b0 = __ldg(bias + nb);
            float b1 = (nb + 1 < N) ? __ldg(bias + nb + 1) : 0.f;
            float v00 = acc[i][j][0] + b0, v01 = acc[i][j][1] + b1;
            float v10 = acc[i][j][2] + b0, v11 = acc[i][j][3] + b1;
            if (flags & FLAG_RELU) {
                v00 = fmaxf(v00, 0.f); v01 = fmaxf(v01, 0.f);
                v10 = fmaxf(v10, 0.f); v11 = fmaxf(v11, 0.f);
            }
            v00 *= mvA; v01 *= mvA; v10 *= mvB; v11 *= mvB;
            if (flags & FLAG_TRANS) {
                Cf[((size_t)bA * N + nb) * S_ + sA2] = v00;
                Cf[((size_t)bB * N + nb) * S_ + sB2] = v10;
                if (nb + 1 < N) {
                    Cf[((size_t)bA * N + nb + 1) * S_ + sA2] = v01;
                    Cf[((size_t)bB * N + nb + 1) * S_ + sB2] = v11;
                }
            } else {
                if (Cf) {
                    *(float2*)(Cf + (size_t)mA * N + nb) = make_float2(v00, v01);
                    *(float2*)(Cf + (size_t)mB * N + nb) = make_float2(v10, v11);
                }
                if (Cq) {
                    *(uint32_t*)(Cq + (size_t)mA * N + nb) =
                        packh(__float2half_rn(v00), __float2half_rn(v01));
                    *(uint32_t*)(Cq + (size_t)mB * N + nb) =
                        packh(__float2half_rn(v10), __float2half_rn(v11));
                }
            }
        }
    }
}

// ---------------- fp16 flash attention: single planes, 1 pass per GEMM ----------
__global__ __launch_bounds__(128, 4) void attn_kernel(
    const f16* __restrict__ qsf, const f16* __restrict__ ksf,
    const f16* __restrict__ vsf,
    f16* __restrict__ of, const int* __restrict__ lengths)
{
    extern __shared__ __align__(16) char sm[];
    const uint32_t sb = smem_u32(sm);
    const uint32_t QF = 0;
    const uint32_t ST0 = 8192, STSZ = 16384;

    int t = threadIdx.x, wid = t >> 5, lane = t & 31;
    int qt = blockIdx.x, hh = blockIdx.y, b = blockIdx.z;
    int len = lengths[b];

    int kt0 = len >> 6;
    if (kt0 > 7) kt0 = 7;

#pragma unroll
    for (int it = 0; it < 4; it++) {
        int idx = t + it * 128;
        int r = idx >> 3, c = idx & 7;
        size_t src = ((size_t)b * S_ + qt * 64 + r) * H_ + hh * HD_ + c * 8;
        cpa16(sb + QF + SWZ128(r, c), qsf + src, 16);
    }
    asm volatile("cp.async.commit_group;");

    auto load_kv = [&](int kt, int stg) {
        uint32_t base = sb + ST0 + stg * STSZ;
#pragma unroll
        for (int it = 0; it < 4; it++) {
            int idx = t + it * 128;
            int r = idx >> 3, c = idx & 7;
            size_t src = ((size_t)b * S_ + kt * 64 + r) * H_ + hh * HD_ + c * 8;
            uint32_t d = SWZ128(r, c);
            cpa16(base + d,        ksf + src, 16);
            cpa16(base + 8192 + d, vsf + src, 16);
        }
        asm volatile("cp.async.commit_group;");
    };
    load_kv(kt0, 0);

    asm volatile("cp.async.wait_group 1;");
    __syncthreads();

    int rsel = lane & 15, chalf = lane >> 4;
    uint32_t qf[4][4];
#pragma unroll
    for (int ks = 0; ks < 4; ks++) {
        int rr = wid * 16 + rsel;
        ldsm4(qf[ks], sb + QF + SWZ128(rr, ks * 2 + chalf));
    }

    float oc[8][4];
#pragma unroll
    for (int dt = 0; dt < 8; dt++)
#pragma unroll
        for (int e = 0; e < 4; e++) oc[dt][e] = 0.f;
    float m0 = -INFINITY, m1 = -INFINITY, ls0 = 0.f, ls1 = 0.f;

    for (int kt = kt0; kt < 8; kt++) {
        int stg = (kt - kt0) & 1;
        uint32_t KB = sb + ST0 + stg * STSZ;
        asm volatile("cp.async.wait_group 0;");
        __syncthreads();
        if (kt + 1 < 8) load_kv(kt + 1, stg ^ 1);

        float sv[8][4];
#pragma unroll
        for (int jt = 0; jt < 8; jt++)
#pragma unroll
            for (int e = 0; e < 4; e++) sv[jt][e] = 0.f;
#pragma unroll
        for (int ks = 0; ks < 4; ks++) {
#pragma unroll
            for (int jj = 0; jj < 4; jj++) {
                uint32_t bk[4];
                int rr = jj * 16 + rsel;
                ldsm4(bk, KB + SWZ128(rr, ks * 2 + chalf));
                mma16816(sv[jj * 2 + 0], qf[ks], bk[0], bk[2]);
                mma16816(sv[jj * 2 + 1], qf[ks], bk[1], bk[3]);
            }
        }

        int colb = kt * 64 + (lane & 3) * 2;
        float rm0 = -INFINITY, rm1 = -INFINITY;
#pragma unroll
        for (int jt = 0; jt < 8; jt++) {
#pragma unroll
            for (int e = 0; e < 2; e++) {
                int kp = colb + jt * 8 + e;
                bool keep = (kp >= len);
                float v0 = sv[jt][e] * 0.125f;
                float v1 = sv[jt][2 + e] * 0.125f;
                sv[jt][e]     = keep ? v0 : -1e9f;
                sv[jt][2 + e] = keep ? v1 : -1e9f;
                rm0 = fmaxf(rm0, sv[jt][e]);
                rm1 = fmaxf(rm1, sv[jt][2 + e]);
            }
        }
        rm0 = fmaxf(rm0, __shfl_xor_sync(0xffffffffu, rm0, 1));
        rm0 = fmaxf(rm0, __shfl_xor_sync(0xffffffffu, rm0, 2));
        rm1 = fmaxf(rm1, __shfl_xor_sync(0xffffffffu, rm1, 1));
        rm1 = fmaxf(rm1, __shfl_xor_sync(0xffffffffu, rm1, 2));
        float mn0 = fmaxf(m0, rm0), mn1 = fmaxf(m1, rm1);
        float a0 = __expf(m0 - mn0), a1 = __expf(m1 - mn1);
        m0 = mn0; m1 = mn1;
        float s0 = 0.f, s1 = 0.f;
#pragma unroll
        for (int jt = 0; jt < 8; jt++) {
            sv[jt][0] = __expf(sv[jt][0] - mn0);
            sv[jt][1] = __expf(sv[jt][1] - mn0);
            sv[jt][2] = __expf(sv[jt][2] - mn1);
            sv[jt][3] = __expf(sv[jt][3] - mn1);
            s0 += sv[jt][0] + sv[jt][1];
            s1 += sv[jt][2] + sv[jt][3];
        }
        s0 += __shfl_xor_sync(0xffffffffu, s0, 1);
        s0 += __shfl_xor_sync(0xffffffffu, s0, 2);
        s1 += __shfl_xor_sync(0xffffffffu, s1, 1);
        s1 += __shfl_xor_sync(0xffffffffu, s1, 2);
        ls0 = ls0 * a0 + s0;
        ls1 = ls1 * a1 + s1;
#pragma unroll
        for (int dt = 0; dt < 8; dt++) {
            oc[dt][0] *= a0; oc[dt][1] *= a0;
            oc[dt][2] *= a1; oc[dt][3] *= a1;
        }

        uint32_t VB = KB + 8192;
#pragma unroll
        for (int jp = 0; jp < 4; jp++) {
            uint32_t pa[4];
#pragma unroll
            for (int half = 0; half < 2; half++) {
                pa[2 * half + 0] = packh(__float2half_rn(sv[2 * jp + half][0]),
                                         __float2half_rn(sv[2 * jp + half][1]));
                pa[2 * half + 1] = packh(__float2half_rn(sv[2 * jp + half][2]),
                                         __float2half_rn(sv[2 * jp + half][3]));
            }
            int vrow = jp * 16 + ((lane >> 3) & 1) * 8 + (lane & 7);
#pragma unroll
            for (int g = 0; g < 4; g++) {
                int cch = 2 * g + (lane >> 4);
                uint32_t vv[4];
                ldsm4t(vv, VB + SWZ128(vrow, cch));
                mma16816(oc[2 * g],     pa, vv[0], vv[1]);
                mma16816(oc[2 * g + 1], pa, vv[2], vv[3]);
            }
        }
        __syncthreads();
    }

    float i0 = 1.f / ls0, i1 = 1.f / ls1;
    int r0 = qt * 64 + wid * 16 + (lane >> 2);
#pragma unroll
    for (int dt = 0; dt < 8; dt++) {
        int d = hh * HD_ + dt * 8 + (lane & 3) * 2;
        size_t o0 = ((size_t)b * S_ + r0) * H_ + d;
        size_t o1 = o0 + (size_t)8 * H_;
        *(uint32_t*)(of + o0) = packh(__float2half_rn(oc[dt][0] * i0),
                                      __float2half_rn(oc[dt][1] * i0));
        *(uint32_t*)(of + o1) = packh(__float2half_rn(oc[dt][2] * i1),
                                      __float2half_rn(oc[dt][3] * i1));
    }
}

// ------- LayerNorm, 2 rows/block; optional residual, f16 and masked-f16 outs ----
__global__ __launch_bounds__(256) void ln_kernel(
    const float* __restrict__ x, const float* __restrict__ res,
    const float* __restrict__ g, const float* __restrict__ be,
    float* __restrict__ out, f16* __restrict__ of, int C,
    const int* __restrict__ lengths, f16* __restrict__ mf)
{
    int rb = threadIdx.x >> 7;
    int m  = blockIdx.x * 2 + rb;
    int t  = threadIdx.x & 127;
    int nv = C >> 2;
    float4 v = make_float4(0.f, 0.f, 0.f, 0.f);
    if (t < nv) {
        v = ((const float4*)(x + (size_t)m * C))[t];
        if (res) {
            float4 w = ((const float4*)(res + (size_t)m * C))[t];
            v.x += w.x; v.y += w.y; v.z += w.z; v.w += w.w;
        }
    }
    float sum = v.x + v.y + v.z + v.w;
    float sq  = v.x * v.x + v.y * v.y + v.z * v.z + v.w * v.w;
#pragma unroll
    for (int off = 16; off; off >>= 1) {
        sum += __shfl_xor_sync(0xffffffffu, sum, off);
        sq  += __shfl_xor_sync(0xffffffffu, sq,  off);
    }
    __shared__ float s1[2][4], s2[2][4];
    if ((t & 31) == 0) { s1[rb][t >> 5] = sum; s2[rb][t >> 5] = sq; }
    __syncthreads();
    sum = s1[rb][0] + s1[rb][1] + s1[rb][2] + s1[rb][3];
    sq  = s2[rb][0] + s2[rb][1] + s2[rb][2] + s2[rb][3];
    float mean = sum / C;
    float var  = sq / C - mean * mean;
    float inv  = rsqrtf(var + 1e-5f);
    if (t < nv) {
        float4 gv = ((const float4*)g)[t];
        float4 bv = ((const float4*)be)[t];
        float4 o4;
        o4.x = (v.x - mean) * inv * gv.x + bv.x;
        o4.y = (v.y - mean) * inv * gv.y + bv.y;
        o4.z = (v.z - mean) * inv * gv.z + bv.z;
        o4.w = (v.w - mean) * inv * gv.w + bv.w;
        if (out) ((float4*)(out + (size_t)m * C))[t] = o4;
        if (of) {
            *(uint32_t*)(of + (size_t)m * C + t * 4) =
                packh(__float2half_rn(o4.x), __float2half_rn(o4.y));
            *(uint32_t*)(of + (size_t)m * C + t * 4 + 2) =
                packh(__float2half_rn(o4.z), __float2half_rn(o4.w));
        }
        if (mf) {
            int s = m & (S_ - 1), b = m >> 9;
            float mv = (s >= lengths[b]) ? 1.f : 0.f;   // inverted mask
            *(uint32_t*)(mf + (size_t)m * C + t * 4) =
                packh(__float2half_rn(o4.x * mv), __float2half_rn(o4.y * mv));
            *(uint32_t*)(mf + (size_t)m * C + t * 4 + 2) =
                packh(__float2half_rn(o4.z * mv), __float2half_rn(o4.w * mv));
        }
    }
}

// ---------------- small kernels ----------------
__global__ __launch_bounds__(256) void embed_kernel(
    const int* __restrict__ x, const float* __restrict__ emb,
    float* __restrict__ h, f16* __restrict__ hf)
{
    int idx = blockIdx.x * blockDim.x + threadIdx.x;
    if (idx >= M_ * (H_ / 4)) return;
    int m = idx >> 7, c4 = idx & 127;
    int tok = x[m];
    float4 e = ((const float4*)(emb + (size_t)tok * H_))[c4];
    const float sc = 22.62741699796952f;  // sqrt(512)
    e.x *= sc; e.y *= sc; e.z *= sc; e.w *= sc;
    ((float4*)(h + (size_t)m * H_))[c4] = e;
    *(uint32_t*)(hf + (size_t)m * H_ + c4 * 4) =
        packh(__float2half_rn(e.x), __float2half_rn(e.y));
    *(uint32_t*)(hf + (size_t)m * H_ + c4 * 4 + 2) =
        packh(__float2half_rn(e.z), __float2half_rn(e.w));
}

#define NW1 (L_*F_*H_*3)
#define NW2 (L_*H_*F_*3)
#define ND1 (FD_*H_*3)
#define ND2 (FD_*FD_*3)
__global__ __launch_bounds__(256) void prep_conv_kernel(
    const float* __restrict__ c1w, const float* __restrict__ c2w,
    const float* __restrict__ d1w, const float* __restrict__ d2w)
{
    int idx = blockIdx.x * blockDim.x + threadIdx.x;
    const float* src; f16 *dh, *dl; int CI; int base;
    if (idx < NW1)                        { src = c1w; dh = g_w1h; dl = g_w1l; CI = H_;  base = idx; }
    else if (idx < NW1 + NW2)             { src = c2w; dh = g_w2h; dl = g_w2l; CI = F_;  base = idx - NW1; }
    else if (idx < NW1 + NW2 + ND1)       { src = d1w; dh = g_d1h; dl = g_d1l; CI = H_;  base = idx - NW1 - NW2; }
    else if (idx < NW1 + NW2 + ND1 + ND2) { src = d2w; dh = g_d2h; dl = g_d2l; CI = FD_; base = idx - NW1 - NW2 - ND1; }
    else return;
    int kk = base % 3;
    int rest = base / 3;
    int ci = rest % CI;
    int co = rest / CI;
    f16 h, l; split_w(src[base], h, l);
    size_t o = (size_t)co * (3 * CI) + kk * CI + ci;
    dh[o] = h; dl[o] = l;
}

#define NQKV (L_*3*H_*H_)
#define NWO  (L_*H_*H_)
#define NPJ  (OUT_*H_)
#define NBQ  (L_*3*H_)
#define NRT  (S_*32)
__global__ __launch_bounds__(256) void prep_lin_kernel(
    const float* __restrict__ Wq, const float* __restrict__ Wk,
    const float* __restrict__ Wv, const float* __restrict__ Wo,
    const float* __restrict__ pj,
    const float* __restrict__ bq, const float* __restrict__ bk,
    const float* __restrict__ bv)
{
    int idx = blockIdx.x * blockDim.x + threadIdx.x;
    if (idx < NQKV) {
        int e = idx % H_;
        int n = (idx / H_) % (3 * H_);
        int l = idx / (3 * H_ * H_);
        const float* W = (n < H_) ? Wq : (n < 2 * H_) ? Wk : Wv;
        int nn = n & (H_ - 1);
        f16 h, lo; split_w(W[(size_t)l * H_ * H_ + (size_t)nn * H_ + e], h, lo);
        g_wqkvh[idx] = h; g_wqkvl[idx] = lo;
        return;
    }
    int i2 = idx - NQKV;
    if (i2 < NWO) {
        f16 h, lo; split_w(Wo[i2], h, lo);
        g_woh[i2] = h; g_wol[i2] = lo;
        return;
    }
    int i3 = i2 - NWO;
    if (i3 < NPJ) {
        f16 h, lo; split_w(pj[i3], h, lo);
        g_pjh[i3] = h; g_pjl[i3] = lo;
        return;
    }
    int i4 = i3 - NPJ;
    if (i4 < NBQ) {
        int n = i4 % (3 * H_);
        int l = i4 / (3 * H_);
        const float* bb = (n < H_) ? bq : (n < 2 * H_) ? bk : bv;
        g_bqkv[i4] = bb[l * H_ + (n & (H_ - 1))];
        return;
    }
    int i5 = i4 - NBQ;
    if (i5 < NRT) {
        int s = i5 >> 5, j = i5 & 31;
        float th = expf(-(float)j * 0.28782313662425574f);
        float sn, cs;
        sincosf((float)s * th, &sn, &cs);
        g_rope[i5] = make_float2(cs, sn);
    }
}

__global__ __launch_bounds__(256) void dp_final_kernel(
    const float* __restrict__ x, const float* __restrict__ w,
    const float* __restrict__ pb, const int* __restrict__ lengths,
    float* __restrict__ out)
{
    int warp = threadIdx.x >> 5, lane = threadIdx.x & 31;
    int m = blockIdx.x * 8 + warp;
    if (m >= M_) return;
    const float* xr = x + (size_t)m * FD_;
    float s = 0.f;
    for (int c = lane; c < FD_; c += 32) s += xr[c] * w[c];
#pragma unroll
    for (int off = 16; off; off >>= 1) s += __shfl_xor_sync(0xffffffffu, s, off);
    if (lane == 0) {
        int b = m >> 9, sp = m & (S_ - 1);
        float mv = (sp >= lengths[b]) ? 1.f : 0.f;
        float val = (s + pb[0]) * mv;
        out[(size_t)b * S_ + sp] = ceilf(expf(val));
    }
}

// ---------------- orchestration ----------------
extern "C" void kernel_launch(void* const* d_in, const int* in_sizes, int n_in,
                              void* d_out, int out_size)
{
    const int*   x      = (const int*)  d_in[0];
    const int*   xlen   = (const int*)  d_in[1];
    const float* emb    = (const float*)d_in[2];
    const float* Wq     = (const float*)d_in[3];
    const float* bq     = (const float*)d_in[4];
    const float* Wk     = (const float*)d_in[5];
    const float* bk     = (const float*)d_in[6];
    const float* Wv     = (const float*)d_in[7];
    const float* bv     = (const float*)d_in[8];
    const float* Wo     = (const float*)d_in[9];
    const float* bo     = (const float*)d_in[10];
    const float* c1w    = (const float*)d_in[11];
    const float* c1b    = (const float*)d_in[12];
    const float* c2w    = (const float*)d_in[13];
    const float* c2b    = (const float*)d_in[14];
    const float* ln1g   = (const float*)d_in[15];
    const float* ln1b   = (const float*)d_in[16];
    const float* ln2g   = (const float*)d_in[17];
    const float* ln2b   = (const float*)d_in[18];
    const float* projw  = (const float*)d_in[19];
    const float* projb  = (const float*)d_in[20];
    const float* dpc1w  = (const float*)d_in[21];
    const float* dpc1b  = (const float*)d_in[22];
    const float* dpln1g = (const float*)d_in[23];
    const float* dpln1b = (const float*)d_in[24];
    const float* dpc2w  = (const float*)d_in[25];
    const float* dpc2b  = (const float*)d_in[26];
    const float* dpln2g = (const float*)d_in[27];
    const float* dpln2b = (const float*)d_in[28];
    const float* dppw   = (const float*)d_in[29];
    const float* dppb   = (const float*)d_in[30];
    float* out = (float*)d_out;

    float *h, *x1, *op, *cv2, *bqkv;
    f16 *hf, *x1f, *af, *midf, *mkf, *dpxf, *qsf, *ksf, *vsf;
    f16 *wqh, *wql, *woh, *wol, *w1h, *w1l, *w2h, *w2l, *pjh, *pjl, *d1h, *d1l, *d2h, *d2l;
    cudaGetSymbolAddress((void**)&h,    g_h);
    cudaGetSymbolAddress((void**)&x1,   g_x1);
    cudaGetSymbolAddress((void**)&op,   g_op);
    cudaGetSymbolAddress((void**)&cv2,  g_cv2);
    cudaGetSymbolAddress((void**)&hf,   g_hf);
    cudaGetSymbolAddress((void**)&x1f,  g_x1f);
    cudaGetSymbolAddress((void**)&af,   g_af);
    cudaGetSymbolAddress((void**)&midf, g_midf);
    cudaGetSymbolAddress((void**)&mkf,  g_mkf);
    cudaGetSymbolAddress((void**)&dpxf, g_dpxf);
    cudaGetSymbolAddress((void**)&qsf,  g_qsf);
    cudaGetSymbolAddress((void**)&ksf,  g_ksf);
    cudaGetSymbolAddress((void**)&vsf,  g_vsf);
    cudaGetSymbolAddress((void**)&wqh,  g_wqkvh);
    cudaGetSymbolAddress((void**)&wql,  g_wqkvl);
    cudaGetSymbolAddress((void**)&woh,  g_woh);
    cudaGetSymbolAddress((void**)&wol,  g_wol);
    cudaGetSymbolAddress((void**)&w1h,  g_w1h);
    cudaGetSymbolAddress((void**)&w1l,  g_w1l);
    cudaGetSymbolAddress((void**)&w2h,  g_w2h);
    cudaGetSymbolAddress((void**)&w2l,  g_w2l);
    cudaGetSymbolAddress((void**)&pjh,  g_pjh);
    cudaGetSymbolAddress((void**)&pjl,  g_pjl);
    cudaGetSymbolAddress((void**)&d1h,  g_d1h);
    cudaGetSymbolAddress((void**)&d1l,  g_d1l);
    cudaGetSymbolAddress((void**)&d2h,  g_d2h);
    cudaGetSymbolAddress((void**)&d2l,  g_d2l);
    cudaGetSymbolAddress((void**)&bqkv, g_bqkv);

    cudaFuncSetAttribute((const void*)attn_kernel,
                         cudaFuncAttributeMaxDynamicSharedMemorySize, 40960);
    cudaFuncSetAttribute((const void*)hgemm_kernel,
                         cudaFuncAttributeMaxDynamicSharedMemorySize, 40960);

    {
        int tot = NW1 + NW2 + ND1 + ND2;
        prep_conv_kernel<<<(tot + 255) / 256, 256>>>(c1w, c2w, dpc1w, dpc2w);
        tot = NQKV + NWO + NPJ + NBQ + NRT;
        prep_lin_kernel<<<(tot + 255) / 256, 256>>>(Wq, Wk, Wv, Wo, projw, bq, bk, bv);
    }
    embed_kernel<<<M_ * (H_ / 4) / 256, 256>>>(x, emb, h, hf);

    const int SM_G = 40960;
    const int SM_A = 40960;
    dim3 gQKV(3 * H_ / 128, M_ / 64);   // (12,256)
    dim3 gH(H_ / 128, M_ / 64);         // (4,256)
    dim3 gF(F_ / 128, M_ / 64);         // (16,256)
    dim3 gMu(1, M_ / 64);
    dim3 gDp(FD_ / 128, M_ / 64);       // (2,256)
    dim3 ga(S_ / 64, NH_, B_);
    const int LNB = M_ / 2;

    for (int l = 0; l < L_; l++) {
        size_t wOff = (size_t)l * H_ * H_;
        size_t wqOff = (size_t)l * 3 * H_ * H_;
        bool last = (l == L_ - 1);
        hgemm_kernel<<<gQKV, 128, SM_G>>>(hf, wqh + wqOff, wql + wqOff,
                                          bqkv + l * 3 * H_, nullptr, nullptr,
                                          3 * H_, 9, 1, 0, FLAG_QKV, xlen);
        attn_kernel<<<ga, 128, SM_A>>>(qsf, ksf, vsf, af, xlen);
        hgemm_kernel<<<gH, 128, SM_G>>>(af, woh + wOff, wol + wOff,
                                        bo + l * H_, op, nullptr,
                                        H_, 9, 1, 0, 0, xlen);
        ln_kernel<<<LNB, 256>>>(op, h, ln1g + l * H_, ln1b + l * H_,
                                x1, x1f, H_, nullptr, nullptr);
        hgemm_kernel<<<gF, 128, SM_G>>>(x1f,
                                        w1h + (size_t)l * F_ * 3 * H_, w1l + (size_t)l * F_ * 3 * H_,
                                        c1b + l * F_, nullptr, midf,
                                        F_, 9, 3, 1, FLAG_RELU, xlen);
        hgemm_kernel<<<gH, 128, SM_G>>>(midf,
                                        w2h + (size_t)l * H_ * 3 * F_, w2l + (size_t)l * H_ * 3 * F_,
                                        c2b + l * H_, cv2, nullptr,
                                        H_, 11, 3, 1, 0, xlen);
        ln_kernel<<<LNB, 256>>>(cv2, x1, ln2g + l * H_, ln2b + l * H_,
                                h, hf, H_,
                                last ? xlen : nullptr,
                                last ? mkf : nullptr);
    }

    hgemm_kernel<<<gMu, 128, SM_G>>>(hf, pjh, pjl, projb, out, nullptr,
                                     OUT_, 9, 1, 0, FLAG_TRANS, xlen);

    hgemm_kernel<<<gDp, 128, SM_G>>>(mkf, d1h, d1l, dpc1b, op, nullptr,
                                     FD_, 9, 3, 1, FLAG_RELU | FLAG_MASK, xlen);
    ln_kernel<<<LNB, 256>>>(op, nullptr, dpln1g, dpln1b, cv2, dpxf, FD_,
                            nullptr, nullptr);
    hgemm_kernel<<<gDp, 128, SM_G>>>(dpxf, d2h, d2l, dpc2b, op, nullptr,
                                     FD_, 8, 3, 1, FLAG_RELU | FLAG_MASK, xlen);
    ln_kernel<<<LNB, 256>>>(op, nullptr, dpln2g, dpln2b, x1, nullptr, FD_,
                            nullptr, nullptr);
    dp_final_kernel<<<M_ / 8, 256>>>(x1, dppw, dppb, xlen,
                                     out + ((size_t)out_size - (size_t)B_ * S_));
}

// round 17
// speedup vs baseline: 1.6367x; 1.0295x over previous
#include <cuda_runtime.h>
#include <cuda_fp16.h>
#include <math.h>
#include <stdint.h>

#define B_   32
#define S_   512
#define H_   512
#define NH_  8
#define HD_  64
#define F_   2048
#define L_   6
#define OUT_ 80
#define FD_  256
#define M_   (B_*S_)   // 16384 tokens

typedef __half  f16;

// ---------------- scratch (static device globals) ----------------
__device__ float g_h   [M_*H_];
__device__ float g_x1  [M_*H_];
__device__ float g_op  [M_*H_];
__device__ float g_cv2 [M_*H_];
__device__ f16   g_hf  [M_*H_];
__device__ f16   g_x1f [M_*H_];
__device__ f16   g_af  [M_*H_];
__device__ f16   g_midf[M_*F_];
__device__ f16   g_mkf [M_*H_];
__device__ f16   g_dpxf[M_*FD_];
__device__ f16   g_qsf[M_*H_], g_ksf[M_*H_], g_vsf[M_*H_];
__device__ f16   g_wqkvh[L_*3*H_*H_], g_wqkvl[L_*3*H_*H_];
__device__ f16   g_woh [L_*H_*H_],    g_wol [L_*H_*H_];
__device__ f16   g_w1h [L_*F_*3*H_],  g_w1l [L_*F_*3*H_];
__device__ f16   g_w2h [L_*H_*3*F_],  g_w2l [L_*H_*3*F_];
__device__ f16   g_pjh [OUT_*H_],     g_pjl [OUT_*H_];
__device__ f16   g_d1h [FD_*3*H_],    g_d1l [FD_*3*H_];
__device__ f16   g_d2h [FD_*3*FD_],   g_d2l [FD_*3*FD_];
__device__ float g_bqkv[L_*3*H_];
__device__ float2 g_rope[S_*32];

#define FLAG_RELU  1
#define FLAG_MASK  2
#define FLAG_TRANS 4
#define FLAG_QKV   8
#define FLAG_W1P   16   // single-pass weights (skip lo plane)

#define SWZ128(r,c) ((uint32_t)((r)*128 + ((((c) ^ ((r)&7))) << 4)))

// ---------------- helpers ----------------
__device__ __forceinline__ void split_w(float x, f16& h, f16& l) {
    h = __float2half_rn(x);
    l = __float2half_rn(x - __half2float(h));
}

__device__ __forceinline__ uint32_t packh(f16 x, f16 y) {
    return (uint32_t)__half_as_ushort(x) | ((uint32_t)__half_as_ushort(y) << 16);
}

__device__ __forceinline__ uint32_t smem_u32(const void* p) {
    uint32_t a;
    asm("{ .reg .u64 t; cvta.to.shared.u64 t, %1; cvt.u32.u64 %0, t; }" : "=r"(a) : "l"(p));
    return a;
}

__device__ __forceinline__ void cpa16(uint32_t dst, const void* src, int sz) {
    asm volatile("cp.async.cg.shared.global [%0], [%1], 16, %2;"
                 :: "r"(dst), "l"(src), "r"(sz));
}

__device__ __forceinline__ void ldsm4(uint32_t* r, uint32_t addr) {
    asm volatile("ldmatrix.sync.aligned.m8n8.x4.shared.b16 {%0,%1,%2,%3}, [%4];"
                 : "=r"(r[0]), "=r"(r[1]), "=r"(r[2]), "=r"(r[3]) : "r"(addr));
}

__device__ __forceinline__ void ldsm4t(uint32_t* r, uint32_t addr) {
    asm volatile("ldmatrix.sync.aligned.m8n8.x4.trans.shared.b16 {%0,%1,%2,%3}, [%4];"
                 : "=r"(r[0]), "=r"(r[1]), "=r"(r[2]), "=r"(r[3]) : "r"(addr));
}

__device__ __forceinline__ void mma16816(float* c, const uint32_t* a,
                                         uint32_t b0, uint32_t b1) {
    asm volatile(
        "mma.sync.aligned.m16n8k16.row.col.f32.f16.f16.f32 "
        "{%0,%1,%2,%3}, {%4,%5,%6,%7}, {%8,%9}, {%0,%1,%2,%3};"
        : "+f"(c[0]), "+f"(c[1]), "+f"(c[2]), "+f"(c[3])
        : "r"(a[0]), "r"(a[1]), "r"(a[2]), "r"(a[3]), "r"(b0), "r"(b1));
}

// ---------------- fp16 HMMA GEMM: A single-plane, W 1- or 2-plane ----------
// 128 threads, 4 warps (2x2, warp tile 32x64), CTA tile 64x128, K-chunk 32.
// smem: A 8K | Bhi 16K | Blo 16K = 40KB, 4 CTAs/SM.
// Tile skips (bit-exact): QKV k/v tiles never read by attention; fully-masked
// dp tiles skip compute.
__global__ __launch_bounds__(128, 4) void hgemm_kernel(
    const f16* __restrict__ Af,
    const f16* __restrict__ Whi, const f16* __restrict__ Wlo,
    const float* __restrict__ bias,
    float* __restrict__ Cf, f16* __restrict__ Cq,
    int N, int cinLog2, int nseg, int pad, int flags,
    const int* __restrict__ lengths)
{
    extern __shared__ __align__(16) char smem[];
    const uint32_t sb = smem_u32(smem);
    const uint32_t sA = sb, sBHI = sb + 8192, sBLO = sb + 24576;

    int t = threadIdx.x, wid = t >> 5, lane = t & 31;
    int m0 = blockIdx.y * 64, n0 = blockIdx.x * 128;
    int cin  = 1 << cinLog2;
    int Kdim = nseg << cinLog2;
    int nch  = Kdim >> 5;
    int wm = (wid >> 1) * 32, wn = (wid & 1) * 64;
    const bool twop = !(flags & FLAG_W1P);

    // ---- zero-risk tile skips ----
    bool skip_compute = false;
    {
        int bb = m0 >> 9;
        int s0 = m0 & (S_ - 1);
        if (flags & FLAG_QKV) {
            int region = n0 >> 9;               // 0=q, 1=k, 2=v
            if (region >= 1 && (s0 >> 6) < (lengths[bb] >> 6)) return;
        } else if (flags & FLAG_MASK) {
            if (s0 + 63 < lengths[bb]) skip_compute = true;
        }
    }

    float acc[2][8][4];
#pragma unroll
    for (int i = 0; i < 2; i++)
#pragma unroll
        for (int j = 0; j < 8; j++)
#pragma unroll
            for (int e = 0; e < 4; e++) acc[i][j][e] = 0.f;

    auto load_chunk = [&](int kc) {
        int kh4 = (kc & 1) * 4;
        int kk0 = kc << 5;
        int seg = kk0 >> cinLog2;
        int ci0 = kk0 & (cin - 1);
#pragma unroll
        for (int it = 0; it < 2; it++) {
            int idx = t + it * 128;
            int r = idx >> 2, c = idx & 3;
            int m = m0 + r;
            const f16* sh = Af;
            int sz = 16;
            if (nseg == 1) {
                sh += (size_t)m * cin + kk0 + c * 8;
            } else {
                int s = m & (S_ - 1);
                int srow = s + seg - pad;
                if (srow >= 0 && srow < S_)
                    sh += (size_t)(m + srow - s) * cin + ci0 + c * 8;
                else sz = 0;
            }
            cpa16(sA + SWZ128(r, kh4 + c), sh, sz);
        }
#pragma unroll
        for (int it = 0; it < 4; it++) {
            int idx = t + it * 128;
            int r = idx >> 2, c = idx & 3;
            int n = n0 + r;
            int sz = (n < N) ? 16 : 0;
            size_t off = (n < N) ? ((size_t)n * Kdim + kk0 + c * 8) : 0;
            uint32_t d = SWZ128(r, kh4 + c);
            cpa16(sBHI + d, Whi + off, sz);
            if (twop) cpa16(sBLO + d, Wlo + off, sz);
        }
        asm volatile("cp.async.commit_group;");
    };

    int rsel = lane & 15, chalf = lane >> 4;
    auto compute_chunk = [&](int kc) {
        int kh4 = (kc & 1) * 4;
#pragma unroll
        for (int ks = 0; ks < 2; ks++) {
            int cc = kh4 + ks * 2 + chalf;
            uint32_t av[2][4];
#pragma unroll
            for (int i = 0; i < 2; i++) {
                int rr = wm + i * 16 + rsel;
                ldsm4(av[i], sA + SWZ128(rr, cc));
            }
#pragma unroll
            for (int jj = 0; jj < 4; jj++) {
                uint32_t bh[4];
                int rr = wn + jj * 16 + rsel;
                uint32_t off = SWZ128(rr, cc);
                ldsm4(bh, sBHI + off);
                mma16816(acc[0][jj * 2 + 0], av[0], bh[0], bh[2]);
                mma16816(acc[0][jj * 2 + 1], av[0], bh[1], bh[3]);
                mma16816(acc[1][jj * 2 + 0], av[1], bh[0], bh[2]);
                mma16816(acc[1][jj * 2 + 1], av[1], bh[1], bh[3]);
                if (twop) {
                    uint32_t bl[4];
                    ldsm4(bl, sBLO + off);
                    mma16816(acc[0][jj * 2 + 0], av[0], bl[0], bl[2]);
                    mma16816(acc[0][jj * 2 + 1], av[0], bl[1], bl[3]);
                    mma16816(acc[1][jj * 2 + 0], av[1], bl[0], bl[2]);
                    mma16816(acc[1][jj * 2 + 1], av[1], bl[1], bl[3]);
                }
            }
        }
    };

    if (!skip_compute) {
        load_chunk(0);
        for (int kc = 0; kc < nch; kc++) {
            asm volatile("cp.async.wait_group 0;");
            __syncthreads();
            if (kc + 1 < nch) load_chunk(kc + 1);
            compute_chunk(kc);
        }
    }

    int r0 = lane >> 2, c0 = (lane & 3) * 2;

    // ---- fused QKV epilogue: bias + rope (register pairs) + f16 store ----
    if (flags & FLAG_QKV) {
#pragma unroll
        for (int i = 0; i < 2; i++)
#pragma unroll
            for (int j = 0; j < 8; j++) {
                int nb = n0 + wn + j * 8 + c0;
                float b0 = __ldg(bias + nb), b1 = __ldg(bias + nb + 1);
                acc[i][j][0] += b0; acc[i][j][1] += b1;
                acc[i][j][2] += b0; acc[i][j][3] += b1;
            }
        int region = n0 >> 9;   // 0=q, 1=k, 2=v
        f16* df = (region == 0) ? g_qsf : (region == 1) ? g_ksf : g_vsf;
        if (region < 2) {
#pragma unroll
            for (int i = 0; i < 2; i++) {
                int mA = m0 + wm + i * 16 + r0;
                int sA2 = mA & (S_ - 1), sB2 = (mA + 8) & (S_ - 1);
#pragma unroll
                for (int j = 0; j < 4; j++) {
                    int jp = j + 4;
                    int t0 = (j * 8 + c0) & 31;
                    const float2* rA = g_rope + sA2 * 32 + t0;
                    const float2* rB = g_rope + sB2 * 32 + t0;
#pragma unroll
                    for (int e = 0; e < 2; e++) {
                        float2 cA = rA[e], cB = rB[e];
                        float xj = acc[i][j][e],      xp = acc[i][jp][e];
                        acc[i][j][e]  = xj * cA.x - xp * cA.y;
                        acc[i][jp][e] = xp * cA.x + xj * cA.y;
                        xj = acc[i][j][e + 2]; xp = acc[i][jp][e + 2];
                        acc[i][j][e + 2]  = xj * cB.x - xp * cB.y;
                        acc[i][jp][e + 2] = xp * cB.x + xj * cB.y;
                    }
                }
            }
        }
#pragma unroll
        for (int i = 0; i < 2; i++) {
            int mA = m0 + wm + i * 16 + r0, mB = mA + 8;
#pragma unroll
            for (int j = 0; j < 8; j++) {
                int nc = (n0 + wn + j * 8 + c0) & (H_ - 1);
                *(uint32_t*)(df + (size_t)mA * H_ + nc) =
                    packh(__float2half_rn(acc[i][j][0]), __float2half_rn(acc[i][j][1]));
                *(uint32_t*)(df + (size_t)mB * H_ + nc) =
                    packh(__float2half_rn(acc[i][j][2]), __float2half_rn(acc[i][j][3]));
            }
        }
        return;
    }

    // ---- standard epilogue ----
#pragma unroll
    for (int i = 0; i < 2; i++) {
        int mA = m0 + wm + i * 16 + r0;
        int mB = mA + 8;
        int sA2 = mA & (S_ - 1), bA = mA >> 9;
        int sB2 = mB & (S_ - 1), bB = mB >> 9;
        float mvA = 1.f, mvB = 1.f;
        if (flags & FLAG_MASK) {
            mvA = (sA2 >= lengths[bA]) ? 1.f : 0.f;   // reference's inverted mask
            mvB = (sB2 >= lengths[bB]) ? 1.f : 0.f;
        }
#pragma unroll
        for (int j = 0; j < 8; j++) {
            int nb = n0 + wn + j * 8 + c0;
            if (nb >= N) continue;
            float b0 = __ldg(bias + nb);
            float b1 = (nb + 1 < N) ? __ldg(bias + nb + 1) : 0.f;
            float v00 = acc[i][j][0] + b0, v01 = acc[i][j][1] + b1;
            float v10 = acc[i][j][2] + b0, v11 = acc[i][j][3] + b1;
            if (flags & FLAG_RELU) {
                v00 = fmaxf(v00, 0.f); v01 = fmaxf(v01, 0.f);
                v10 = fmaxf(v10, 0.f); v11 = fmaxf(v11, 0.f);
            }
            v00 *= mvA; v01 *= mvA; v10 *= mvB; v11 *= mvB;
            if (flags & FLAG_TRANS) {
                Cf[((size_t)bA * N + nb) * S_ + sA2] = v00;
                Cf[((size_t)bB * N + nb) * S_ + sB2] = v10;
                if (nb + 1 < N) {
                    Cf[((size_t)bA * N + nb + 1) * S_ + sA2] = v01;
                    Cf[((size_t)bB * N + nb + 1) * S_ + sB2] = v11;
                }
            } else {
                if (Cf) {
                    *(float2*)(Cf + (size_t)mA * N + nb) = make_float2(v00, v01);
                    *(float2*)(Cf + (size_t)mB * N + nb) = make_float2(v10, v11);
                }
                if (Cq) {
                    *(uint32_t*)(Cq + (size_t)mA * N + nb) =
                        packh(__float2half_rn(v00), __float2half_rn(v01));
                    *(uint32_t*)(Cq + (size_t)mB * N + nb) =
                        packh(__float2half_rn(v10), __float2half_rn(v11));
                }
            }
        }
    }
}

// ---------------- fp16 flash attention: single planes, 1 pass per GEMM ----------
__global__ __launch_bounds__(128, 4) void attn_kernel(
    const f16* __restrict__ qsf, const f16* __restrict__ ksf,
    const f16* __restrict__ vsf,
    f16* __restrict__ of, const int* __restrict__ lengths)
{
    extern __shared__ __align__(16) char sm[];
    const uint32_t sb = smem_u32(sm);
    const uint32_t QF = 0;
    const uint32_t ST0 = 8192, STSZ = 16384;

    int t = threadIdx.x, wid = t >> 5, lane = t & 31;
    int qt = blockIdx.x, hh = blockIdx.y, b = blockIdx.z;
    int len = lengths[b];

    int kt0 = len >> 6;
    if (kt0 > 7) kt0 = 7;

#pragma unroll
    for (int it = 0; it < 4; it++) {
        int idx = t + it * 128;
        int r = idx >> 3, c = idx & 7;
        size_t src = ((size_t)b * S_ + qt * 64 + r) * H_ + hh * HD_ + c * 8;
        cpa16(sb + QF + SWZ128(r, c), qsf + src, 16);
    }
    asm volatile("cp.async.commit_group;");

    auto load_kv = [&](int kt, int stg) {
        uint32_t base = sb + ST0 + stg * STSZ;
#pragma unroll
        for (int it = 0; it < 4; it++) {
            int idx = t + it * 128;
            int r = idx >> 3, c = idx & 7;
            size_t src = ((size_t)b * S_ + kt * 64 + r) * H_ + hh * HD_ + c * 8;
            uint32_t d = SWZ128(r, c);
            cpa16(base + d,        ksf + src, 16);
            cpa16(base + 8192 + d, vsf + src, 16);
        }
        asm volatile("cp.async.commit_group;");
    };
    load_kv(kt0, 0);

    asm volatile("cp.async.wait_group 1;");
    __syncthreads();

    int rsel = lane & 15, chalf = lane >> 4;
    uint32_t qf[4][4];
#pragma unroll
    for (int ks = 0; ks < 4; ks++) {
        int rr = wid * 16 + rsel;
        ldsm4(qf[ks], sb + QF + SWZ128(rr, ks * 2 + chalf));
    }

    float oc[8][4];
#pragma unroll
    for (int dt = 0; dt < 8; dt++)
#pragma unroll
        for (int e = 0; e < 4; e++) oc[dt][e] = 0.f;
    float m0 = -INFINITY, m1 = -INFINITY, ls0 = 0.f, ls1 = 0.f;

    for (int kt = kt0; kt < 8; kt++) {
        int stg = (kt - kt0) & 1;
        uint32_t KB = sb + ST0 + stg * STSZ;
        asm volatile("cp.async.wait_group 0;");
        __syncthreads();
        if (kt + 1 < 8) load_kv(kt + 1, stg ^ 1);

        float sv[8][4];
#pragma unroll
        for (int jt = 0; jt < 8; jt++)
#pragma unroll
            for (int e = 0; e < 4; e++) sv[jt][e] = 0.f;
#pragma unroll
        for (int ks = 0; ks < 4; ks++) {
#pragma unroll
            for (int jj = 0; jj < 4; jj++) {
                uint32_t bk[4];
                int rr = jj * 16 + rsel;
                ldsm4(bk, KB + SWZ128(rr, ks * 2 + chalf));
                mma16816(sv[jj * 2 + 0], qf[ks], bk[0], bk[2]);
                mma16816(sv[jj * 2 + 1], qf[ks], bk[1], bk[3]);
            }
        }

        int colb = kt * 64 + (lane & 3) * 2;
        float rm0 = -INFINITY, rm1 = -INFINITY;
#pragma unroll
        for (int jt = 0; jt < 8; jt++) {
#pragma unroll
            for (int e = 0; e < 2; e++) {
                int kp = colb + jt * 8 + e;
                bool keep = (kp >= len);
                float v0 = sv[jt][e] * 0.125f;
                float v1 = sv[jt][2 + e] * 0.125f;
                sv[jt][e]     = keep ? v0 : -1e9f;
                sv[jt][2 + e] = keep ? v1 : -1e9f;
                rm0 = fmaxf(rm0, sv[jt][e]);
                rm1 = fmaxf(rm1, sv[jt][2 + e]);
            }
        }
        rm0 = fmaxf(rm0, __shfl_xor_sync(0xffffffffu, rm0, 1));
        rm0 = fmaxf(rm0, __shfl_xor_sync(0xffffffffu, rm0, 2));
        rm1 = fmaxf(rm1, __shfl_xor_sync(0xffffffffu, rm1, 1));
        rm1 = fmaxf(rm1, __shfl_xor_sync(0xffffffffu, rm1, 2));
        float mn0 = fmaxf(m0, rm0), mn1 = fmaxf(m1, rm1);
        float a0 = __expf(m0 - mn0), a1 = __expf(m1 - mn1);
        m0 = mn0; m1 = mn1;
        float s0 = 0.f, s1 = 0.f;
#pragma unroll
        for (int jt = 0; jt < 8; jt++) {
            sv[jt][0] = __expf(sv[jt][0] - mn0);
            sv[jt][1] = __expf(sv[jt][1] - mn0);
            sv[jt][2] = __expf(sv[jt][2] - mn1);
            sv[jt][3] = __expf(sv[jt][3] - mn1);
            s0 += sv[jt][0] + sv[jt][1];
            s1 += sv[jt][2] + sv[jt][3];
        }
        s0 += __shfl_xor_sync(0xffffffffu, s0, 1);
        s0 += __shfl_xor_sync(0xffffffffu, s0, 2);
        s1 += __shfl_xor_sync(0xffffffffu, s1, 1);
        s1 += __shfl_xor_sync(0xffffffffu, s1, 2);
        ls0 = ls0 * a0 + s0;
        ls1 = ls1 * a1 + s1;
#pragma unroll
        for (int dt = 0; dt < 8; dt++) {
            oc[dt][0] *= a0; oc[dt][1] *= a0;
            oc[dt][2] *= a1; oc[dt][3] *= a1;
        }

        uint32_t VB = KB + 8192;
#pragma unroll
        for (int jp = 0; jp < 4; jp++) {
            uint32_t pa[4];
#pragma unroll
            for (int half = 0; half < 2; half++) {
                pa[2 * half + 0] = packh(__float2half_rn(sv[2 * jp + half][0]),
                                         __float2half_rn(sv[2 * jp + half][1]));
                pa[2 * half + 1] = packh(__float2half_rn(sv[2 * jp + half][2]),
                                         __float2half_rn(sv[2 * jp + half][3]));
            }
            int vrow = jp * 16 + ((lane >> 3) & 1) * 8 + (lane & 7);
#pragma unroll
            for (int g = 0; g < 4; g++) {
                int cch = 2 * g + (lane >> 4);
                uint32_t vv[4];
                ldsm4t(vv, VB + SWZ128(vrow, cch));
                mma16816(oc[2 * g],     pa, vv[0], vv[1]);
                mma16816(oc[2 * g + 1], pa, vv[2], vv[3]);
            }
        }
        __syncthreads();
    }

    float i0 = 1.f / ls0, i1 = 1.f / ls1;
    int r0 = qt * 64 + wid * 16 + (lane >> 2);
#pragma unroll
    for (int dt = 0; dt < 8; dt++) {
        int d = hh * HD_ + dt * 8 + (lane & 3) * 2;
        size_t o0 = ((size_t)b * S_ + r0) * H_ + d;
        size_t o1 = o0 + (size_t)8 * H_;
        *(uint32_t*)(of + o0) = packh(__float2half_rn(oc[dt][0] * i0),
                                      __float2half_rn(oc[dt][1] * i0));
        *(uint32_t*)(of + o1) = packh(__float2half_rn(oc[dt][2] * i1),
                                      __float2half_rn(oc[dt][3] * i1));
    }
}

// ------- LayerNorm, 2 rows/block; optional residual, f16 and masked-f16 outs ----
__global__ __launch_bounds__(256) void ln_kernel(
    const float* __restrict__ x, const float* __restrict__ res,
    const float* __restrict__ g, const float* __restrict__ be,
    float* __restrict__ out, f16* __restrict__ of, int C,
    const int* __restrict__ lengths, f16* __restrict__ mf)
{
    int rb = threadIdx.x >> 7;
    int m  = blockIdx.x * 2 + rb;
    int t  = threadIdx.x & 127;
    int nv = C >> 2;
    float4 v = make_float4(0.f, 0.f, 0.f, 0.f);
    if (t < nv) {
        v = ((const float4*)(x + (size_t)m * C))[t];
        if (res) {
            float4 w = ((const float4*)(res + (size_t)m * C))[t];
            v.x += w.x; v.y += w.y; v.z += w.z; v.w += w.w;
        }
    }
    float sum = v.x + v.y + v.z + v.w;
    float sq  = v.x * v.x + v.y * v.y + v.z * v.z + v.w * v.w;
#pragma unroll
    for (int off = 16; off; off >>= 1) {
        sum += __shfl_xor_sync(0xffffffffu, sum, off);
        sq  += __shfl_xor_sync(0xffffffffu, sq,  off);
    }
    __shared__ float s1[2][4], s2[2][4];
    if ((t & 31) == 0) { s1[rb][t >> 5] = sum; s2[rb][t >> 5] = sq; }
    __syncthreads();
    sum = s1[rb][0] + s1[rb][1] + s1[rb][2] + s1[rb][3];
    sq  = s2[rb][0] + s2[rb][1] + s2[rb][2] + s2[rb][3];
    float mean = sum / C;
    float var  = sq / C - mean * mean;
    float inv  = rsqrtf(var + 1e-5f);
    if (t < nv) {
        float4 gv = ((const float4*)g)[t];
        float4 bv = ((const float4*)be)[t];
        float4 o4;
        o4.x = (v.x - mean) * inv * gv.x + bv.x;
        o4.y = (v.y - mean) * inv * gv.y + bv.y;
        o4.z = (v.z - mean) * inv * gv.z + bv.z;
        o4.w = (v.w - mean) * inv * gv.w + bv.w;
        if (out) ((float4*)(out + (size_t)m * C))[t] = o4;
        if (of) {
            *(uint32_t*)(of + (size_t)m * C + t * 4) =
                packh(__float2half_rn(o4.x), __float2half_rn(o4.y));
            *(uint32_t*)(of + (size_t)m * C + t * 4 + 2) =
                packh(__float2half_rn(o4.z), __float2half_rn(o4.w));
        }
        if (mf) {
            int s = m & (S_ - 1), b = m >> 9;
            float mv = (s >= lengths[b]) ? 1.f : 0.f;   // inverted mask
            *(uint32_t*)(mf + (size_t)m * C + t * 4) =
                packh(__float2half_rn(o4.x * mv), __float2half_rn(o4.y * mv));
            *(uint32_t*)(mf + (size_t)m * C + t * 4 + 2) =
                packh(__float2half_rn(o4.z * mv), __float2half_rn(o4.w * mv));
        }
    }
}

// ---------------- small kernels ----------------
__global__ __launch_bounds__(256) void embed_kernel(
    const int* __restrict__ x, const float* __restrict__ emb,
    float* __restrict__ h, f16* __restrict__ hf)
{
    int idx = blockIdx.x * blockDim.x + threadIdx.x;
    if (idx >= M_ * (H_ / 4)) return;
    int m = idx >> 7, c4 = idx & 127;
    int tok = x[m];
    float4 e = ((const float4*)(emb + (size_t)tok * H_))[c4];
    const float sc = 22.62741699796952f;  // sqrt(512)
    e.x *= sc; e.y *= sc; e.z *= sc; e.w *= sc;
    ((float4*)(h + (size_t)m * H_))[c4] = e;
    *(uint32_t*)(hf + (size_t)m * H_ + c4 * 4) =
        packh(__float2half_rn(e.x), __float2half_rn(e.y));
    *(uint32_t*)(hf + (size_t)m * H_ + c4 * 4 + 2) =
        packh(__float2half_rn(e.z), __float2half_rn(e.w));
}

#define NW1 (L_*F_*H_*3)
#define NW2 (L_*H_*F_*3)
#define ND1 (FD_*H_*3)
#define ND2 (FD_*FD_*3)
__global__ __launch_bounds__(256) void prep_conv_kernel(
    const float* __restrict__ c1w, const float* __restrict__ c2w,
    const float* __restrict__ d1w, const float* __restrict__ d2w)
{
    int idx = blockIdx.x * blockDim.x + threadIdx.x;
    const float* src; f16 *dh, *dl; int CI; int base;
    if (idx < NW1)                        { src = c1w; dh = g_w1h; dl = g_w1l; CI = H_;  base = idx; }
    else if (idx < NW1 + NW2)             { src = c2w; dh = g_w2h; dl = g_w2l; CI = F_;  base = idx - NW1; }
    else if (idx < NW1 + NW2 + ND1)       { src = d1w; dh = g_d1h; dl = g_d1l; CI = H_;  base = idx - NW1 - NW2; }
    else if (idx < NW1 + NW2 + ND1 + ND2) { src = d2w; dh = g_d2h; dl = g_d2l; CI = FD_; base = idx - NW1 - NW2 - ND1; }
    else return;
    int kk = base % 3;
    int rest = base / 3;
    int ci = rest % CI;
    int co = rest / CI;
    f16 h, l; split_w(src[base], h, l);
    size_t o = (size_t)co * (3 * CI) + kk * CI + ci;
    dh[o] = h; dl[o] = l;
}

#define NQKV (L_*3*H_*H_)
#define NWO  (L_*H_*H_)
#define NPJ  (OUT_*H_)
#define NBQ  (L_*3*H_)
#define NRT  (S_*32)
__global__ __launch_bounds__(256) void prep_lin_kernel(
    const float* __restrict__ Wq, const float* __restrict__ Wk,
    const float* __restrict__ Wv, const float* __restrict__ Wo,
    const float* __restrict__ pj,
    const float* __restrict__ bq, const float* __restrict__ bk,
    const float* __restrict__ bv)
{
    int idx = blockIdx.x * blockDim.x + threadIdx.x;
    if (idx < NQKV) {
        int e = idx % H_;
        int n = (idx / H_) % (3 * H_);
        int l = idx / (3 * H_ * H_);
        const float* W = (n < H_) ? Wq : (n < 2 * H_) ? Wk : Wv;
        int nn = n & (H_ - 1);
        f16 h, lo; split_w(W[(size_t)l * H_ * H_ + (size_t)nn * H_ + e], h, lo);
        g_wqkvh[idx] = h; g_wqkvl[idx] = lo;
        return;
    }
    int i2 = idx - NQKV;
    if (i2 < NWO) {
        f16 h, lo; split_w(Wo[i2], h, lo);
        g_woh[i2] = h; g_wol[i2] = lo;
        return;
    }
    int i3 = i2 - NWO;
    if (i3 < NPJ) {
        f16 h, lo; split_w(pj[i3], h, lo);
        g_pjh[i3] = h; g_pjl[i3] = lo;
        return;
    }
    int i4 = i3 - NPJ;
    if (i4 < NBQ) {
        int n = i4 % (3 * H_);
        int l = i4 / (3 * H_);
        const float* bb = (n < H_) ? bq : (n < 2 * H_) ? bk : bv;
        g_bqkv[i4] = bb[l * H_ + (n & (H_ - 1))];
        return;
    }
    int i5 = i4 - NBQ;
    if (i5 < NRT) {
        int s = i5 >> 5, j = i5 & 31;
        float th = expf(-(float)j * 0.28782313662425574f);
        float sn, cs;
        sincosf((float)s * th, &sn, &cs);
        g_rope[i5] = make_float2(cs, sn);
    }
}

__global__ __launch_bounds__(256) void dp_final_kernel(
    const float* __restrict__ x, const float* __restrict__ w,
    const float* __restrict__ pb, const int* __restrict__ lengths,
    float* __restrict__ out)
{
    int warp = threadIdx.x >> 5, lane = threadIdx.x & 31;
    int m = blockIdx.x * 8 + warp;
    if (m >= M_) return;
    const float* xr = x + (size_t)m * FD_;
    float s = 0.f;
    for (int c = lane; c < FD_; c += 32) s += xr[c] * w[c];
#pragma unroll
    for (int off = 16; off; off >>= 1) s += __shfl_xor_sync(0xffffffffu, s, off);
    if (lane == 0) {
        int b = m >> 9, sp = m & (S_ - 1);
        float mv = (sp >= lengths[b]) ? 1.f : 0.f;
        float val = (s + pb[0]) * mv;
        out[(size_t)b * S_ + sp] = ceilf(expf(val));
    }
}

// ---------------- orchestration ----------------
extern "C" void kernel_launch(void* const* d_in, const int* in_sizes, int n_in,
                              void* d_out, int out_size)
{
    const int*   x      = (const int*)  d_in[0];
    const int*   xlen   = (const int*)  d_in[1];
    const float* emb    = (const float*)d_in[2];
    const float* Wq     = (const float*)d_in[3];
    const float* bq     = (const float*)d_in[4];
    const float* Wk     = (const float*)d_in[5];
    const float* bk     = (const float*)d_in[6];
    const float* Wv     = (const float*)d_in[7];
    const float* bv     = (const float*)d_in[8];
    const float* Wo     = (const float*)d_in[9];
    const float* bo     = (const float*)d_in[10];
    const float* c1w    = (const float*)d_in[11];
    const float* c1b    = (const float*)d_in[12];
    const float* c2w    = (const float*)d_in[13];
    const float* c2b    = (const float*)d_in[14];
    const float* ln1g   = (const float*)d_in[15];
    const float* ln1b   = (const float*)d_in[16];
    const float* ln2g   = (const float*)d_in[17];
    const float* ln2b   = (const float*)d_in[18];
    const float* projw  = (const float*)d_in[19];
    const float* projb  = (const float*)d_in[20];
    const float* dpc1w  = (const float*)d_in[21];
    const float* dpc1b  = (const float*)d_in[22];
    const float* dpln1g = (const float*)d_in[23];
    const float* dpln1b = (const float*)d_in[24];
    const float* dpc2w  = (const float*)d_in[25];
    const float* dpc2b  = (const float*)d_in[26];
    const float* dpln2g = (const float*)d_in[27];
    const float* dpln2b = (const float*)d_in[28];
    const float* dppw   = (const float*)d_in[29];
    const float* dppb   = (const float*)d_in[30];
    float* out = (float*)d_out;

    float *h, *x1, *op, *cv2, *bqkv;
    f16 *hf, *x1f, *af, *midf, *mkf, *dpxf, *qsf, *ksf, *vsf;
    f16 *wqh, *wql, *woh, *wol, *w1h, *w1l, *w2h, *w2l, *pjh, *pjl, *d1h, *d1l, *d2h, *d2l;
    cudaGetSymbolAddress((void**)&h,    g_h);
    cudaGetSymbolAddress((void**)&x1,   g_x1);
    cudaGetSymbolAddress((void**)&op,   g_op);
    cudaGetSymbolAddress((void**)&cv2,  g_cv2);
    cudaGetSymbolAddress((void**)&hf,   g_hf);
    cudaGetSymbolAddress((void**)&x1f,  g_x1f);
    cudaGetSymbolAddress((void**)&af,   g_af);
    cudaGetSymbolAddress((void**)&midf, g_midf);
    cudaGetSymbolAddress((void**)&mkf,  g_mkf);
    cudaGetSymbolAddress((void**)&dpxf, g_dpxf);
    cudaGetSymbolAddress((void**)&qsf,  g_qsf);
    cudaGetSymbolAddress((void**)&ksf,  g_ksf);
    cudaGetSymbolAddress((void**)&vsf,  g_vsf);
    cudaGetSymbolAddress((void**)&wqh,  g_wqkvh);
    cudaGetSymbolAddress((void**)&wql,  g_wqkvl);
    cudaGetSymbolAddress((void**)&woh,  g_woh);
    cudaGetSymbolAddress((void**)&wol,  g_wol);
    cudaGetSymbolAddress((void**)&w1h,  g_w1h);
    cudaGetSymbolAddress((void**)&w1l,  g_w1l);
    cudaGetSymbolAddress((void**)&w2h,  g_w2h);
    cudaGetSymbolAddress((void**)&w2l,  g_w2l);
    cudaGetSymbolAddress((void**)&pjh,  g_pjh);
    cudaGetSymbolAddress((void**)&pjl,  g_pjl);
    cudaGetSymbolAddress((void**)&d1h,  g_d1h);
    cudaGetSymbolAddress((void**)&d1l,  g_d1l);
    cudaGetSymbolAddress((void**)&d2h,  g_d2h);
    cudaGetSymbolAddress((void**)&d2l,  g_d2l);
    cudaGetSymbolAddress((void**)&bqkv, g_bqkv);

    cudaFuncSetAttribute((const void*)attn_kernel,
                         cudaFuncAttributeMaxDynamicSharedMemorySize, 40960);
    cudaFuncSetAttribute((const void*)hgemm_kernel,
                         cudaFuncAttributeMaxDynamicSharedMemorySize, 40960);

    {
        int tot = NW1 + NW2 + ND1 + ND2;
        prep_conv_kernel<<<(tot + 255) / 256, 256>>>(c1w, c2w, dpc1w, dpc2w);
        tot = NQKV + NWO + NPJ + NBQ + NRT;
        prep_lin_kernel<<<(tot + 255) / 256, 256>>>(Wq, Wk, Wv, Wo, projw, bq, bk, bv);
    }
    embed_kernel<<<M_ * (H_ / 4) / 256, 256>>>(x, emb, h, hf);

    const int SM_G = 40960;
    const int SM_A = 40960;
    dim3 gQKV(3 * H_ / 128, M_ / 64);   // (12,256)
    dim3 gH(H_ / 128, M_ / 64);         // (4,256)
    dim3 gF(F_ / 128, M_ / 64);         // (16,256)
    dim3 gMu(1, M_ / 64);
    dim3 gDp(FD_ / 128, M_ / 64);       // (2,256)
    dim3 ga(S_ / 64, NH_, B_);
    const int LNB = M_ / 2;

    for (int l = 0; l < L_; l++) {
        size_t wOff = (size_t)l * H_ * H_;
        size_t wqOff = (size_t)l * 3 * H_ * H_;
        bool last = (l == L_ - 1);
        hgemm_kernel<<<gQKV, 128, SM_G>>>(hf, wqh + wqOff, wql + wqOff,
                                          bqkv + l * 3 * H_, nullptr, nullptr,
                                          3 * H_, 9, 1, 0, FLAG_QKV, xlen);
        attn_kernel<<<ga, 128, SM_A>>>(qsf, ksf, vsf, af, xlen);
        hgemm_kernel<<<gH, 128, SM_G>>>(af, woh + wOff, wol + wOff,
                                        bo + l * H_, op, nullptr,
                                        H_, 9, 1, 0, 0, xlen);
        ln_kernel<<<LNB, 256>>>(op, h, ln1g + l * H_, ln1b + l * H_,
                                x1, x1f, H_, nullptr, nullptr);
        hgemm_kernel<<<gF, 128, SM_G>>>(x1f,
                                        w1h + (size_t)l * F_ * 3 * H_, w1l + (size_t)l * F_ * 3 * H_,
                                        c1b + l * F_, nullptr, midf,
                                        F_, 9, 3, 1, FLAG_RELU, xlen);
        // conv2: single-pass weights (post-relu input halves effective error K)
        hgemm_kernel<<<gH, 128, SM_G>>>(midf,
                                        w2h + (size_t)l * H_ * 3 * F_, w2l + (size_t)l * H_ * 3 * F_,
                                        c2b + l * H_, cv2, nullptr,
                                        H_, 11, 3, 1, FLAG_W1P, xlen);
        ln_kernel<<<LNB, 256>>>(cv2, x1, ln2g + l * H_, ln2b + l * H_,
                                h, hf, H_,
                                last ? xlen : nullptr,
                                last ? mkf : nullptr);
    }

    hgemm_kernel<<<gMu, 128, SM_G>>>(hf, pjh, pjl, projb, out, nullptr,
                                     OUT_, 9, 1, 0, FLAG_TRANS, xlen);

    hgemm_kernel<<<gDp, 128, SM_G>>>(mkf, d1h, d1l, dpc1b, op, nullptr,
                                     FD_, 9, 3, 1, FLAG_RELU | FLAG_MASK, xlen);
    ln_kernel<<<LNB, 256>>>(op, nullptr, dpln1g, dpln1b, cv2, dpxf, FD_,
                            nullptr, nullptr);
    hgemm_kernel<<<gDp, 128, SM_G>>>(dpxf, d2h, d2l, dpc2b, op, nullptr,
                                     FD_, 8, 3, 1, FLAG_RELU | FLAG_MASK, xlen);
    ln_kernel<<<LNB, 256>>>(op, nullptr, dpln2g, dpln2b, x1, nullptr, FD_,
                            nullptr, nullptr);
    dp_final_kernel<<<M_ / 8, 256>>>(x1, dppw, dppb, xlen,
                                     out + ((size_t)out_size - (size_t)B_ * S_));
}